// round 1
// baseline (speedup 1.0000x reference)
#include <cuda_runtime.h>
#include <math.h>

#define BATCH 8
#define CH    256
#define HWP   4096   // 64*64

// ---------------- scratch (static device allocations; no cudaMalloc) ----------
__device__ float g_comp [BATCH*128*HWP];   // 16.8 MB
__device__ float g_t    [BATCH*64*HWP];    //  8.4 MB
__device__ float g_kw   [BATCH*HWP*36];    //  4.7 MB  softmaxed kernels [b][p][s*9+k]
__device__ float g_kwsum[BATCH*HWP*9];     //  1.2 MB  sum over s
__device__ float g_gmap [BATCH*HWP];       //  g map for pooled kernel_out
__device__ float g_enh  [BATCH*CH*HWP];    // 33.5 MB  grouped-conv output
__device__ float g_pooled[BATCH*CH];
__device__ float g_gate  [BATCH*CH];

// ---------------- K1: 1x1 conv 256->128 (comp) --------------------------------
__global__ __launch_bounds__(256) void k1_conv1x1(const float* __restrict__ x,
    const float* __restrict__ Wkc, const float* __restrict__ bkc) {
  __shared__ float ws[16*256];
  int tid = threadIdx.x;
  int co0 = blockIdx.y * 16;
  int b   = blockIdx.z;
  int p0  = blockIdx.x * 1024 + tid;
  for (int i = tid; i < 4096; i += 256) ws[i] = Wkc[co0*256 + i];
  __syncthreads();
  float acc[16][4];
  #pragma unroll
  for (int j = 0; j < 16; j++) {
    float bv = bkc[co0+j];
    acc[j][0]=bv; acc[j][1]=bv; acc[j][2]=bv; acc[j][3]=bv;
  }
  const float* xb = x + b*CH*HWP + p0;
  for (int ci = 0; ci < 256; ci++) {
    float x0 = xb[ci*HWP];
    float x1 = xb[ci*HWP+256];
    float x2 = xb[ci*HWP+512];
    float x3 = xb[ci*HWP+768];
    #pragma unroll
    for (int j = 0; j < 16; j++) {
      float w = ws[j*256+ci];
      acc[j][0] += w*x0; acc[j][1] += w*x1; acc[j][2] += w*x2; acc[j][3] += w*x3;
    }
  }
  float* cb = g_comp + (b*128+co0)*HWP + p0;
  #pragma unroll
  for (int j = 0; j < 16; j++) {
    cb[j*HWP]     = acc[j][0];
    cb[j*HWP+256] = acc[j][1];
    cb[j*HWP+512] = acc[j][2];
    cb[j*HWP+768] = acc[j][3];
  }
}

// ---------------- K2: 3x3 conv 128->64 + BN + SiLU ----------------------------
__global__ __launch_bounds__(256) void k2_conv3x3(const float* __restrict__ W,
    const float* __restrict__ bias, const float* __restrict__ g1,
    const float* __restrict__ be1, const float* __restrict__ m1,
    const float* __restrict__ v1) {
  __shared__ float xs[8][10][10];
  __shared__ float ws[64][73];
  int tid = threadIdx.x;
  int co = tid & 63, pg = tid >> 6;
  int qy = (pg >> 1) * 4, qx = (pg & 1) * 4;
  int ty0 = (blockIdx.x >> 3) * 8, tx0 = (blockIdx.x & 7) * 8;
  int b = blockIdx.y;
  float acc[4][4];
  #pragma unroll
  for (int i=0;i<4;i++)
    #pragma unroll
    for (int j=0;j<4;j++) acc[i][j]=0.f;

  for (int c0 = 0; c0 < 128; c0 += 8) {
    __syncthreads();
    for (int i = tid; i < 800; i += 256) {
      int ci = i / 100, rem = i % 100;
      int r = rem / 10, cc = rem % 10;
      int y = ty0 + r - 1, xx = tx0 + cc - 1;
      float v = 0.f;
      if ((unsigned)y < 64u && (unsigned)xx < 64u)
        v = g_comp[(b*128 + c0 + ci)*HWP + y*64 + xx];
      xs[ci][r][cc] = v;
    }
    for (int i = tid; i < 4608; i += 256) {
      int c = i / 72, rem = i % 72;
      ws[c][rem] = W[(c*128 + c0 + rem/9)*9 + rem%9];
    }
    __syncthreads();
    #pragma unroll
    for (int ci = 0; ci < 8; ci++) {
      float w[9];
      #pragma unroll
      for (int t=0;t<9;t++) w[t]=ws[co][ci*9+t];
      float xr[6][6];
      #pragma unroll
      for (int r=0;r<6;r++)
        #pragma unroll
        for (int c2=0;c2<6;c2++) xr[r][c2]=xs[ci][qy+r][qx+c2];
      #pragma unroll
      for (int dy=0;dy<3;dy++)
        #pragma unroll
        for (int dx=0;dx<3;dx++) {
          float wv = w[dy*3+dx];
          #pragma unroll
          for (int py=0;py<4;py++)
            #pragma unroll
            for (int px=0;px<4;px++)
              acc[py][px] += wv * xr[py+dy][px+dx];
        }
    }
  }
  float bv = bias[co];
  float sc = g1[co] * rsqrtf(v1[co] + 1e-5f);
  float sh = be1[co] - m1[co]*sc;
  #pragma unroll
  for (int py=0;py<4;py++)
    #pragma unroll
    for (int px=0;px<4;px++) {
      float y = (acc[py][px] + bv) * sc + sh;
      float sg = 1.f/(1.f+expf(-y));
      g_t[(b*64+co)*HWP + (ty0+qy+py)*64 + (tx0+qx+px)] = y * sg;
    }
}

// ---------------- K3: 1x1 conv 64->36 + softmax(9) groups ---------------------
__global__ __launch_bounds__(256) void k3_kw(const float* __restrict__ Wkp2,
                                             const float* __restrict__ bkp2) {
  __shared__ float ws[36*64];
  __shared__ float bs[36];
  int tid = threadIdx.x;
  for (int i = tid; i < 2304; i += 256) ws[i] = Wkp2[i];
  if (tid < 36) bs[tid] = bkp2[tid];
  __syncthreads();
  int gp = blockIdx.x*256 + tid;       // 0..32767
  int b = gp >> 12, p = gp & 4095;
  float acc[36];
  #pragma unroll
  for (int j=0;j<36;j++) acc[j]=bs[j];
  const float* tb = g_t + b*64*HWP + p;
  for (int ci=0; ci<64; ci++) {
    float tv = tb[ci*HWP];
    #pragma unroll
    for (int j=0;j<36;j++) acc[j] += ws[j*64+ci]*tv;
  }
  float ks[9];
  #pragma unroll
  for (int k=0;k<9;k++) ks[k]=0.f;
  float* kwp = g_kw + gp*36;
  #pragma unroll
  for (int s=0;s<4;s++) {
    float m = acc[s*9];
    #pragma unroll
    for (int k=1;k<9;k++) m = fmaxf(m, acc[s*9+k]);
    float e[9]; float sum=0.f;
    #pragma unroll
    for (int k=0;k<9;k++){ e[k]=expf(acc[s*9+k]-m); sum+=e[k]; }
    float inv = 1.f/sum;
    #pragma unroll
    for (int k=0;k<9;k++){ float v=e[k]*inv; kwp[s*9+k]=v; ks[k]+=v; }
  }
  float* ksp = g_kwsum + gp*9;
  #pragma unroll
  for (int k=0;k<9;k++) ksp[k]=ks[k];
}

// ---------------- K3b: g map = 3x3 box correlation of kwsum -------------------
__global__ void k3b_gmap() {
  int gp = blockIdx.x*256 + threadIdx.x;
  int b = gp >> 12, p = gp & 4095;
  int i = p >> 6, j = p & 63;
  float s = 0.f;
  #pragma unroll
  for (int ih=0; ih<3; ih++)
    #pragma unroll
    for (int iw=0; iw<3; iw++) {
      int h = i + 1 - ih, w = j + 1 - iw;
      if ((unsigned)h < 64u && (unsigned)w < 64u)
        s += g_kwsum[(b*4096 + h*64 + w)*9 + ih*3 + iw];
    }
  g_gmap[gp] = s;
}

// ---------------- K4: grouped 3x3 conv 256->256 (groups=4, no bias) -----------
__global__ __launch_bounds__(256) void k4_gconv(const float* __restrict__ x,
                                                const float* __restrict__ Wdef) {
  __shared__ float xs[8][10][10];
  __shared__ float ws[64][73];
  int tid = threadIdx.x;
  int co = tid & 63, pg = tid >> 6;
  int qy = (pg >> 1)*4, qx = (pg & 1)*4;
  int ty0 = (blockIdx.x >> 3)*8, tx0 = (blockIdx.x & 7)*8;
  int gi = blockIdx.y;
  int b  = blockIdx.z;
  float acc[4][4];
  #pragma unroll
  for (int i=0;i<4;i++)
    #pragma unroll
    for (int j=0;j<4;j++) acc[i][j]=0.f;

  for (int c0 = 0; c0 < 64; c0 += 8) {
    __syncthreads();
    for (int i = tid; i < 800; i += 256) {
      int ci = i / 100, rem = i % 100;
      int r = rem / 10, cc = rem % 10;
      int y = ty0 + r - 1, xx = tx0 + cc - 1;
      float v = 0.f;
      if ((unsigned)y < 64u && (unsigned)xx < 64u)
        v = x[(b*CH + gi*64 + c0 + ci)*HWP + y*64 + xx];
      xs[ci][r][cc] = v;
    }
    for (int i = tid; i < 4608; i += 256) {
      int c = i / 72, rem = i % 72;
      ws[c][rem] = Wdef[((gi*64 + c)*64 + c0 + rem/9)*9 + rem%9];
    }
    __syncthreads();
    #pragma unroll
    for (int ci = 0; ci < 8; ci++) {
      float w[9];
      #pragma unroll
      for (int t=0;t<9;t++) w[t]=ws[co][ci*9+t];
      float xr[6][6];
      #pragma unroll
      for (int r=0;r<6;r++)
        #pragma unroll
        for (int c2=0;c2<6;c2++) xr[r][c2]=xs[ci][qy+r][qx+c2];
      #pragma unroll
      for (int dy=0;dy<3;dy++)
        #pragma unroll
        for (int dx=0;dx<3;dx++) {
          float wv = w[dy*3+dx];
          #pragma unroll
          for (int py=0;py<4;py++)
            #pragma unroll
            for (int px=0;px<4;px++)
              acc[py][px] += wv * xr[py+dy][px+dx];
        }
    }
  }
  #pragma unroll
  for (int py=0;py<4;py++)
    #pragma unroll
    for (int px=0;px<4;px++)
      g_enh[(b*CH + gi*64 + co)*HWP + (ty0+qy+py)*64 + (tx0+qx+px)] = acc[py][px];
}

// ---------------- K5: pooled[b,c] = sum(x*g)/16384 + sum(enh)/4096 ------------
__global__ __launch_bounds__(256) void k5_pool(const float* __restrict__ x) {
  int bc = blockIdx.x;               // 0..2047
  int b = bc >> 8;
  const float* xp = x      + (size_t)bc*HWP;
  const float* ep = g_enh  + (size_t)bc*HWP;
  const float* gp = g_gmap + (size_t)b*HWP;
  int tid = threadIdx.x;
  float s1=0.f, s2=0.f;
  for (int i = tid; i < HWP; i += 256) { s1 += xp[i]*gp[i]; s2 += ep[i]; }
  __shared__ float r1[256], r2[256];
  r1[tid]=s1; r2[tid]=s2;
  __syncthreads();
  for (int st=128; st>0; st>>=1) {
    if (tid < st) { r1[tid]+=r1[tid+st]; r2[tid]+=r2[tid+st]; }
    __syncthreads();
  }
  if (tid==0) g_pooled[bc] = r1[0]*(1.f/16384.f) + r2[0]*(1.f/4096.f);
}

// ---------------- K6: SE gate ---------------------------------------------------
__global__ __launch_bounds__(256) void k6_gate(const float* __restrict__ Wg1,
    const float* __restrict__ bg1, const float* __restrict__ Wg2,
    const float* __restrict__ bg2) {
  int b = blockIdx.x, tid = threadIdx.x;
  __shared__ float pl[256], hid[64];
  pl[tid] = g_pooled[b*256 + tid];
  __syncthreads();
  if (tid < 64) {
    float a = bg1[tid];
    for (int ci=0; ci<256; ci++) a += Wg1[tid*256+ci]*pl[ci];
    hid[tid] = a / (1.f + expf(-a));   // silu
  }
  __syncthreads();
  float a = bg2[tid];
  for (int j=0;j<64;j++) a += Wg2[tid*64+j]*hid[j];
  g_gate[b*256+tid] = 1.f/(1.f+expf(-a));
}

// ---------------- K7: reassembly + bilinear up + gate -> output ----------------
__global__ __launch_bounds__(256) void k7_fused(const float* __restrict__ x,
                                                float* __restrict__ out) {
  __shared__ float kws[64][37];
  __shared__ float xs[16][3][66];
  __shared__ float es[16][3][64];
  int tid = threadIdx.x;
  int wl = tid & 63, cs = tid >> 6;
  int c0 = blockIdx.x * 16;
  int h  = blockIdx.y;
  int b  = blockIdx.z;
  for (int i = tid; i < 2304; i += 256) {
    int w = i / 36, m = i % 36;
    kws[w][m] = g_kw[(b*4096 + h*64 + w)*36 + m];
  }
  for (int i = tid; i < 16*3*66; i += 256) {
    int cc = i / 198, rem = i % 198;
    int r = rem / 66, col = rem % 66 - 1;
    int y = h + r - 1;
    float v = 0.f;
    if ((unsigned)y < 64u && (unsigned)col < 64u)
      v = x[((b*CH)+c0+cc)*HWP + y*64 + col];
    xs[cc][r][col+1] = v;
  }
  for (int i = tid; i < 16*3*64; i += 256) {
    int cc = i / 192, rem = i % 192;
    int r = rem / 64, col = rem % 64;
    int y = min(max(h + r - 1, 0), 63);
    es[cc][r][col] = g_enh[((b*CH)+c0+cc)*HWP + y*64 + col];
  }
  __syncthreads();
  // column interpolation for bilinear (half-pixel, clamped)
  int base; float fw;
  if (wl & 1) { base = (wl - 1) >> 1; fw = 0.25f; }
  else        { base = (wl >> 1) - 1; fw = 0.75f; }
  int cA0 = max(base, 0);
  int cB0 = base + 1;           // <=32, in range for dj=0
  int cA1 = base + 32;          // >=31, in range for dj=1
  int cB1 = min(base + 33, 63);
  float fw1 = 1.f - fw;
  #pragma unroll
  for (int q = 0; q < 4; q++) {
    int cc = cs*4 + q;
    int c  = c0 + cc;
    float gt = g_gate[b*256 + c];
    float x00=xs[cc][0][wl], x01=xs[cc][0][wl+1], x02=xs[cc][0][wl+2];
    float x10=xs[cc][1][wl], x11=xs[cc][1][wl+1], x12=xs[cc][1][wl+2];
    float x20=xs[cc][2][wl], x21=xs[cc][2][wl+1], x22=xs[cc][2][wl+2];
    float rv[3][2];
    #pragma unroll
    for (int r=0;r<3;r++) {
      rv[r][0] = fw1*es[cc][r][cA0] + fw*es[cc][r][cB0];
      rv[r][1] = fw1*es[cc][r][cA1] + fw*es[cc][r][cB1];
    }
    float up[2][2];
    up[0][0] = 0.25f*rv[0][0] + 0.75f*rv[1][0];
    up[0][1] = 0.25f*rv[0][1] + 0.75f*rv[1][1];
    up[1][0] = 0.75f*rv[1][0] + 0.25f*rv[2][0];
    up[1][1] = 0.75f*rv[1][1] + 0.25f*rv[2][1];
    #pragma unroll
    for (int s=0;s<4;s++) {
      const float* kp = &kws[wl][s*9];
      float ko = x00*kp[0]+x01*kp[1]+x02*kp[2]
               + x10*kp[3]+x11*kp[4]+x12*kp[5]
               + x20*kp[6]+x21*kp[7]+x22*kp[8];
      int di = s >> 1, dj = s & 1;
      size_t oidx = (size_t)(b*256 + c)*16384 + (size_t)(2*h+di)*128 + (size_t)(dj*64 + wl);
      out[oidx] = (ko + up[di][dj]) * gt;
    }
  }
}

// ---------------- launch --------------------------------------------------------
extern "C" void kernel_launch(void* const* d_in, const int* in_sizes, int n_in,
                              void* d_out, int out_size) {
  const float* x    = (const float*)d_in[0];
  const float* Wkc  = (const float*)d_in[1];
  const float* bkc  = (const float*)d_in[2];
  const float* Wkp1 = (const float*)d_in[3];
  const float* bkp1 = (const float*)d_in[4];
  const float* g1   = (const float*)d_in[5];
  const float* be1  = (const float*)d_in[6];
  const float* m1   = (const float*)d_in[7];
  const float* v1   = (const float*)d_in[8];
  const float* Wkp2 = (const float*)d_in[9];
  const float* bkp2 = (const float*)d_in[10];
  const float* Wdef = (const float*)d_in[11];
  const float* Wg1  = (const float*)d_in[12];
  const float* bg1  = (const float*)d_in[13];
  const float* Wg2  = (const float*)d_in[14];
  const float* bg2  = (const float*)d_in[15];
  float* out = (float*)d_out;

  k1_conv1x1<<<dim3(4,8,8),  256>>>(x, Wkc, bkc);
  k2_conv3x3<<<dim3(64,8),   256>>>(Wkp1, bkp1, g1, be1, m1, v1);
  k3_kw     <<<128,          256>>>(Wkp2, bkp2);
  k3b_gmap  <<<128,          256>>>();
  k4_gconv  <<<dim3(64,4,8), 256>>>(x, Wdef);
  k5_pool   <<<2048,         256>>>(x);
  k6_gate   <<<8,            256>>>(Wg1, bg1, Wg2, bg2);
  k7_fused  <<<dim3(16,64,8),256>>>(x, out);
}

// round 2
// speedup vs baseline: 1.1329x; 1.1329x over previous
#include <cuda_runtime.h>
#include <math.h>

#define BATCH 8
#define CH    256
#define HWP   4096   // 64*64

typedef unsigned long long ull;

// ---- packed f32x2 helpers (Blackwell FFMA2) ----------------------------------
__device__ __forceinline__ ull pk2(float lo, float hi) {
  ull r; asm("mov.b64 %0, {%1, %2};" : "=l"(r) : "f"(lo), "f"(hi)); return r;
}
__device__ __forceinline__ float lo2(ull v) {
  float a, b; asm("mov.b64 {%0, %1}, %2;" : "=f"(a), "=f"(b) : "l"(v)); return a;
}
__device__ __forceinline__ float hi2(ull v) {
  float a, b; asm("mov.b64 {%0, %1}, %2;" : "=f"(a), "=f"(b) : "l"(v)); return b;
}
__device__ __forceinline__ void fma2(ull& d, ull a, ull b) {
  asm("fma.rn.f32x2 %0, %1, %2, %0;" : "+l"(d) : "l"(a), "l"(b));
}

// ---------------- scratch (static device allocations; no cudaMalloc) ----------
__device__ float g_comp [BATCH*128*HWP];   // 16.8 MB
__device__ float g_t    [BATCH*64*HWP];    //  8.4 MB
__device__ float g_kw   [BATCH*HWP*36];    //  4.7 MB  softmaxed kernels [b][p][s*9+k]
__device__ float g_kwsum[BATCH*HWP*9];     //  1.2 MB  sum over s
__device__ float g_gmap [BATCH*HWP];       //  g map for pooled kernel_out
__device__ float g_enh  [BATCH*CH*HWP];    // 33.5 MB  grouped-conv output
__device__ float g_pooled[BATCH*CH];
__device__ float g_gate  [BATCH*CH];

// ---------------- K1: 1x1 conv 256->128 as register-blocked GEMM --------------
// block: 64 co x 256 px, thread: 8 co x 8 px (f32x2-packed)
__global__ __launch_bounds__(256,2) void k1_gemm(const float* __restrict__ x,
    const float* __restrict__ Wkc, const float* __restrict__ bkc) {
  __shared__ alignas(16) float ws[16][64];
  __shared__ alignas(16) float xsm[16][256];
  int tid  = threadIdx.x;
  int cob0 = blockIdx.y * 64;
  int pxb0 = blockIdx.x * 256;
  int b    = blockIdx.z;
  int co0t = (tid >> 5) * 8;
  int px0  = (tid & 31) * 8;

  ull acc[8][4];
  #pragma unroll
  for (int j = 0; j < 8; j++)
    #pragma unroll
    for (int i = 0; i < 4; i++) acc[j][i] = 0ULL;

  for (int c0 = 0; c0 < 256; c0 += 16) {
    __syncthreads();
    #pragma unroll
    for (int rep = 0; rep < 4; rep++) {
      int i = rep*256 + tid;
      int k = i >> 6, co = i & 63;
      ws[k][co] = Wkc[(size_t)(cob0 + co)*256 + c0 + k];
    }
    #pragma unroll
    for (int rep = 0; rep < 16; rep++) {
      int i = rep*256 + tid;
      int k = i >> 8, p = i & 255;
      xsm[k][p] = x[((size_t)b*256 + c0 + k)*HWP + pxb0 + p];
    }
    __syncthreads();
    #pragma unroll
    for (int k = 0; k < 16; k++) {
      const ull* xp = (const ull*)&xsm[k][px0];
      ull xv0 = xp[0], xv1 = xp[1], xv2 = xp[2], xv3 = xp[3];
      #pragma unroll
      for (int j = 0; j < 8; j++) {
        float w = ws[k][co0t + j];
        ull w2 = pk2(w, w);
        fma2(acc[j][0], w2, xv0);
        fma2(acc[j][1], w2, xv1);
        fma2(acc[j][2], w2, xv2);
        fma2(acc[j][3], w2, xv3);
      }
    }
  }
  #pragma unroll
  for (int j = 0; j < 8; j++) {
    int co = cob0 + co0t + j;
    float bv = bkc[co];
    float* op = g_comp + ((size_t)b*128 + co)*HWP + pxb0 + px0;
    #pragma unroll
    for (int i = 0; i < 4; i++) {
      float2 v; v.x = lo2(acc[j][i]) + bv; v.y = hi2(acc[j][i]) + bv;
      *(float2*)(op + 2*i) = v;
    }
  }
}

// ---------------- K2/K4: 3x3 conv, 16x16 tile, thread = 4x4 px * 4 co ---------
// BN=true applies eval BatchNorm + SiLU (k2); BN=false raw output (k4, grouped)
template<int CIN, bool BN>
__global__ __launch_bounds__(256) void conv3x3_t(
    const float* __restrict__ in, const float* __restrict__ W,
    float* __restrict__ out,
    const float* __restrict__ bias, const float* __restrict__ g1,
    const float* __restrict__ be1, const float* __restrict__ m1,
    const float* __restrict__ v1) {
  __shared__ alignas(16) float xs[8][18][18];
  __shared__ float ws[64][73];
  int tid = threadIdx.x;
  int q = tid & 15, cg = tid >> 4;
  int qy = (q >> 2) * 4, qx = (q & 3) * 4;
  int col = cg * 4;
  int ty0 = (blockIdx.x >> 2) * 16, tx0 = (blockIdx.x & 3) * 16;
  int co0 = blockIdx.y * 64;
  int b = blockIdx.z;
  int nch = gridDim.y * CIN;
  int nco = gridDim.y * 64;
  const float* inb = in + ((size_t)b*nch + blockIdx.y*CIN)*HWP;

  ull acc[4][4][2];
  #pragma unroll
  for (int j = 0; j < 4; j++)
    #pragma unroll
    for (int py = 0; py < 4; py++) { acc[j][py][0] = 0ULL; acc[j][py][1] = 0ULL; }

  for (int c0 = 0; c0 < CIN; c0 += 8) {
    __syncthreads();
    for (int i = tid; i < 2592; i += 256) {       // 8 ci * 18 * 18
      int ci = i / 324, rem = i % 324;
      int r = rem / 18, c = rem % 18;
      int y = ty0 + r - 1, xx = tx0 + c - 1;
      float v = 0.f;
      if ((unsigned)y < 64u && (unsigned)xx < 64u)
        v = inb[(size_t)(c0 + ci)*HWP + y*64 + xx];
      xs[ci][r][c] = v;
    }
    for (int i = tid; i < 4608; i += 256) {       // 64 co * 72
      int co = i / 72, rem = i % 72;
      ws[co][rem] = W[((size_t)(co0 + co)*CIN + c0)*9 + rem];
    }
    __syncthreads();
    #pragma unroll
    for (int ci = 0; ci < 8; ci++) {
      ull p[6][3], qd[6][2];
      #pragma unroll
      for (int r = 0; r < 6; r++) {
        const ull* rp = (const ull*)&xs[ci][qy + r][qx];
        p[r][0] = rp[0]; p[r][1] = rp[1]; p[r][2] = rp[2];
        qd[r][0] = pk2(hi2(p[r][0]), lo2(p[r][1]));
        qd[r][1] = pk2(hi2(p[r][1]), lo2(p[r][2]));
      }
      #pragma unroll
      for (int j = 0; j < 4; j++) {
        const float* wp = &ws[col + j][ci*9];
        #pragma unroll
        for (int dy = 0; dy < 3; dy++) {
          #pragma unroll
          for (int dx = 0; dx < 3; dx++) {
            float wv = wp[dy*3+dx];
            ull w2 = pk2(wv, wv);
            #pragma unroll
            for (int py = 0; py < 4; py++) {
              int r = py + dy;
              if (dx == 0) {
                fma2(acc[j][py][0], w2, p[r][0]);  fma2(acc[j][py][1], w2, p[r][1]);
              } else if (dx == 1) {
                fma2(acc[j][py][0], w2, qd[r][0]); fma2(acc[j][py][1], w2, qd[r][1]);
              } else {
                fma2(acc[j][py][0], w2, p[r][1]);  fma2(acc[j][py][1], w2, p[r][2]);
              }
            }
          }
        }
      }
    }
  }
  #pragma unroll
  for (int j = 0; j < 4; j++) {
    int co = co0 + col + j;
    float bv = 0.f, sc = 1.f, sh = 0.f;
    if (BN) {
      bv = bias[co];
      sc = g1[co] * rsqrtf(v1[co] + 1e-5f);
      sh = be1[co] - m1[co]*sc;
    }
    #pragma unroll
    for (int py = 0; py < 4; py++) {
      float* op = out + ((size_t)b*nco + co)*HWP + (ty0+qy+py)*64 + tx0 + qx;
      #pragma unroll
      for (int c = 0; c < 2; c++) {
        float vlo = lo2(acc[j][py][c]);
        float vhi = hi2(acc[j][py][c]);
        if (BN) {
          vlo = (vlo + bv)*sc + sh;  vlo = vlo / (1.f + expf(-vlo));
          vhi = (vhi + bv)*sc + sh;  vhi = vhi / (1.f + expf(-vhi));
        }
        float2 v; v.x = vlo; v.y = vhi;
        *(float2*)(op + 2*c) = v;
      }
    }
  }
}

// ---------------- K3: 1x1 conv 64->36 + softmax(9) groups ---------------------
__global__ __launch_bounds__(256) void k3_kw(const float* __restrict__ Wkp2,
                                             const float* __restrict__ bkp2) {
  __shared__ float ws[36*64];
  __shared__ float bs[36];
  int tid = threadIdx.x;
  for (int i = tid; i < 2304; i += 256) ws[i] = Wkp2[i];
  if (tid < 36) bs[tid] = bkp2[tid];
  __syncthreads();
  int gp = blockIdx.x*256 + tid;       // 0..32767
  int b = gp >> 12, p = gp & 4095;
  float acc[36];
  #pragma unroll
  for (int j=0;j<36;j++) acc[j]=bs[j];
  const float* tb = g_t + (size_t)b*64*HWP + p;
  for (int ci=0; ci<64; ci++) {
    float tv = tb[(size_t)ci*HWP];
    #pragma unroll
    for (int j=0;j<36;j++) acc[j] += ws[j*64+ci]*tv;
  }
  float ks[9];
  #pragma unroll
  for (int k=0;k<9;k++) ks[k]=0.f;
  float* kwp = g_kw + (size_t)gp*36;
  #pragma unroll
  for (int s=0;s<4;s++) {
    float m = acc[s*9];
    #pragma unroll
    for (int k=1;k<9;k++) m = fmaxf(m, acc[s*9+k]);
    float e[9]; float sum=0.f;
    #pragma unroll
    for (int k=0;k<9;k++){ e[k]=expf(acc[s*9+k]-m); sum+=e[k]; }
    float inv = 1.f/sum;
    #pragma unroll
    for (int k=0;k<9;k++){ float v=e[k]*inv; kwp[s*9+k]=v; ks[k]+=v; }
  }
  float* ksp = g_kwsum + (size_t)gp*9;
  #pragma unroll
  for (int k=0;k<9;k++) ksp[k]=ks[k];
}

// ---------------- K3b: g map = 3x3 box correlation of kwsum -------------------
__global__ void k3b_gmap() {
  int gp = blockIdx.x*256 + threadIdx.x;
  int b = gp >> 12, p = gp & 4095;
  int i = p >> 6, j = p & 63;
  float s = 0.f;
  #pragma unroll
  for (int ih=0; ih<3; ih++)
    #pragma unroll
    for (int iw=0; iw<3; iw++) {
      int h = i + 1 - ih, w = j + 1 - iw;
      if ((unsigned)h < 64u && (unsigned)w < 64u)
        s += g_kwsum[(size_t)(b*4096 + h*64 + w)*9 + ih*3 + iw];
    }
  g_gmap[gp] = s;
}

// ---------------- K5: pooled[b,c] = sum(x*g)/16384 + sum(enh)/4096 ------------
__global__ __launch_bounds__(256) void k5_pool(const float* __restrict__ x) {
  int bc = blockIdx.x;               // 0..2047
  int b = bc >> 8;
  const float* xp = x      + (size_t)bc*HWP;
  const float* ep = g_enh  + (size_t)bc*HWP;
  const float* gp = g_gmap + (size_t)b*HWP;
  int tid = threadIdx.x;
  float s1=0.f, s2=0.f;
  for (int i = tid; i < HWP; i += 256) { s1 += xp[i]*gp[i]; s2 += ep[i]; }
  __shared__ float r1[256], r2[256];
  r1[tid]=s1; r2[tid]=s2;
  __syncthreads();
  for (int st=128; st>0; st>>=1) {
    if (tid < st) { r1[tid]+=r1[tid+st]; r2[tid]+=r2[tid+st]; }
    __syncthreads();
  }
  if (tid==0) g_pooled[bc] = r1[0]*(1.f/16384.f) + r2[0]*(1.f/4096.f);
}

// ---------------- K6: SE gate ---------------------------------------------------
__global__ __launch_bounds__(256) void k6_gate(const float* __restrict__ Wg1,
    const float* __restrict__ bg1, const float* __restrict__ Wg2,
    const float* __restrict__ bg2) {
  int b = blockIdx.x, tid = threadIdx.x;
  __shared__ float pl[256], hid[64];
  pl[tid] = g_pooled[b*256 + tid];
  __syncthreads();
  if (tid < 64) {
    float a = bg1[tid];
    for (int ci=0; ci<256; ci++) a += Wg1[tid*256+ci]*pl[ci];
    hid[tid] = a / (1.f + expf(-a));   // silu
  }
  __syncthreads();
  float a = bg2[tid];
  for (int j=0;j<64;j++) a += Wg2[tid*64+j]*hid[j];
  g_gate[b*256+tid] = 1.f/(1.f+expf(-a));
}

// ---------------- K7: reassembly + bilinear up + gate -> output ----------------
__global__ __launch_bounds__(256) void k7_fused(const float* __restrict__ x,
                                                float* __restrict__ out) {
  __shared__ float kws[64][37];
  __shared__ float xs[16][3][66];
  __shared__ float es[16][3][64];
  int tid = threadIdx.x;
  int wl = tid & 63, cs = tid >> 6;
  int c0 = blockIdx.x * 16;
  int h  = blockIdx.y;
  int b  = blockIdx.z;
  for (int i = tid; i < 2304; i += 256) {
    int w = i / 36, m = i % 36;
    kws[w][m] = g_kw[(size_t)(b*4096 + h*64 + w)*36 + m];
  }
  for (int i = tid; i < 16*3*66; i += 256) {
    int cc = i / 198, rem = i % 198;
    int r = rem / 66, col = rem % 66 - 1;
    int y = h + r - 1;
    float v = 0.f;
    if ((unsigned)y < 64u && (unsigned)col < 64u)
      v = x[((size_t)(b*CH)+c0+cc)*HWP + y*64 + col];
    xs[cc][r][col+1] = v;
  }
  for (int i = tid; i < 16*3*64; i += 256) {
    int cc = i / 192, rem = i % 192;
    int r = rem / 64, col = rem % 64;
    int y = min(max(h + r - 1, 0), 63);
    es[cc][r][col] = g_enh[((size_t)(b*CH)+c0+cc)*HWP + y*64 + col];
  }
  __syncthreads();
  // column interpolation for bilinear (half-pixel, clamped)
  int base; float fw;
  if (wl & 1) { base = (wl - 1) >> 1; fw = 0.25f; }
  else        { base = (wl >> 1) - 1; fw = 0.75f; }
  int cA0 = max(base, 0);
  int cB0 = base + 1;           // <=32, in range for dj=0
  int cA1 = base + 32;          // >=31, in range for dj=1
  int cB1 = min(base + 33, 63);
  float fw1 = 1.f - fw;
  #pragma unroll
  for (int qq = 0; qq < 4; qq++) {
    int cc = cs*4 + qq;
    int c  = c0 + cc;
    float gt = g_gate[b*256 + c];
    float x00=xs[cc][0][wl], x01=xs[cc][0][wl+1], x02=xs[cc][0][wl+2];
    float x10=xs[cc][1][wl], x11=xs[cc][1][wl+1], x12=xs[cc][1][wl+2];
    float x20=xs[cc][2][wl], x21=xs[cc][2][wl+1], x22=xs[cc][2][wl+2];
    float rv[3][2];
    #pragma unroll
    for (int r=0;r<3;r++) {
      rv[r][0] = fw1*es[cc][r][cA0] + fw*es[cc][r][cB0];
      rv[r][1] = fw1*es[cc][r][cA1] + fw*es[cc][r][cB1];
    }
    float up[2][2];
    up[0][0] = 0.25f*rv[0][0] + 0.75f*rv[1][0];
    up[0][1] = 0.25f*rv[0][1] + 0.75f*rv[1][1];
    up[1][0] = 0.75f*rv[1][0] + 0.25f*rv[2][0];
    up[1][1] = 0.75f*rv[1][1] + 0.25f*rv[2][1];
    #pragma unroll
    for (int s=0;s<4;s++) {
      const float* kp = &kws[wl][s*9];
      float ko = x00*kp[0]+x01*kp[1]+x02*kp[2]
               + x10*kp[3]+x11*kp[4]+x12*kp[5]
               + x20*kp[6]+x21*kp[7]+x22*kp[8];
      int di = s >> 1, dj = s & 1;
      size_t oidx = (size_t)(b*256 + c)*16384 + (size_t)(2*h+di)*128 + (size_t)(dj*64 + wl);
      out[oidx] = (ko + up[di][dj]) * gt;
    }
  }
}

// ---------------- launch --------------------------------------------------------
extern "C" void kernel_launch(void* const* d_in, const int* in_sizes, int n_in,
                              void* d_out, int out_size) {
  const float* x    = (const float*)d_in[0];
  const float* Wkc  = (const float*)d_in[1];
  const float* bkc  = (const float*)d_in[2];
  const float* Wkp1 = (const float*)d_in[3];
  const float* bkp1 = (const float*)d_in[4];
  const float* g1   = (const float*)d_in[5];
  const float* be1  = (const float*)d_in[6];
  const float* m1   = (const float*)d_in[7];
  const float* v1   = (const float*)d_in[8];
  const float* Wkp2 = (const float*)d_in[9];
  const float* bkp2 = (const float*)d_in[10];
  const float* Wdef = (const float*)d_in[11];
  const float* Wg1  = (const float*)d_in[12];
  const float* bg1  = (const float*)d_in[13];
  const float* Wg2  = (const float*)d_in[14];
  const float* bg2  = (const float*)d_in[15];
  float* out = (float*)d_out;

  float* comp = nullptr; float* t = nullptr; float* enh = nullptr;
  cudaGetSymbolAddress((void**)&comp, g_comp);
  cudaGetSymbolAddress((void**)&t,    g_t);
  cudaGetSymbolAddress((void**)&enh,  g_enh);

  k1_gemm<<<dim3(16,2,8),  256>>>(x, Wkc, bkc);
  conv3x3_t<128,true ><<<dim3(16,1,8), 256>>>(comp, Wkp1, t,   bkp1, g1, be1, m1, v1);
  k3_kw     <<<128,          256>>>(Wkp2, bkp2);
  k3b_gmap  <<<128,          256>>>();
  conv3x3_t<64, false><<<dim3(16,4,8), 256>>>(x, Wdef, enh, nullptr, nullptr, nullptr, nullptr, nullptr);
  k5_pool   <<<2048,         256>>>(x);
  k6_gate   <<<8,            256>>>(Wg1, bg1, Wg2, bg2);
  k7_fused  <<<dim3(16,64,8),256>>>(x, out);
}

// round 4
// speedup vs baseline: 1.7754x; 1.5671x over previous
#include <cuda_runtime.h>
#include <cuda_bf16.h>
#include <cstdint>
#include <math.h>

#define BATCH 8
#define CH    256
#define HWP   4096   // 64*64

// ---------------- scratch (static device allocations; no cudaMalloc) ----------
__device__ float g_comp [BATCH*128*HWP];
__device__ float g_t    [BATCH*64*HWP];
__device__ float g_kw   [BATCH*HWP*36];
__device__ float g_kwsum[BATCH*HWP*9];
__device__ float g_gmap [BATCH*HWP];
__device__ float g_enh  [BATCH*CH*HWP];
__device__ float g_pooled[BATCH*CH];
__device__ float g_gate  [BATCH*CH];

// ---------------- helpers ------------------------------------------------------
__device__ __forceinline__ uint32_t s2u(const void* p){
  uint32_t a; asm("{ .reg .u64 t; cvta.to.shared.u64 t, %1; cvt.u32.u64 %0, t; }"
                  : "=r"(a) : "l"(p)); return a;
}
__device__ __forceinline__ void bf16split(float v, uint16_t& h, uint16_t& l){
  __nv_bfloat16 hb = __float2bfloat16(v);
  float hf = __bfloat162float(hb);
  __nv_bfloat16 lb = __float2bfloat16(v - hf);
  h = __bfloat16_as_ushort(hb);
  l = __bfloat16_as_ushort(lb);
}
__device__ __forceinline__ void ldmx4(uint32_t r[4], uint32_t addr){
  asm volatile("ldmatrix.sync.aligned.m8n8.x4.shared.b16 {%0,%1,%2,%3}, [%4];"
               : "=r"(r[0]), "=r"(r[1]), "=r"(r[2]), "=r"(r[3]) : "r"(addr));
}
__device__ __forceinline__ void mma_bf16(float c[4], const uint32_t a[4],
                                         uint32_t b0, uint32_t b1){
  asm volatile("mma.sync.aligned.m16n8k16.row.col.f32.bf16.bf16.f32 "
               "{%0,%1,%2,%3},{%4,%5,%6,%7},{%8,%9},{%0,%1,%2,%3};"
               : "+f"(c[0]), "+f"(c[1]), "+f"(c[2]), "+f"(c[3])
               : "r"(a[0]), "r"(a[1]), "r"(a[2]), "r"(a[3]), "r"(b0), "r"(b1));
}

// ================= implicit-GEMM conv on HMMA bf16 (3-pass split) =============
// CTA: 128 px (2 image rows) x 64 output channels.  K loop: 16-ci blocks x taps.
// A = pixels [px][ci16] (ldmatrix, tap shift = pointer offset, built ONCE per
//     ci-block); B = weights [tap][co][ci16] (plain LDS b32).
// EPI: 0 = +bias, 1 = +bias,BN,SiLU, 2 = raw
template<int CI, int TAPS, int EPI, int GROUPED>
__global__ __launch_bounds__(256) void conv_mma(
    const float* __restrict__ in, const float* __restrict__ W,
    float* __restrict__ out,
    const float* __restrict__ bias, const float* __restrict__ g1,
    const float* __restrict__ be1, const float* __restrict__ m1,
    const float* __restrict__ v1) {
  extern __shared__ char sm[];
  constexpr uint32_t P_BYTES = 4*66*16*2;                 // 8448
  constexpr uint32_t OP_H = 0, OP_L = P_BYTES;
  constexpr uint32_t OW_H = 2*P_BYTES;                    // 16896
  constexpr uint32_t W_BYTES = TAPS*64*16*2;
  constexpr uint32_t OW_L = OW_H + W_BYTES;
  constexpr uint32_t OOUT = OW_H + 2*W_BYTES;

  const int tid = threadIdx.x;
  const int lane = tid & 31, wid = tid >> 5;
  const int wy = wid >> 1, wx = wid & 1;                  // 4 m-warps x 2 n-warps
  const int g = lane >> 2, tq = lane & 3;
  const int y0 = blockIdx.x * 2;
  const int cob = blockIdx.y;
  const int co0 = cob * 64;
  const int b = blockIdx.z;
  const int nco = gridDim.y * 64;
  const int nch = GROUPED ? gridDim.y * CI : CI;
  const int in_off = GROUPED ? cob * CI : 0;
  const float* inb = in + ((size_t)b*nch + in_off)*HWP;
  const uint32_t sbase = s2u(sm);

  float cacc[2][4][4];
  #pragma unroll
  for (int mm = 0; mm < 2; mm++)
    #pragma unroll
    for (int nn = 0; nn < 4; nn++)
      #pragma unroll
      for (int j = 0; j < 4; j++) cacc[mm][nn][j] = 0.f;

  for (int cb = 0; cb < CI/16; cb++) {
    __syncthreads();
    // ---- build pixel tile [4 rows halo][66 cols][16 ci] hi/lo ----
    for (int i = tid; i < 528; i += 256) {
      int half = i & 1, slot = i >> 1;
      int r = slot / 66, c = slot - r*66;
      int y = y0 + r - 1, xx = c - 1;
      bool ok = ((unsigned)y < 64u) && ((unsigned)xx < 64u);
      const float* src = inb + (size_t)(cb*16 + half*8)*HWP + y*64 + xx;
      uint32_t hw[4], lw[4];
      #pragma unroll
      for (int jj = 0; jj < 4; jj++) {
        float v0 = ok ? src[(size_t)(2*jj)*HWP]   : 0.f;
        float v1 = ok ? src[(size_t)(2*jj+1)*HWP] : 0.f;
        uint16_t h0,l0,h1,l1;
        bf16split(v0,h0,l0); bf16split(v1,h1,l1);
        hw[jj] = (uint32_t)h0 | ((uint32_t)h1 << 16);
        lw[jj] = (uint32_t)l0 | ((uint32_t)l1 << 16);
      }
      uint32_t boff = (uint32_t)slot*32 + half*16;
      *(uint4*)(sm + OP_H + boff) = make_uint4(hw[0],hw[1],hw[2],hw[3]);
      *(uint4*)(sm + OP_L + boff) = make_uint4(lw[0],lw[1],lw[2],lw[3]);
    }
    // ---- build weight tile [tap][64 co][16 ci] hi/lo (float4 gmem reads) ----
    constexpr int PERM = TAPS*4;   // float4 per co-row for this ci-block
    for (int i = tid; i < 64*PERM; i += 256) {
      int m = i / PERM, q = i - m*PERM;
      const float* wm = W + ((size_t)(co0+m)*CI + cb*16)*TAPS;
      float4 v = *(const float4*)(wm + q*4);
      #pragma unroll
      for (int j = 0; j < 4; j++) {
        int e = q*4 + j;
        int ci = e / TAPS, t = e - ci*TAPS;
        uint16_t h, l;
        bf16split((&v.x)[j], h, l);
        uint32_t off = (uint32_t)((t*64 + m)*16 + ci)*2;
        *(uint16_t*)(sm + OW_H + off) = h;
        *(uint16_t*)(sm + OW_L + off) = l;
      }
    }
    __syncthreads();
    // ---- taps: shift pixel pointers, mma ----
    #pragma unroll 1
    for (int tap = 0; tap < TAPS; tap++) {
      int dy = (TAPS == 9) ? tap/3 - 1 : 0;
      int dx = (TAPS == 9) ? tap - (tap/3)*3 - 1 : 0;
      uint32_t ah[2][4], al[2][4];
      #pragma unroll
      for (int mm = 0; mm < 2; mm++) {
        int pxm = wy*32 + mm*16 + (lane & 15);
        int rr = (pxm >> 6) + 1 + dy;
        int cc = (pxm & 63) + 1 + dx;
        uint32_t boff = (uint32_t)(rr*66 + cc)*32 + ((lane >> 4) & 1)*16;
        ldmx4(ah[mm], sbase + OP_H + boff);
        ldmx4(al[mm], sbase + OP_L + boff);
      }
      #pragma unroll
      for (int nn = 0; nn < 4; nn++) {
        int cof = wx*32 + nn*8 + g;
        uint32_t woff = (uint32_t)((tap*64 + cof)*16 + tq*2)*2;
        uint32_t bh0 = *(const uint32_t*)(sm + OW_H + woff);
        uint32_t bh1 = *(const uint32_t*)(sm + OW_H + woff + 16);
        uint32_t bl0 = *(const uint32_t*)(sm + OW_L + woff);
        uint32_t bl1 = *(const uint32_t*)(sm + OW_L + woff + 16);
        #pragma unroll
        for (int mm = 0; mm < 2; mm++) {
          mma_bf16(cacc[mm][nn], ah[mm], bh0, bh1);
          mma_bf16(cacc[mm][nn], ah[mm], bl0, bl1);
          mma_bf16(cacc[mm][nn], al[mm], bh0, bh1);
        }
      }
    }
  }
  // ---- epilogue: c frags -> padded smem -> coalesced gmem ----
  __syncthreads();
  float* osm = (float*)(sm + OOUT);
  #pragma unroll
  for (int mm = 0; mm < 2; mm++)
    #pragma unroll
    for (int nn = 0; nn < 4; nn++) {
      int px  = wy*32 + mm*16 + g;
      int col = wx*32 + nn*8 + tq*2;
      osm[(col  )*130 + px    ] = cacc[mm][nn][0];
      osm[(col+1)*130 + px    ] = cacc[mm][nn][1];
      osm[(col  )*130 + px + 8] = cacc[mm][nn][2];
      osm[(col+1)*130 + px + 8] = cacc[mm][nn][3];
    }
  __syncthreads();
  for (int i = tid; i < 8192; i += 256) {
    int col = i >> 7, px = i & 127;
    float v = osm[col*130 + px];
    int cg = co0 + col;
    if (EPI == 0) v += bias[cg];
    if (EPI == 1) {
      float sc = g1[cg] * rsqrtf(v1[cg] + 1e-5f);
      float sh = be1[cg] - m1[cg]*sc;
      v = (v + bias[cg])*sc + sh;
      v = v / (1.f + expf(-v));
    }
    out[((size_t)(b*nco + cg))*HWP + y0*64 + px] = v;
  }
}

// ---------------- K3: 1x1 conv 64->36 + softmax(9) groups ---------------------
__global__ __launch_bounds__(256) void k3_kw(const float* __restrict__ Wkp2,
                                             const float* __restrict__ bkp2) {
  __shared__ float ws[36*64];
  __shared__ float bs[36];
  int tid = threadIdx.x;
  for (int i = tid; i < 2304; i += 256) ws[i] = Wkp2[i];
  if (tid < 36) bs[tid] = bkp2[tid];
  __syncthreads();
  int gp = blockIdx.x*256 + tid;
  int b = gp >> 12, p = gp & 4095;
  float acc[36];
  #pragma unroll
  for (int j=0;j<36;j++) acc[j]=bs[j];
  const float* tb = g_t + (size_t)b*64*HWP + p;
  for (int ci=0; ci<64; ci++) {
    float tv = tb[(size_t)ci*HWP];
    #pragma unroll
    for (int j=0;j<36;j++) acc[j] += ws[j*64+ci]*tv;
  }
  float ks[9];
  #pragma unroll
  for (int k=0;k<9;k++) ks[k]=0.f;
  float* kwp = g_kw + (size_t)gp*36;
  #pragma unroll
  for (int s=0;s<4;s++) {
    float m = acc[s*9];
    #pragma unroll
    for (int k=1;k<9;k++) m = fmaxf(m, acc[s*9+k]);
    float e[9]; float sum=0.f;
    #pragma unroll
    for (int k=0;k<9;k++){ e[k]=expf(acc[s*9+k]-m); sum+=e[k]; }
    float inv = 1.f/sum;
    #pragma unroll
    for (int k=0;k<9;k++){ float v=e[k]*inv; kwp[s*9+k]=v; ks[k]+=v; }
  }
  float* ksp = g_kwsum + (size_t)gp*9;
  #pragma unroll
  for (int k=0;k<9;k++) ksp[k]=ks[k];
}

// ---------------- K3b: g map = 3x3 box correlation of kwsum -------------------
__global__ void k3b_gmap() {
  int gp = blockIdx.x*256 + threadIdx.x;
  int b = gp >> 12, p = gp & 4095;
  int i = p >> 6, j = p & 63;
  float s = 0.f;
  #pragma unroll
  for (int ih=0; ih<3; ih++)
    #pragma unroll
    for (int iw=0; iw<3; iw++) {
      int h = i + 1 - ih, w = j + 1 - iw;
      if ((unsigned)h < 64u && (unsigned)w < 64u)
        s += g_kwsum[(size_t)(b*4096 + h*64 + w)*9 + ih*3 + iw];
    }
  g_gmap[gp] = s;
}

// ---------------- K5: pooled[b,c] = sum(x*g)/16384 + sum(enh)/4096 ------------
__global__ __launch_bounds__(256) void k5_pool(const float* __restrict__ x) {
  int bc = blockIdx.x;
  int b = bc >> 8;
  const float* xp = x      + (size_t)bc*HWP;
  const float* ep = g_enh  + (size_t)bc*HWP;
  const float* gp = g_gmap + (size_t)b*HWP;
  int tid = threadIdx.x;
  float s1=0.f, s2=0.f;
  for (int i = tid; i < HWP; i += 256) { s1 += xp[i]*gp[i]; s2 += ep[i]; }
  __shared__ float r1[256], r2[256];
  r1[tid]=s1; r2[tid]=s2;
  __syncthreads();
  for (int st=128; st>0; st>>=1) {
    if (tid < st) { r1[tid]+=r1[tid+st]; r2[tid]+=r2[tid+st]; }
    __syncthreads();
  }
  if (tid==0) g_pooled[bc] = r1[0]*(1.f/16384.f) + r2[0]*(1.f/4096.f);
}

// ---------------- K6: SE gate ---------------------------------------------------
__global__ __launch_bounds__(256) void k6_gate(const float* __restrict__ Wg1,
    const float* __restrict__ bg1, const float* __restrict__ Wg2,
    const float* __restrict__ bg2) {
  int b = blockIdx.x, tid = threadIdx.x;
  __shared__ float pl[256], hid[64];
  pl[tid] = g_pooled[b*256 + tid];
  __syncthreads();
  if (tid < 64) {
    float a = bg1[tid];
    for (int ci=0; ci<256; ci++) a += Wg1[tid*256+ci]*pl[ci];
    hid[tid] = a / (1.f + expf(-a));
  }
  __syncthreads();
  float a = bg2[tid];
  for (int j=0;j<64;j++) a += Wg2[tid*64+j]*hid[j];
  g_gate[b*256+tid] = 1.f/(1.f+expf(-a));
}

// ---------------- K7: reassembly + bilinear up + gate -> output ----------------
__global__ __launch_bounds__(256) void k7_fused(const float* __restrict__ x,
                                                float* __restrict__ out) {
  __shared__ float kws[64][37];
  __shared__ float xs[16][3][66];
  __shared__ float es[16][3][64];
  int tid = threadIdx.x;
  int wl = tid & 63, cs = tid >> 6;
  int c0 = blockIdx.x * 16;
  int h  = blockIdx.y;
  int b  = blockIdx.z;
  for (int i = tid; i < 2304; i += 256) {
    int w = i / 36, m = i % 36;
    kws[w][m] = g_kw[(size_t)(b*4096 + h*64 + w)*36 + m];
  }
  for (int i = tid; i < 16*3*66; i += 256) {
    int cc = i / 198, rem = i % 198;
    int r = rem / 66, col = rem % 66 - 1;
    int y = h + r - 1;
    float v = 0.f;
    if ((unsigned)y < 64u && (unsigned)col < 64u)
      v = x[((size_t)(b*CH)+c0+cc)*HWP + y*64 + col];
    xs[cc][r][col+1] = v;
  }
  for (int i = tid; i < 16*3*64; i += 256) {
    int cc = i / 192, rem = i % 192;
    int r = rem / 64, col = rem % 64;
    int y = min(max(h + r - 1, 0), 63);
    es[cc][r][col] = g_enh[((size_t)(b*CH)+c0+cc)*HWP + y*64 + col];
  }
  __syncthreads();
  int base; float fw;
  if (wl & 1) { base = (wl - 1) >> 1; fw = 0.25f; }
  else        { base = (wl >> 1) - 1; fw = 0.75f; }
  int cA0 = max(base, 0);
  int cB0 = base + 1;
  int cA1 = base + 32;
  int cB1 = min(base + 33, 63);
  float fw1 = 1.f - fw;
  #pragma unroll
  for (int qq = 0; qq < 4; qq++) {
    int cc = cs*4 + qq;
    int c  = c0 + cc;
    float gt = g_gate[b*256 + c];
    float x00=xs[cc][0][wl], x01=xs[cc][0][wl+1], x02=xs[cc][0][wl+2];
    float x10=xs[cc][1][wl], x11=xs[cc][1][wl+1], x12=xs[cc][1][wl+2];
    float x20=xs[cc][2][wl], x21=xs[cc][2][wl+1], x22=xs[cc][2][wl+2];
    float rv[3][2];
    #pragma unroll
    for (int r=0;r<3;r++) {
      rv[r][0] = fw1*es[cc][r][cA0] + fw*es[cc][r][cB0];
      rv[r][1] = fw1*es[cc][r][cA1] + fw*es[cc][r][cB1];
    }
    float up[2][2];
    up[0][0] = 0.25f*rv[0][0] + 0.75f*rv[1][0];
    up[0][1] = 0.25f*rv[0][1] + 0.75f*rv[1][1];
    up[1][0] = 0.75f*rv[1][0] + 0.25f*rv[2][0];
    up[1][1] = 0.75f*rv[1][1] + 0.25f*rv[2][1];
    #pragma unroll
    for (int s=0;s<4;s++) {
      const float* kp = &kws[wl][s*9];
      float ko = x00*kp[0]+x01*kp[1]+x02*kp[2]
               + x10*kp[3]+x11*kp[4]+x12*kp[5]
               + x20*kp[6]+x21*kp[7]+x22*kp[8];
      int di = s >> 1, dj = s & 1;
      size_t oidx = (size_t)(b*256 + c)*16384 + (size_t)(2*h+di)*128 + (size_t)(dj*64 + wl);
      out[oidx] = (ko + up[di][dj]) * gt;
    }
  }
}

// ---------------- launch --------------------------------------------------------
extern "C" void kernel_launch(void* const* d_in, const int* in_sizes, int n_in,
                              void* d_out, int out_size) {
  const float* x    = (const float*)d_in[0];
  const float* Wkc  = (const float*)d_in[1];
  const float* bkc  = (const float*)d_in[2];
  const float* Wkp1 = (const float*)d_in[3];
  const float* bkp1 = (const float*)d_in[4];
  const float* g1   = (const float*)d_in[5];
  const float* be1  = (const float*)d_in[6];
  const float* m1   = (const float*)d_in[7];
  const float* v1   = (const float*)d_in[8];
  const float* Wkp2 = (const float*)d_in[9];
  const float* bkp2 = (const float*)d_in[10];
  const float* Wdef = (const float*)d_in[11];
  const float* Wg1  = (const float*)d_in[12];
  const float* bg1  = (const float*)d_in[13];
  const float* Wg2  = (const float*)d_in[14];
  const float* bg2  = (const float*)d_in[15];
  float* out = (float*)d_out;

  float* comp = nullptr; float* t = nullptr; float* enh = nullptr;
  cudaGetSymbolAddress((void**)&comp, g_comp);
  cudaGetSymbolAddress((void**)&t,    g_t);
  cudaGetSymbolAddress((void**)&enh,  g_enh);

  // dynamic smem sizes: 2*P(8448) + 2*W(TAPS*2048) + out stage (64*130*4)
  const int SM_9TAP = 16896 + 2*9*2048 + 64*130*4;  // 87040
  const int SM_1TAP = 16896 + 2*1*2048 + 64*130*4;  // 54272

  cudaFuncSetAttribute(conv_mma<256,1,0,0>, cudaFuncAttributeMaxDynamicSharedMemorySize, SM_1TAP);
  cudaFuncSetAttribute(conv_mma<128,9,1,0>, cudaFuncAttributeMaxDynamicSharedMemorySize, SM_9TAP);
  cudaFuncSetAttribute(conv_mma<64,9,2,1>,  cudaFuncAttributeMaxDynamicSharedMemorySize, SM_9TAP);

  conv_mma<256,1,0,0><<<dim3(32,2,8), 256, SM_1TAP>>>(x,    Wkc,  comp, bkc,  nullptr, nullptr, nullptr, nullptr);
  conv_mma<128,9,1,0><<<dim3(32,1,8), 256, SM_9TAP>>>(comp, Wkp1, t,    bkp1, g1, be1, m1, v1);
  k3_kw     <<<128,          256>>>(Wkp2, bkp2);
  conv_mma<64,9,2,1> <<<dim3(32,4,8), 256, SM_9TAP>>>(x,    Wdef, enh,  nullptr, nullptr, nullptr, nullptr, nullptr);
  k3b_gmap  <<<128,          256>>>();
  k5_pool   <<<2048,         256>>>(x);
  k6_gate   <<<8,            256>>>(Wg1, bg1, Wg2, bg2);
  k7_fused  <<<dim3(16,64,8),256>>>(x, out);
}

// round 5
// speedup vs baseline: 1.9560x; 1.1018x over previous
#include <cuda_runtime.h>
#include <cuda_bf16.h>
#include <cstdint>
#include <math.h>

#define BATCH 8
#define CH    256
#define HWP   4096   // 64*64

// ---------------- scratch (static device allocations; no cudaMalloc) ----------
__device__ float g_comp [BATCH*128*HWP];
__device__ float g_t    [BATCH*64*HWP];
__device__ float g_kw   [BATCH*HWP*36];
__device__ float g_kwsum[BATCH*HWP*9];
__device__ float g_gmap [BATCH*HWP];
__device__ float g_enh  [BATCH*CH*HWP];
__device__ float g_pooled[BATCH*CH];
__device__ float g_gate  [BATCH*CH];

// ---------------- helpers ------------------------------------------------------
__device__ __forceinline__ uint32_t s2u(const void* p){
  uint32_t a; asm("{ .reg .u64 t; cvta.to.shared.u64 t, %1; cvt.u32.u64 %0, t; }"
                  : "=r"(a) : "l"(p)); return a;
}
__device__ __forceinline__ void bf16split(float v, uint16_t& h, uint16_t& l){
  __nv_bfloat16 hb = __float2bfloat16(v);
  float hf = __bfloat162float(hb);
  __nv_bfloat16 lb = __float2bfloat16(v - hf);
  h = __bfloat16_as_ushort(hb);
  l = __bfloat16_as_ushort(lb);
}
__device__ __forceinline__ void ldmx4(uint32_t r[4], uint32_t addr){
  asm volatile("ldmatrix.sync.aligned.m8n8.x4.shared.b16 {%0,%1,%2,%3}, [%4];"
               : "=r"(r[0]), "=r"(r[1]), "=r"(r[2]), "=r"(r[3]) : "r"(addr));
}
__device__ __forceinline__ void mma_bf16(float c[4], const uint32_t a[4],
                                         uint32_t b0, uint32_t b1){
  asm volatile("mma.sync.aligned.m16n8k16.row.col.f32.bf16.bf16.f32 "
               "{%0,%1,%2,%3},{%4,%5,%6,%7},{%8,%9},{%0,%1,%2,%3};"
               : "+f"(c[0]), "+f"(c[1]), "+f"(c[2]), "+f"(c[3])
               : "r"(a[0]), "r"(a[1]), "r"(a[2]), "r"(a[3]), "r"(b0), "r"(b1));
}

// ================= implicit-GEMM conv on HMMA bf16 (3-pass split) =============
// CTA: 256 px (4 image rows) x 64 output channels. Warps: 4m x 2n, each warp
// computes 64px x 32co (mm=4, nn=4). Pixel tile: 6 rows x 66 cols halo, slot
// stride 48B (bank-conflict-free ldmatrix). Weights: [tap][co][16ci] with ci
// re-paired (k,k+8 adjacent) so each B fragment half is one 8B LDS.64.
// EPI: 0 = +bias, 1 = +bias,BN,SiLU, 2 = raw
template<int CI, int TAPS, int EPI, int GROUPED>
__global__ __launch_bounds__(256, 2) void conv_mma(
    const float* __restrict__ in, const float* __restrict__ W,
    float* __restrict__ out,
    const float* __restrict__ bias, const float* __restrict__ g1,
    const float* __restrict__ be1, const float* __restrict__ m1,
    const float* __restrict__ v1) {
  extern __shared__ char sm[];
  constexpr uint32_t P_BYTES = 6*66*48;                   // 19008 per half
  constexpr uint32_t OP_H = 0, OP_L = P_BYTES;
  constexpr uint32_t OW_H = 2*P_BYTES;                    // 38016
  constexpr uint32_t W_BYTES = TAPS*64*32;                // 16ci*2B per co
  constexpr uint32_t OW_L = OW_H + W_BYTES;

  const int tid = threadIdx.x;
  const int lane = tid & 31, wid = tid >> 5;
  const int wy = wid >> 1, wx = wid & 1;                  // 4 m-warps x 2 n-warps
  const int g = lane >> 2, tq = lane & 3;
  const int rowblk = blockIdx.x;                          // 4 image rows
  const int cob = blockIdx.y;
  const int co0 = cob * 64;
  const int b = blockIdx.z;
  const int nco = gridDim.y * 64;
  const int nch = GROUPED ? gridDim.y * CI : CI;
  const int in_off = GROUPED ? cob * CI : 0;
  const float* inb = in + ((size_t)b*nch + in_off)*HWP;
  const uint32_t sbase = s2u(sm);

  float cacc[4][4][4];
  #pragma unroll
  for (int mm = 0; mm < 4; mm++)
    #pragma unroll
    for (int nn = 0; nn < 4; nn++)
      #pragma unroll
      for (int j = 0; j < 4; j++) cacc[mm][nn][j] = 0.f;

  for (int cb = 0; cb < CI/16; cb++) {
    __syncthreads();
    // ---- pixel tile [6 rows][66 cols][16 ci], 48B slot stride, hi/lo ----
    for (int i = tid; i < 792; i += 256) {
      int half = i & 1, slot = i >> 1;
      int r = slot / 66, c = slot - r*66;
      int y = rowblk*4 + r - 1, xx = c - 1;
      bool ok = ((unsigned)y < 64u) && ((unsigned)xx < 64u);
      const float* src = inb + (size_t)(cb*16 + half*8)*HWP + y*64 + xx;
      uint32_t hw[4], lw[4];
      #pragma unroll
      for (int jj = 0; jj < 4; jj++) {
        float v0 = ok ? src[(size_t)(2*jj)*HWP]   : 0.f;
        float v1 = ok ? src[(size_t)(2*jj+1)*HWP] : 0.f;
        uint16_t h0,l0,h1,l1;
        bf16split(v0,h0,l0); bf16split(v1,h1,l1);
        hw[jj] = (uint32_t)h0 | ((uint32_t)h1 << 16);
        lw[jj] = (uint32_t)l0 | ((uint32_t)l1 << 16);
      }
      uint32_t boff = (uint32_t)slot*48 + half*16;
      *(uint4*)(sm + OP_H + boff) = make_uint4(hw[0],hw[1],hw[2],hw[3]);
      *(uint4*)(sm + OP_L + boff) = make_uint4(lw[0],lw[1],lw[2],lw[3]);
    }
    // ---- weight tile [tap][64 co][16 ci re-paired] hi/lo ----
    constexpr int PERM = TAPS*4;   // float4 per co-row for this ci-block
    for (int i = tid; i < 64*PERM; i += 256) {
      int m = i / PERM, q = i - m*PERM;
      const float* wm = W + ((size_t)(co0+m)*CI + cb*16)*TAPS;
      float4 v = *(const float4*)(wm + q*4);
      #pragma unroll
      for (int j = 0; j < 4; j++) {
        int e = q*4 + j;
        int ci = e / TAPS, t = e - ci*TAPS;
        int pos = ((ci & 7) >> 1)*4 + (ci >> 3)*2 + (ci & 1);
        uint16_t h, l;
        bf16split((&v.x)[j], h, l);
        uint32_t off = (uint32_t)((t*64 + m)*16 + pos)*2;
        *(uint16_t*)(sm + OW_H + off) = h;
        *(uint16_t*)(sm + OW_L + off) = l;
      }
    }
    __syncthreads();
    // ---- taps: shift pixel pointers, mma ----
    #pragma unroll 1
    for (int tap = 0; tap < TAPS; tap++) {
      int dy = (TAPS == 9) ? tap/3 - 1 : 0;
      int dx = (TAPS == 9) ? tap - (tap/3)*3 - 1 : 0;
      uint32_t ah[4][4], al[4][4];
      #pragma unroll
      for (int mm = 0; mm < 4; mm++) {
        int pxm = wy*64 + mm*16 + (lane & 15);
        int rr = (pxm >> 6) + 1 + dy;
        int cc = (pxm & 63) + 1 + dx;
        uint32_t boff = (uint32_t)(rr*66 + cc)*48 + ((lane >> 4) & 1)*16;
        ldmx4(ah[mm], sbase + OP_H + boff);
        ldmx4(al[mm], sbase + OP_L + boff);
      }
      #pragma unroll
      for (int nn = 0; nn < 4; nn++) {
        int cof = wx*32 + nn*8 + g;
        uint32_t woff = (uint32_t)(tap*64 + cof)*32 + tq*8;
        uint2 bh = *(const uint2*)(sm + OW_H + woff);
        uint2 bl = *(const uint2*)(sm + OW_L + woff);
        #pragma unroll
        for (int mm = 0; mm < 4; mm++) {
          mma_bf16(cacc[mm][nn], ah[mm], bh.x, bh.y);
          mma_bf16(cacc[mm][nn], ah[mm], bl.x, bl.y);
          mma_bf16(cacc[mm][nn], al[mm], bh.x, bh.y);
        }
      }
    }
  }
  // ---- epilogue: frags -> smem stage (stride 260 = conflict-free) -> gmem ----
  __syncthreads();
  float* osm = (float*)sm;
  #pragma unroll
  for (int mm = 0; mm < 4; mm++)
    #pragma unroll
    for (int nn = 0; nn < 4; nn++) {
      int px  = wy*64 + mm*16 + g;
      int col = wx*32 + nn*8 + tq*2;
      osm[(col  )*260 + px    ] = cacc[mm][nn][0];
      osm[(col+1)*260 + px    ] = cacc[mm][nn][1];
      osm[(col  )*260 + px + 8] = cacc[mm][nn][2];
      osm[(col+1)*260 + px + 8] = cacc[mm][nn][3];
    }
  __syncthreads();
  for (int i = tid; i < 16384; i += 256) {
    int col = i >> 8, px = i & 255;
    float v = osm[col*260 + px];
    int cg = co0 + col;
    if (EPI == 0) v += bias[cg];
    if (EPI == 1) {
      float sc = g1[cg] * rsqrtf(v1[cg] + 1e-5f);
      float sh = be1[cg] - m1[cg]*sc;
      v = (v + bias[cg])*sc + sh;
      v = v / (1.f + expf(-v));
    }
    out[((size_t)(b*nco + cg))*HWP + rowblk*256 + px] = v;
  }
}

// ---------------- K3: 1x1 conv 64->36 + softmax(9) groups ---------------------
__global__ __launch_bounds__(256) void k3_kw(const float* __restrict__ Wkp2,
                                             const float* __restrict__ bkp2) {
  __shared__ float ws[36*64];
  __shared__ float bs[36];
  int tid = threadIdx.x;
  for (int i = tid; i < 2304; i += 256) ws[i] = Wkp2[i];
  if (tid < 36) bs[tid] = bkp2[tid];
  __syncthreads();
  int gp = blockIdx.x*256 + tid;
  int b = gp >> 12, p = gp & 4095;
  float acc[36];
  #pragma unroll
  for (int j=0;j<36;j++) acc[j]=bs[j];
  const float* tb = g_t + (size_t)b*64*HWP + p;
  for (int ci=0; ci<64; ci++) {
    float tv = tb[(size_t)ci*HWP];
    #pragma unroll
    for (int j=0;j<36;j++) acc[j] += ws[j*64+ci]*tv;
  }
  float ks[9];
  #pragma unroll
  for (int k=0;k<9;k++) ks[k]=0.f;
  float* kwp = g_kw + (size_t)gp*36;
  #pragma unroll
  for (int s=0;s<4;s++) {
    float m = acc[s*9];
    #pragma unroll
    for (int k=1;k<9;k++) m = fmaxf(m, acc[s*9+k]);
    float e[9]; float sum=0.f;
    #pragma unroll
    for (int k=0;k<9;k++){ e[k]=expf(acc[s*9+k]-m); sum+=e[k]; }
    float inv = 1.f/sum;
    #pragma unroll
    for (int k=0;k<9;k++){ float v=e[k]*inv; kwp[s*9+k]=v; ks[k]+=v; }
  }
  float* ksp = g_kwsum + (size_t)gp*9;
  #pragma unroll
  for (int k=0;k<9;k++) ksp[k]=ks[k];
}

// ---------------- K3b: g map = 3x3 box correlation of kwsum -------------------
__global__ void k3b_gmap() {
  int gp = blockIdx.x*256 + threadIdx.x;
  int b = gp >> 12, p = gp & 4095;
  int i = p >> 6, j = p & 63;
  float s = 0.f;
  #pragma unroll
  for (int ih=0; ih<3; ih++)
    #pragma unroll
    for (int iw=0; iw<3; iw++) {
      int h = i + 1 - ih, w = j + 1 - iw;
      if ((unsigned)h < 64u && (unsigned)w < 64u)
        s += g_kwsum[(size_t)(b*4096 + h*64 + w)*9 + ih*3 + iw];
    }
  g_gmap[gp] = s;
}

// ---------------- K5: pooled[b,c] = sum(x*g)/16384 + sum(enh)/4096 ------------
__global__ __launch_bounds__(256) void k5_pool(const float* __restrict__ x) {
  int bc = blockIdx.x;
  int b = bc >> 8;
  const float* xp = x      + (size_t)bc*HWP;
  const float* ep = g_enh  + (size_t)bc*HWP;
  const float* gp = g_gmap + (size_t)b*HWP;
  int tid = threadIdx.x;
  float s1=0.f, s2=0.f;
  for (int i = tid; i < HWP; i += 256) { s1 += xp[i]*gp[i]; s2 += ep[i]; }
  __shared__ float r1[256], r2[256];
  r1[tid]=s1; r2[tid]=s2;
  __syncthreads();
  for (int st=128; st>0; st>>=1) {
    if (tid < st) { r1[tid]+=r1[tid+st]; r2[tid]+=r2[tid+st]; }
    __syncthreads();
  }
  if (tid==0) g_pooled[bc] = r1[0]*(1.f/16384.f) + r2[0]*(1.f/4096.f);
}

// ---------------- K6: SE gate ---------------------------------------------------
__global__ __launch_bounds__(256) void k6_gate(const float* __restrict__ Wg1,
    const float* __restrict__ bg1, const float* __restrict__ Wg2,
    const float* __restrict__ bg2) {
  int b = blockIdx.x, tid = threadIdx.x;
  __shared__ float pl[256], hid[64];
  pl[tid] = g_pooled[b*256 + tid];
  __syncthreads();
  if (tid < 64) {
    float a = bg1[tid];
    for (int ci=0; ci<256; ci++) a += Wg1[tid*256+ci]*pl[ci];
    hid[tid] = a / (1.f + expf(-a));
  }
  __syncthreads();
  float a = bg2[tid];
  for (int j=0;j<64;j++) a += Wg2[tid*64+j]*hid[j];
  g_gate[b*256+tid] = 1.f/(1.f+expf(-a));
}

// ---------------- K7: reassembly + bilinear up + gate -> output ----------------
__global__ __launch_bounds__(256) void k7_fused(const float* __restrict__ x,
                                                float* __restrict__ out) {
  __shared__ float kws[64][37];
  __shared__ float xs[16][3][66];
  __shared__ float es[16][3][64];
  int tid = threadIdx.x;
  int wl = tid & 63, cs = tid >> 6;
  int c0 = blockIdx.x * 16;
  int h  = blockIdx.y;
  int b  = blockIdx.z;
  for (int i = tid; i < 2304; i += 256) {
    int w = i / 36, m = i % 36;
    kws[w][m] = g_kw[(size_t)(b*4096 + h*64 + w)*36 + m];
  }
  for (int i = tid; i < 16*3*66; i += 256) {
    int cc = i / 198, rem = i % 198;
    int r = rem / 66, col = rem % 66 - 1;
    int y = h + r - 1;
    float v = 0.f;
    if ((unsigned)y < 64u && (unsigned)col < 64u)
      v = x[((size_t)(b*CH)+c0+cc)*HWP + y*64 + col];
    xs[cc][r][col+1] = v;
  }
  for (int i = tid; i < 16*3*64; i += 256) {
    int cc = i / 192, rem = i % 192;
    int r = rem / 64, col = rem % 64;
    int y = min(max(h + r - 1, 0), 63);
    es[cc][r][col] = g_enh[((size_t)(b*CH)+c0+cc)*HWP + y*64 + col];
  }
  __syncthreads();
  int base; float fw;
  if (wl & 1) { base = (wl - 1) >> 1; fw = 0.25f; }
  else        { base = (wl >> 1) - 1; fw = 0.75f; }
  int cA0 = max(base, 0);
  int cB0 = base + 1;
  int cA1 = base + 32;
  int cB1 = min(base + 33, 63);
  float fw1 = 1.f - fw;
  #pragma unroll
  for (int qq = 0; qq < 4; qq++) {
    int cc = cs*4 + qq;
    int c  = c0 + cc;
    float gt = g_gate[b*256 + c];
    float x00=xs[cc][0][wl], x01=xs[cc][0][wl+1], x02=xs[cc][0][wl+2];
    float x10=xs[cc][1][wl], x11=xs[cc][1][wl+1], x12=xs[cc][1][wl+2];
    float x20=xs[cc][2][wl], x21=xs[cc][2][wl+1], x22=xs[cc][2][wl+2];
    float rv[3][2];
    #pragma unroll
    for (int r=0;r<3;r++) {
      rv[r][0] = fw1*es[cc][r][cA0] + fw*es[cc][r][cB0];
      rv[r][1] = fw1*es[cc][r][cA1] + fw*es[cc][r][cB1];
    }
    float up[2][2];
    up[0][0] = 0.25f*rv[0][0] + 0.75f*rv[1][0];
    up[0][1] = 0.25f*rv[0][1] + 0.75f*rv[1][1];
    up[1][0] = 0.75f*rv[1][0] + 0.25f*rv[2][0];
    up[1][1] = 0.75f*rv[1][1] + 0.25f*rv[2][1];
    #pragma unroll
    for (int s=0;s<4;s++) {
      const float* kp = &kws[wl][s*9];
      float ko = x00*kp[0]+x01*kp[1]+x02*kp[2]
               + x10*kp[3]+x11*kp[4]+x12*kp[5]
               + x20*kp[6]+x21*kp[7]+x22*kp[8];
      int di = s >> 1, dj = s & 1;
      size_t oidx = (size_t)(b*256 + c)*16384 + (size_t)(2*h+di)*128 + (size_t)(dj*64 + wl);
      out[oidx] = (ko + up[di][dj]) * gt;
    }
  }
}

// ---------------- launch --------------------------------------------------------
extern "C" void kernel_launch(void* const* d_in, const int* in_sizes, int n_in,
                              void* d_out, int out_size) {
  const float* x    = (const float*)d_in[0];
  const float* Wkc  = (const float*)d_in[1];
  const float* bkc  = (const float*)d_in[2];
  const float* Wkp1 = (const float*)d_in[3];
  const float* bkp1 = (const float*)d_in[4];
  const float* g1   = (const float*)d_in[5];
  const float* be1  = (const float*)d_in[6];
  const float* m1   = (const float*)d_in[7];
  const float* v1   = (const float*)d_in[8];
  const float* Wkp2 = (const float*)d_in[9];
  const float* bkp2 = (const float*)d_in[10];
  const float* Wdef = (const float*)d_in[11];
  const float* Wg1  = (const float*)d_in[12];
  const float* bg1  = (const float*)d_in[13];
  const float* Wg2  = (const float*)d_in[14];
  const float* bg2  = (const float*)d_in[15];
  float* out = (float*)d_out;

  float* comp = nullptr; float* t = nullptr; float* enh = nullptr;
  cudaGetSymbolAddress((void**)&comp, g_comp);
  cudaGetSymbolAddress((void**)&t,    g_t);
  cudaGetSymbolAddress((void**)&enh,  g_enh);

  // smem: max(2*P(19008) + 2*W(TAPS*2048), out stage 64*260*4=66560)
  const int SM_9TAP = 2*19008 + 2*9*2048;               // 74880
  const int SM_1TAP = 66560;                            // stage dominates

  cudaFuncSetAttribute(conv_mma<256,1,0,0>, cudaFuncAttributeMaxDynamicSharedMemorySize, SM_1TAP);
  cudaFuncSetAttribute(conv_mma<128,9,1,0>, cudaFuncAttributeMaxDynamicSharedMemorySize, SM_9TAP);
  cudaFuncSetAttribute(conv_mma<64,9,2,1>,  cudaFuncAttributeMaxDynamicSharedMemorySize, SM_9TAP);

  conv_mma<256,1,0,0><<<dim3(16,2,8), 256, SM_1TAP>>>(x,    Wkc,  comp, bkc,  nullptr, nullptr, nullptr, nullptr);
  conv_mma<128,9,1,0><<<dim3(16,1,8), 256, SM_9TAP>>>(comp, Wkp1, t,    bkp1, g1, be1, m1, v1);
  k3_kw     <<<128,          256>>>(Wkp2, bkp2);
  conv_mma<64,9,2,1> <<<dim3(16,4,8), 256, SM_9TAP>>>(x,    Wdef, enh,  nullptr, nullptr, nullptr, nullptr, nullptr);
  k3b_gmap  <<<128,          256>>>();
  k5_pool   <<<2048,         256>>>(x);
  k6_gate   <<<8,            256>>>(Wg1, bg1, Wg2, bg2);
  k7_fused  <<<dim3(16,64,8),256>>>(x, out);
}

// round 6
// speedup vs baseline: 2.1466x; 1.0974x over previous
#include <cuda_runtime.h>
#include <cuda_fp16.h>
#include <cstdint>
#include <math.h>

#define BATCH 8
#define CH    256
#define HWP   4096   // 64*64

// ---------------- scratch (static device allocations; no cudaMalloc) ----------
__device__ float g_comp [BATCH*128*HWP];
__device__ float g_t    [BATCH*64*HWP];
__device__ float g_kw   [BATCH*HWP*36];
__device__ float g_kwsum[BATCH*HWP*9];
__device__ float g_gmap [BATCH*HWP];
__device__ float g_enh  [BATCH*CH*HWP];
__device__ float g_pooled[BATCH*CH];
__device__ float g_gate  [BATCH*CH];

// ---------------- helpers ------------------------------------------------------
__device__ __forceinline__ uint32_t s2u(const void* p){
  uint32_t a; asm("{ .reg .u64 t; cvta.to.shared.u64 t, %1; cvt.u32.u64 %0, t; }"
                  : "=r"(a) : "l"(p)); return a;
}
__device__ __forceinline__ uint16_t f16r(float v){
  __half h = __float2half_rn(v);
  return __half_as_ushort(h);
}
__device__ __forceinline__ void f16split(float v, uint16_t& h, uint16_t& l){
  __half hb = __float2half_rn(v);
  float hf = __half2float(hb);
  __half lb = __float2half_rn(v - hf);
  h = __half_as_ushort(hb);
  l = __half_as_ushort(lb);
}
__device__ __forceinline__ void ldmx4(uint32_t r[4], uint32_t addr){
  asm volatile("ldmatrix.sync.aligned.m8n8.x4.shared.b16 {%0,%1,%2,%3}, [%4];"
               : "=r"(r[0]), "=r"(r[1]), "=r"(r[2]), "=r"(r[3]) : "r"(addr));
}
__device__ __forceinline__ void mma_f16(float c[4], const uint32_t a[4],
                                        uint32_t b0, uint32_t b1){
  asm volatile("mma.sync.aligned.m16n8k16.row.col.f32.f16.f16.f32 "
               "{%0,%1,%2,%3},{%4,%5,%6,%7},{%8,%9},{%0,%1,%2,%3};"
               : "+f"(c[0]), "+f"(c[1]), "+f"(c[2]), "+f"(c[3])
               : "r"(a[0]), "r"(a[1]), "r"(a[2]), "r"(a[3]), "r"(b0), "r"(b1));
}

// ================= implicit-GEMM conv on HMMA fp16 (2-pass: A rounded, B split)
// CTA: 256 px (4 image rows) x 64 output channels. Warps: 4m x 2n, each warp
// computes 64px x 32co. Pixel tile: 6 rows x 66 cols halo, fp16 hi only,
// slot stride 48B (conflict-free ldmatrix). Weights: [tap][co][16ci re-paired]
// hi+lo fp16 so each B fragment is one 8B LDS.64.
// EPI: 0 = +bias, 1 = +bias,BN,SiLU, 2 = raw
template<int CI, int TAPS, int EPI, int GROUPED>
__global__ __launch_bounds__(256, 2) void conv_mma(
    const float* __restrict__ in, const float* __restrict__ W,
    float* __restrict__ out,
    const float* __restrict__ bias, const float* __restrict__ g1,
    const float* __restrict__ be1, const float* __restrict__ m1,
    const float* __restrict__ v1) {
  extern __shared__ char sm[];
  constexpr uint32_t OP = 0;                              // pixel plane 19008 B
  constexpr uint32_t OW_H = 6*66*48;                      // 19008
  constexpr uint32_t W_BYTES = TAPS*64*32;                // 16ci*2B per co
  constexpr uint32_t OW_L = OW_H + W_BYTES;

  const int tid = threadIdx.x;
  const int lane = tid & 31, wid = tid >> 5;
  const int wy = wid >> 1, wx = wid & 1;                  // 4 m-warps x 2 n-warps
  const int g = lane >> 2, tq = lane & 3;
  const int rowblk = blockIdx.x;                          // 4 image rows
  const int cob = blockIdx.y;
  const int co0 = cob * 64;
  const int b = blockIdx.z;
  const int nco = gridDim.y * 64;
  const int nch = GROUPED ? gridDim.y * CI : CI;
  const int in_off = GROUPED ? cob * CI : 0;
  const float* inb = in + ((size_t)b*nch + in_off)*HWP;
  const uint32_t sbase = s2u(sm);

  float cacc[4][4][4];
  #pragma unroll
  for (int mm = 0; mm < 4; mm++)
    #pragma unroll
    for (int nn = 0; nn < 4; nn++)
      #pragma unroll
      for (int j = 0; j < 4; j++) cacc[mm][nn][j] = 0.f;

  for (int cb = 0; cb < CI/16; cb++) {
    __syncthreads();
    // ---- pixel tile [6 rows][66 cols][16 ci] fp16, 48B slot stride ----
    for (int i = tid; i < 792; i += 256) {
      int half = i & 1, slot = i >> 1;
      int r = slot / 66, c = slot - r*66;
      int y = rowblk*4 + r - 1, xx = c - 1;
      bool ok = ((unsigned)y < 64u) && ((unsigned)xx < 64u);
      const float* src = inb + (size_t)(cb*16 + half*8)*HWP + y*64 + xx;
      uint32_t hw[4];
      #pragma unroll
      for (int jj = 0; jj < 4; jj++) {
        float v0 = ok ? src[(size_t)(2*jj)*HWP]   : 0.f;
        float v1 = ok ? src[(size_t)(2*jj+1)*HWP] : 0.f;
        hw[jj] = (uint32_t)f16r(v0) | ((uint32_t)f16r(v1) << 16);
      }
      uint32_t boff = (uint32_t)slot*48 + half*16;
      *(uint4*)(sm + OP + boff) = make_uint4(hw[0],hw[1],hw[2],hw[3]);
    }
    // ---- weight tile [tap][64 co][16 ci re-paired] hi/lo fp16 ----
    constexpr int PERM = TAPS*4;   // float4 per co-row for this ci-block
    for (int i = tid; i < 64*PERM; i += 256) {
      int m = i / PERM, q = i - m*PERM;
      const float* wm = W + ((size_t)(co0+m)*CI + cb*16)*TAPS;
      float4 v = *(const float4*)(wm + q*4);
      #pragma unroll
      for (int j = 0; j < 4; j++) {
        int e = q*4 + j;
        int ci = e / TAPS, t = e - ci*TAPS;
        int pos = ((ci & 7) >> 1)*4 + (ci >> 3)*2 + (ci & 1);
        uint16_t h, l;
        f16split((&v.x)[j], h, l);
        uint32_t off = (uint32_t)((t*64 + m)*16 + pos)*2;
        *(uint16_t*)(sm + OW_H + off) = h;
        *(uint16_t*)(sm + OW_L + off) = l;
      }
    }
    __syncthreads();
    // ---- taps: shift pixel pointers, mma ----
    #pragma unroll 1
    for (int tap = 0; tap < TAPS; tap++) {
      int dy = (TAPS == 9) ? tap/3 - 1 : 0;
      int dx = (TAPS == 9) ? tap - (tap/3)*3 - 1 : 0;
      uint32_t ah[4][4];
      #pragma unroll
      for (int mm = 0; mm < 4; mm++) {
        int pxm = wy*64 + mm*16 + (lane & 15);
        int rr = (pxm >> 6) + 1 + dy;
        int cc = (pxm & 63) + 1 + dx;
        uint32_t boff = (uint32_t)(rr*66 + cc)*48 + ((lane >> 4) & 1)*16;
        ldmx4(ah[mm], sbase + OP + boff);
      }
      #pragma unroll
      for (int nn = 0; nn < 4; nn++) {
        int cof = wx*32 + nn*8 + g;
        uint32_t woff = (uint32_t)(tap*64 + cof)*32 + tq*8;
        uint2 bh = *(const uint2*)(sm + OW_H + woff);
        uint2 bl = *(const uint2*)(sm + OW_L + woff);
        #pragma unroll
        for (int mm = 0; mm < 4; mm++) {
          mma_f16(cacc[mm][nn], ah[mm], bh.x, bh.y);
          mma_f16(cacc[mm][nn], ah[mm], bl.x, bl.y);
        }
      }
    }
  }
  // ---- epilogue: frags -> smem stage (stride 260 = conflict-free) -> gmem ----
  __syncthreads();
  float* osm = (float*)sm;
  #pragma unroll
  for (int mm = 0; mm < 4; mm++)
    #pragma unroll
    for (int nn = 0; nn < 4; nn++) {
      int px  = wy*64 + mm*16 + g;
      int col = wx*32 + nn*8 + tq*2;
      osm[(col  )*260 + px    ] = cacc[mm][nn][0];
      osm[(col+1)*260 + px    ] = cacc[mm][nn][1];
      osm[(col  )*260 + px + 8] = cacc[mm][nn][2];
      osm[(col+1)*260 + px + 8] = cacc[mm][nn][3];
    }
  __syncthreads();
  for (int i = tid; i < 16384; i += 256) {
    int col = i >> 8, px = i & 255;
    float v = osm[col*260 + px];
    int cg = co0 + col;
    if (EPI == 0) v += bias[cg];
    if (EPI == 1) {
      float sc = g1[cg] * rsqrtf(v1[cg] + 1e-5f);
      float sh = be1[cg] - m1[cg]*sc;
      v = (v + bias[cg])*sc + sh;
      v = v / (1.f + expf(-v));
    }
    out[((size_t)(b*nco + cg))*HWP + rowblk*256 + px] = v;
  }
}

// ---------------- K3: 1x1 conv 64->36 + softmax(9) groups ---------------------
__global__ __launch_bounds__(256) void k3_kw(const float* __restrict__ Wkp2,
                                             const float* __restrict__ bkp2) {
  __shared__ float ws[36*64];
  __shared__ float bs[36];
  int tid = threadIdx.x;
  for (int i = tid; i < 2304; i += 256) ws[i] = Wkp2[i];
  if (tid < 36) bs[tid] = bkp2[tid];
  __syncthreads();
  int gp = blockIdx.x*256 + tid;
  int b = gp >> 12, p = gp & 4095;
  float acc[36];
  #pragma unroll
  for (int j=0;j<36;j++) acc[j]=bs[j];
  const float* tb = g_t + (size_t)b*64*HWP + p;
  for (int ci=0; ci<64; ci++) {
    float tv = tb[(size_t)ci*HWP];
    #pragma unroll
    for (int j=0;j<36;j++) acc[j] += ws[j*64+ci]*tv;
  }
  float ks[9];
  #pragma unroll
  for (int k=0;k<9;k++) ks[k]=0.f;
  float* kwp = g_kw + (size_t)gp*36;
  #pragma unroll
  for (int s=0;s<4;s++) {
    float m = acc[s*9];
    #pragma unroll
    for (int k=1;k<9;k++) m = fmaxf(m, acc[s*9+k]);
    float e[9]; float sum=0.f;
    #pragma unroll
    for (int k=0;k<9;k++){ e[k]=expf(acc[s*9+k]-m); sum+=e[k]; }
    float inv = 1.f/sum;
    #pragma unroll
    for (int k=0;k<9;k++){ float v=e[k]*inv; kwp[s*9+k]=v; ks[k]+=v; }
  }
  float* ksp = g_kwsum + (size_t)gp*9;
  #pragma unroll
  for (int k=0;k<9;k++) ksp[k]=ks[k];
}

// ---------------- K3b: g map = 3x3 box correlation of kwsum -------------------
__global__ void k3b_gmap() {
  int gp = blockIdx.x*256 + threadIdx.x;
  int b = gp >> 12, p = gp & 4095;
  int i = p >> 6, j = p & 63;
  float s = 0.f;
  #pragma unroll
  for (int ih=0; ih<3; ih++)
    #pragma unroll
    for (int iw=0; iw<3; iw++) {
      int h = i + 1 - ih, w = j + 1 - iw;
      if ((unsigned)h < 64u && (unsigned)w < 64u)
        s += g_kwsum[(size_t)(b*4096 + h*64 + w)*9 + ih*3 + iw];
    }
  g_gmap[gp] = s;
}

// ---------------- K5: pooled[b,c] = sum(x*g)/16384 + sum(enh)/4096 ------------
__global__ __launch_bounds__(256) void k5_pool(const float* __restrict__ x) {
  int bc = blockIdx.x;
  int b = bc >> 8;
  const float* xp = x      + (size_t)bc*HWP;
  const float* ep = g_enh  + (size_t)bc*HWP;
  const float* gp = g_gmap + (size_t)b*HWP;
  int tid = threadIdx.x;
  float s1=0.f, s2=0.f;
  for (int i = tid; i < HWP; i += 256) { s1 += xp[i]*gp[i]; s2 += ep[i]; }
  __shared__ float r1[256], r2[256];
  r1[tid]=s1; r2[tid]=s2;
  __syncthreads();
  for (int st=128; st>0; st>>=1) {
    if (tid < st) { r1[tid]+=r1[tid+st]; r2[tid]+=r2[tid+st]; }
    __syncthreads();
  }
  if (tid==0) g_pooled[bc] = r1[0]*(1.f/16384.f) + r2[0]*(1.f/4096.f);
}

// ---------------- K6: SE gate ---------------------------------------------------
__global__ __launch_bounds__(256) void k6_gate(const float* __restrict__ Wg1,
    const float* __restrict__ bg1, const float* __restrict__ Wg2,
    const float* __restrict__ bg2) {
  int b = blockIdx.x, tid = threadIdx.x;
  __shared__ float pl[256], hid[64];
  pl[tid] = g_pooled[b*256 + tid];
  __syncthreads();
  if (tid < 64) {
    float a = bg1[tid];
    for (int ci=0; ci<256; ci++) a += Wg1[tid*256+ci]*pl[ci];
    hid[tid] = a / (1.f + expf(-a));
  }
  __syncthreads();
  float a = bg2[tid];
  for (int j=0;j<64;j++) a += Wg2[tid*64+j]*hid[j];
  g_gate[b*256+tid] = 1.f/(1.f+expf(-a));
}

// ---------------- K7: reassembly + bilinear up + gate -> output ----------------
__global__ __launch_bounds__(256) void k7_fused(const float* __restrict__ x,
                                                float* __restrict__ out) {
  __shared__ float kws[64][37];
  __shared__ float xs[16][3][66];
  __shared__ float es[16][3][64];
  int tid = threadIdx.x;
  int wl = tid & 63, cs = tid >> 6;
  int c0 = blockIdx.x * 16;
  int h  = blockIdx.y;
  int b  = blockIdx.z;
  for (int i = tid; i < 2304; i += 256) {
    int w = i / 36, m = i % 36;
    kws[w][m] = g_kw[(size_t)(b*4096 + h*64 + w)*36 + m];
  }
  for (int i = tid; i < 16*3*66; i += 256) {
    int cc = i / 198, rem = i % 198;
    int r = rem / 66, col = rem % 66 - 1;
    int y = h + r - 1;
    float v = 0.f;
    if ((unsigned)y < 64u && (unsigned)col < 64u)
      v = x[((size_t)(b*CH)+c0+cc)*HWP + y*64 + col];
    xs[cc][r][col+1] = v;
  }
  for (int i = tid; i < 16*3*64; i += 256) {
    int cc = i / 192, rem = i % 192;
    int r = rem / 64, col = rem % 64;
    int y = min(max(h + r - 1, 0), 63);
    es[cc][r][col] = g_enh[((size_t)(b*CH)+c0+cc)*HWP + y*64 + col];
  }
  __syncthreads();
  // hoist per-pixel kernel weights into registers (shared across 4 channels)
  float kp[36];
  #pragma unroll
  for (int m = 0; m < 36; m++) kp[m] = kws[wl][m];
  int base; float fw;
  if (wl & 1) { base = (wl - 1) >> 1; fw = 0.25f; }
  else        { base = (wl >> 1) - 1; fw = 0.75f; }
  int cA0 = max(base, 0);
  int cB0 = base + 1;
  int cA1 = base + 32;
  int cB1 = min(base + 33, 63);
  float fw1 = 1.f - fw;
  #pragma unroll
  for (int qq = 0; qq < 4; qq++) {
    int cc = cs*4 + qq;
    int c  = c0 + cc;
    float gt = g_gate[b*256 + c];
    float x00=xs[cc][0][wl], x01=xs[cc][0][wl+1], x02=xs[cc][0][wl+2];
    float x10=xs[cc][1][wl], x11=xs[cc][1][wl+1], x12=xs[cc][1][wl+2];
    float x20=xs[cc][2][wl], x21=xs[cc][2][wl+1], x22=xs[cc][2][wl+2];
    float rv[3][2];
    #pragma unroll
    for (int r=0;r<3;r++) {
      rv[r][0] = fw1*es[cc][r][cA0] + fw*es[cc][r][cB0];
      rv[r][1] = fw1*es[cc][r][cA1] + fw*es[cc][r][cB1];
    }
    float up[2][2];
    up[0][0] = 0.25f*rv[0][0] + 0.75f*rv[1][0];
    up[0][1] = 0.25f*rv[0][1] + 0.75f*rv[1][1];
    up[1][0] = 0.75f*rv[1][0] + 0.25f*rv[2][0];
    up[1][1] = 0.75f*rv[1][1] + 0.25f*rv[2][1];
    #pragma unroll
    for (int s=0;s<4;s++) {
      const float* kq = &kp[s*9];
      float ko = x00*kq[0]+x01*kq[1]+x02*kq[2]
               + x10*kq[3]+x11*kq[4]+x12*kq[5]
               + x20*kq[6]+x21*kq[7]+x22*kq[8];
      int di = s >> 1, dj = s & 1;
      size_t oidx = (size_t)(b*256 + c)*16384 + (size_t)(2*h+di)*128 + (size_t)(dj*64 + wl);
      out[oidx] = (ko + up[di][dj]) * gt;
    }
  }
}

// ---------------- launch --------------------------------------------------------
extern "C" void kernel_launch(void* const* d_in, const int* in_sizes, int n_in,
                              void* d_out, int out_size) {
  const float* x    = (const float*)d_in[0];
  const float* Wkc  = (const float*)d_in[1];
  const float* bkc  = (const float*)d_in[2];
  const float* Wkp1 = (const float*)d_in[3];
  const float* bkp1 = (const float*)d_in[4];
  const float* g1   = (const float*)d_in[5];
  const float* be1  = (const float*)d_in[6];
  const float* m1   = (const float*)d_in[7];
  const float* v1   = (const float*)d_in[8];
  const float* Wkp2 = (const float*)d_in[9];
  const float* bkp2 = (const float*)d_in[10];
  const float* Wdef = (const float*)d_in[11];
  const float* Wg1  = (const float*)d_in[12];
  const float* bg1  = (const float*)d_in[13];
  const float* Wg2  = (const float*)d_in[14];
  const float* bg2  = (const float*)d_in[15];
  float* out = (float*)d_out;

  float* comp = nullptr; float* t = nullptr; float* enh = nullptr;
  cudaGetSymbolAddress((void**)&comp, g_comp);
  cudaGetSymbolAddress((void**)&t,    g_t);
  cudaGetSymbolAddress((void**)&enh,  g_enh);

  // smem: max(pixel(19008) + 2*W(TAPS*2048), out stage 64*260*4 = 66560)
  const int SM_CONV = 66560;

  cudaFuncSetAttribute(conv_mma<256,1,0,0>, cudaFuncAttributeMaxDynamicSharedMemorySize, SM_CONV);
  cudaFuncSetAttribute(conv_mma<128,9,1,0>, cudaFuncAttributeMaxDynamicSharedMemorySize, SM_CONV);
  cudaFuncSetAttribute(conv_mma<64,9,2,1>,  cudaFuncAttributeMaxDynamicSharedMemorySize, SM_CONV);

  conv_mma<256,1,0,0><<<dim3(16,2,8), 256, SM_CONV>>>(x,    Wkc,  comp, bkc,  nullptr, nullptr, nullptr, nullptr);
  conv_mma<128,9,1,0><<<dim3(16,1,8), 256, SM_CONV>>>(comp, Wkp1, t,    bkp1, g1, be1, m1, v1);
  k3_kw     <<<128,          256>>>(Wkp2, bkp2);
  conv_mma<64,9,2,1> <<<dim3(16,4,8), 256, SM_CONV>>>(x,    Wdef, enh,  nullptr, nullptr, nullptr, nullptr, nullptr);
  k3b_gmap  <<<128,          256>>>();
  k5_pool   <<<2048,         256>>>(x);
  k6_gate   <<<8,            256>>>(Wg1, bg1, Wg2, bg2);
  k7_fused  <<<dim3(16,64,8),256>>>(x, out);
}

// round 7
// speedup vs baseline: 2.8145x; 1.3112x over previous
#include <cuda_runtime.h>
#include <cuda_fp16.h>
#include <cstdint>
#include <math.h>

#define BATCH 8
#define CH    256
#define HWP   4096   // 64*64

// ---------------- scratch (static device allocations; no cudaMalloc) ----------
__device__ float g_comp [BATCH*128*HWP];
__device__ float g_t    [BATCH*64*HWP];
__device__ float g_kw   [BATCH*HWP*36];
__device__ float g_kwsum[BATCH*HWP*9];
__device__ float g_gmap [BATCH*HWP];
__device__ float g_enh  [BATCH*CH*HWP];
__device__ float g_pooled[BATCH*CH];
__device__ float g_gate  [BATCH*CH];

// ---------------- helpers ------------------------------------------------------
__device__ __forceinline__ uint32_t s2u(const void* p){
  uint32_t a; asm("{ .reg .u64 t; cvta.to.shared.u64 t, %1; cvt.u32.u64 %0, t; }"
                  : "=r"(a) : "l"(p)); return a;
}
__device__ __forceinline__ uint16_t f16r(float v){
  __half h = __float2half_rn(v);
  return __half_as_ushort(h);
}
__device__ __forceinline__ void ldmx4(uint32_t r[4], uint32_t addr){
  asm volatile("ldmatrix.sync.aligned.m8n8.x4.shared.b16 {%0,%1,%2,%3}, [%4];"
               : "=r"(r[0]), "=r"(r[1]), "=r"(r[2]), "=r"(r[3]) : "r"(addr));
}
__device__ __forceinline__ void mma_f16(float c[4], const uint32_t a[4],
                                        uint32_t b0, uint32_t b1){
  asm volatile("mma.sync.aligned.m16n8k16.row.col.f32.f16.f16.f32 "
               "{%0,%1,%2,%3},{%4,%5,%6,%7},{%8,%9},{%0,%1,%2,%3};"
               : "+f"(c[0]), "+f"(c[1]), "+f"(c[2]), "+f"(c[3])
               : "r"(a[0]), "r"(a[1]), "r"(a[2]), "r"(a[3]), "r"(b0), "r"(b1));
}

// ================= implicit-GEMM conv on HMMA fp16 (single-pass) ==============
// CTA: 256 px (4 image rows) x 64 output channels. Warps: 4m x 2n, each warp
// computes 64px x 32co. Pixel tile: 6 rows x 66 cols halo, fp16, slot stride
// 48B (conflict-free ldmatrix). Weights: [tap][co][16ci re-paired] fp16 so
// each B fragment is one 8B LDS.64.
// EPI: 0 = +bias, 1 = +bias,BN,SiLU, 2 = raw
template<int CI, int TAPS, int EPI, int GROUPED>
__global__ __launch_bounds__(256, 2) void conv_mma(
    const float* __restrict__ in, const float* __restrict__ W,
    float* __restrict__ out,
    const float* __restrict__ bias, const float* __restrict__ g1,
    const float* __restrict__ be1, const float* __restrict__ m1,
    const float* __restrict__ v1) {
  extern __shared__ char sm[];
  constexpr uint32_t OP = 0;                              // pixel plane 19008 B
  constexpr uint32_t OW = 6*66*48;                        // 19008

  const int tid = threadIdx.x;
  const int lane = tid & 31, wid = tid >> 5;
  const int wy = wid >> 1, wx = wid & 1;                  // 4 m-warps x 2 n-warps
  const int g = lane >> 2, tq = lane & 3;
  const int rowblk = blockIdx.x;                          // 4 image rows
  const int cob = blockIdx.y;
  const int co0 = cob * 64;
  const int b = blockIdx.z;
  const int nco = gridDim.y * 64;
  const int nch = GROUPED ? gridDim.y * CI : CI;
  const int in_off = GROUPED ? cob * CI : 0;
  const float* inb = in + ((size_t)b*nch + in_off)*HWP;
  const uint32_t sbase = s2u(sm);

  float cacc[4][4][4];
  #pragma unroll
  for (int mm = 0; mm < 4; mm++)
    #pragma unroll
    for (int nn = 0; nn < 4; nn++)
      #pragma unroll
      for (int j = 0; j < 4; j++) cacc[mm][nn][j] = 0.f;

  for (int cb = 0; cb < CI/16; cb++) {
    __syncthreads();
    // ---- pixel tile [6 rows][66 cols][16 ci] fp16, 48B slot stride ----
    for (int i = tid; i < 792; i += 256) {
      int half = i & 1, slot = i >> 1;
      int r = slot / 66, c = slot - r*66;
      int y = rowblk*4 + r - 1, xx = c - 1;
      bool ok = ((unsigned)y < 64u) && ((unsigned)xx < 64u);
      const float* src = inb + (size_t)(cb*16 + half*8)*HWP + y*64 + xx;
      uint32_t hw[4];
      #pragma unroll
      for (int jj = 0; jj < 4; jj++) {
        float v0 = ok ? src[(size_t)(2*jj)*HWP]   : 0.f;
        float v1 = ok ? src[(size_t)(2*jj+1)*HWP] : 0.f;
        hw[jj] = (uint32_t)f16r(v0) | ((uint32_t)f16r(v1) << 16);
      }
      uint32_t boff = (uint32_t)slot*48 + half*16;
      *(uint4*)(sm + OP + boff) = make_uint4(hw[0],hw[1],hw[2],hw[3]);
    }
    // ---- weight tile [tap][64 co][16 ci re-paired] fp16 ----
    constexpr int PERM = TAPS*4;   // float4 per co-row for this ci-block
    for (int i = tid; i < 64*PERM; i += 256) {
      int m = i / PERM, q = i - m*PERM;
      const float* wm = W + ((size_t)(co0+m)*CI + cb*16)*TAPS;
      float4 v = *(const float4*)(wm + q*4);
      #pragma unroll
      for (int j = 0; j < 4; j++) {
        int e = q*4 + j;
        int ci = e / TAPS, t = e - ci*TAPS;
        int pos = ((ci & 7) >> 1)*4 + (ci >> 3)*2 + (ci & 1);
        uint32_t off = (uint32_t)((t*64 + m)*16 + pos)*2;
        *(uint16_t*)(sm + OW + off) = f16r((&v.x)[j]);
      }
    }
    __syncthreads();
    // ---- taps: shift pixel pointers, mma ----
    #pragma unroll 1
    for (int tap = 0; tap < TAPS; tap++) {
      int dy = (TAPS == 9) ? tap/3 - 1 : 0;
      int dx = (TAPS == 9) ? tap - (tap/3)*3 - 1 : 0;
      uint32_t ah[4][4];
      #pragma unroll
      for (int mm = 0; mm < 4; mm++) {
        int pxm = wy*64 + mm*16 + (lane & 15);
        int rr = (pxm >> 6) + 1 + dy;
        int cc = (pxm & 63) + 1 + dx;
        uint32_t boff = (uint32_t)(rr*66 + cc)*48 + ((lane >> 4) & 1)*16;
        ldmx4(ah[mm], sbase + OP + boff);
      }
      #pragma unroll
      for (int nn = 0; nn < 4; nn++) {
        int cof = wx*32 + nn*8 + g;
        uint32_t woff = (uint32_t)(tap*64 + cof)*32 + tq*8;
        uint2 bh = *(const uint2*)(sm + OW + woff);
        #pragma unroll
        for (int mm = 0; mm < 4; mm++) {
          mma_f16(cacc[mm][nn], ah[mm], bh.x, bh.y);
        }
      }
    }
  }
  // ---- epilogue: frags -> smem stage (stride 260 = conflict-free) -> gmem ----
  __syncthreads();
  float* osm = (float*)sm;
  #pragma unroll
  for (int mm = 0; mm < 4; mm++)
    #pragma unroll
    for (int nn = 0; nn < 4; nn++) {
      int px  = wy*64 + mm*16 + g;
      int col = wx*32 + nn*8 + tq*2;
      osm[(col  )*260 + px    ] = cacc[mm][nn][0];
      osm[(col+1)*260 + px    ] = cacc[mm][nn][1];
      osm[(col  )*260 + px + 8] = cacc[mm][nn][2];
      osm[(col+1)*260 + px + 8] = cacc[mm][nn][3];
    }
  __syncthreads();
  for (int i = tid; i < 16384; i += 256) {
    int col = i >> 8, px = i & 255;
    float v = osm[col*260 + px];
    int cg = co0 + col;
    if (EPI == 0) v += bias[cg];
    if (EPI == 1) {
      float sc = g1[cg] * rsqrtf(v1[cg] + 1e-5f);
      float sh = be1[cg] - m1[cg]*sc;
      v = (v + bias[cg])*sc + sh;
      v = v / (1.f + expf(-v));
    }
    out[((size_t)(b*nco + cg))*HWP + rowblk*256 + px] = v;
  }
}

// ---------------- K3: 1x1 conv 64->36 + softmax(9) groups ---------------------
__global__ __launch_bounds__(256) void k3_kw(const float* __restrict__ Wkp2,
                                             const float* __restrict__ bkp2) {
  __shared__ float ws[36*64];
  __shared__ float bs[36];
  int tid = threadIdx.x;
  for (int i = tid; i < 2304; i += 256) ws[i] = Wkp2[i];
  if (tid < 36) bs[tid] = bkp2[tid];
  __syncthreads();
  int gp = blockIdx.x*256 + tid;
  int b = gp >> 12, p = gp & 4095;
  float acc[36];
  #pragma unroll
  for (int j=0;j<36;j++) acc[j]=bs[j];
  const float* tb = g_t + (size_t)b*64*HWP + p;
  for (int ci=0; ci<64; ci++) {
    float tv = tb[(size_t)ci*HWP];
    #pragma unroll
    for (int j=0;j<36;j++) acc[j] += ws[j*64+ci]*tv;
  }
  float ks[9];
  #pragma unroll
  for (int k=0;k<9;k++) ks[k]=0.f;
  float* kwp = g_kw + (size_t)gp*36;
  #pragma unroll
  for (int s=0;s<4;s++) {
    float m = acc[s*9];
    #pragma unroll
    for (int k=1;k<9;k++) m = fmaxf(m, acc[s*9+k]);
    float e[9]; float sum=0.f;
    #pragma unroll
    for (int k=0;k<9;k++){ e[k]=expf(acc[s*9+k]-m); sum+=e[k]; }
    float inv = 1.f/sum;
    #pragma unroll
    for (int k=0;k<9;k++){ float v=e[k]*inv; kwp[s*9+k]=v; ks[k]+=v; }
  }
  float* ksp = g_kwsum + (size_t)gp*9;
  #pragma unroll
  for (int k=0;k<9;k++) ksp[k]=ks[k];
}

// ---------------- K3b: g map = 3x3 box correlation of kwsum -------------------
__global__ void k3b_gmap() {
  int gp = blockIdx.x*256 + threadIdx.x;
  int b = gp >> 12, p = gp & 4095;
  int i = p >> 6, j = p & 63;
  float s = 0.f;
  #pragma unroll
  for (int ih=0; ih<3; ih++)
    #pragma unroll
    for (int iw=0; iw<3; iw++) {
      int h = i + 1 - ih, w = j + 1 - iw;
      if ((unsigned)h < 64u && (unsigned)w < 64u)
        s += g_kwsum[(size_t)(b*4096 + h*64 + w)*9 + ih*3 + iw];
    }
  g_gmap[gp] = s;
}

// ---------------- K5: pooled[b,c] = sum(x*g)/16384 + sum(enh)/4096 ------------
__global__ __launch_bounds__(256) void k5_pool(const float* __restrict__ x) {
  int bc = blockIdx.x;
  int b = bc >> 8;
  const float* xp = x      + (size_t)bc*HWP;
  const float* ep = g_enh  + (size_t)bc*HWP;
  const float* gp = g_gmap + (size_t)b*HWP;
  int tid = threadIdx.x;
  float s1=0.f, s2=0.f;
  for (int i = tid; i < HWP; i += 256) { s1 += xp[i]*gp[i]; s2 += ep[i]; }
  __shared__ float r1[256], r2[256];
  r1[tid]=s1; r2[tid]=s2;
  __syncthreads();
  for (int st=128; st>0; st>>=1) {
    if (tid < st) { r1[tid]+=r1[tid+st]; r2[tid]+=r2[tid+st]; }
    __syncthreads();
  }
  if (tid==0) g_pooled[bc] = r1[0]*(1.f/16384.f) + r2[0]*(1.f/4096.f);
}

// ---------------- K6: SE gate ---------------------------------------------------
__global__ __launch_bounds__(256) void k6_gate(const float* __restrict__ Wg1,
    const float* __restrict__ bg1, const float* __restrict__ Wg2,
    const float* __restrict__ bg2) {
  int b = blockIdx.x, tid = threadIdx.x;
  __shared__ float pl[256], hid[64];
  pl[tid] = g_pooled[b*256 + tid];
  __syncthreads();
  if (tid < 64) {
    float a = bg1[tid];
    for (int ci=0; ci<256; ci++) a += Wg1[tid*256+ci]*pl[ci];
    hid[tid] = a / (1.f + expf(-a));
  }
  __syncthreads();
  float a = bg2[tid];
  for (int j=0;j<64;j++) a += Wg2[tid*64+j]*hid[j];
  g_gate[b*256+tid] = 1.f/(1.f+expf(-a));
}

// ---------------- K7: reassembly + bilinear up + gate -> output ----------------
// Block: 4 h-rows x 64 cols x 16 channels. One thread = one (h,col) pixel,
// owning all 36 softmax weights in registers; loops 16 channels.
__global__ __launch_bounds__(256, 2) void k7_fused(const float* __restrict__ x,
                                                   float* __restrict__ out) {
  extern __shared__ float sm7[];
  float* xs = sm7;                 // [16][6][66]
  float* es = sm7 + 16*6*66;       // [16][6][64]
  const int tid = threadIdx.x;
  const int c0 = blockIdx.x * 16;
  const int h0 = blockIdx.y * 4;
  const int b  = blockIdx.z;
  // loads: x halo rows h0-1..h0+4, zero-padded cols -1..64
  for (int i = tid; i < 16*6*66; i += 256) {
    int cc = i / 396, rem = i - cc*396;
    int rr = rem / 66, col = rem - rr*66 - 1;
    int y = h0 + rr - 1;
    float v = 0.f;
    if ((unsigned)y < 64u && (unsigned)col < 64u)
      v = x[((size_t)(b*CH)+c0+cc)*HWP + y*64 + col];
    xs[i] = v;
  }
  // enh rows h0-1..h0+4 clamped
  for (int i = tid; i < 16*6*64; i += 256) {
    int cc = i / 384, rem = i - cc*384;
    int rr = rem >> 6, col = rem & 63;
    int y = min(max(h0 + rr - 1, 0), 63);
    es[i] = g_enh[((size_t)(b*CH)+c0+cc)*HWP + y*64 + col];
  }
  __syncthreads();
  const int r = tid >> 6, col = tid & 63;
  const int h = h0 + r;
  // 36 softmax weights for this pixel -> registers (9x float4)
  float kp[36];
  {
    const float4* kq = (const float4*)(g_kw + ((size_t)(b*4096 + h*64 + col))*36);
    #pragma unroll
    for (int j = 0; j < 9; j++) {
      float4 v = kq[j];
      kp[4*j] = v.x; kp[4*j+1] = v.y; kp[4*j+2] = v.z; kp[4*j+3] = v.w;
    }
  }
  // bilinear column interp (half-pixel, clamped)
  int base; float fw;
  if (col & 1) { base = (col - 1) >> 1; fw = 0.25f; }
  else         { base = (col >> 1) - 1; fw = 0.75f; }
  int cA0 = max(base, 0);
  int cB0 = base + 1;
  int cA1 = base + 32;
  int cB1 = min(base + 33, 63);
  float fw1 = 1.f - fw;
  #pragma unroll 1
  for (int cc = 0; cc < 16; cc++) {
    int c = c0 + cc;
    float gt = g_gate[b*256 + c];
    const float* xr = &xs[cc*396 + r*66 + col];
    float x00=xr[0],   x01=xr[1],   x02=xr[2];
    float x10=xr[66],  x11=xr[67],  x12=xr[68];
    float x20=xr[132], x21=xr[133], x22=xr[134];
    const float* er = &es[cc*384 + r*64];
    float rv[3][2];
    #pragma unroll
    for (int j = 0; j < 3; j++) {
      rv[j][0] = fw1*er[j*64 + cA0] + fw*er[j*64 + cB0];
      rv[j][1] = fw1*er[j*64 + cA1] + fw*er[j*64 + cB1];
    }
    float up[2][2];
    up[0][0] = 0.25f*rv[0][0] + 0.75f*rv[1][0];
    up[0][1] = 0.25f*rv[0][1] + 0.75f*rv[1][1];
    up[1][0] = 0.75f*rv[1][0] + 0.25f*rv[2][0];
    up[1][1] = 0.75f*rv[1][1] + 0.25f*rv[2][1];
    #pragma unroll
    for (int s = 0; s < 4; s++) {
      const float* kq = &kp[s*9];
      float ko = x00*kq[0]+x01*kq[1]+x02*kq[2]
               + x10*kq[3]+x11*kq[4]+x12*kq[5]
               + x20*kq[6]+x21*kq[7]+x22*kq[8];
      int di = s >> 1, dj = s & 1;
      size_t oidx = (size_t)(b*256 + c)*16384 + (size_t)(2*h+di)*128 + (size_t)(dj*64 + col);
      out[oidx] = (ko + up[di][dj]) * gt;
    }
  }
}

// ---------------- launch --------------------------------------------------------
extern "C" void kernel_launch(void* const* d_in, const int* in_sizes, int n_in,
                              void* d_out, int out_size) {
  const float* x    = (const float*)d_in[0];
  const float* Wkc  = (const float*)d_in[1];
  const float* bkc  = (const float*)d_in[2];
  const float* Wkp1 = (const float*)d_in[3];
  const float* bkp1 = (const float*)d_in[4];
  const float* g1   = (const float*)d_in[5];
  const float* be1  = (const float*)d_in[6];
  const float* m1   = (const float*)d_in[7];
  const float* v1   = (const float*)d_in[8];
  const float* Wkp2 = (const float*)d_in[9];
  const float* bkp2 = (const float*)d_in[10];
  const float* Wdef = (const float*)d_in[11];
  const float* Wg1  = (const float*)d_in[12];
  const float* bg1  = (const float*)d_in[13];
  const float* Wg2  = (const float*)d_in[14];
  const float* bg2  = (const float*)d_in[15];
  float* out = (float*)d_out;

  float* comp = nullptr; float* t = nullptr; float* enh = nullptr;
  cudaGetSymbolAddress((void**)&comp, g_comp);
  cudaGetSymbolAddress((void**)&t,    g_t);
  cudaGetSymbolAddress((void**)&enh,  g_enh);

  // conv smem: max(pixel(19008) + W(TAPS*2048), out stage 64*260*4 = 66560)
  const int SM_CONV = 66560;
  const int SM_K7   = (16*6*66 + 16*6*64) * 4;   // 49920

  cudaFuncSetAttribute(conv_mma<256,1,0,0>, cudaFuncAttributeMaxDynamicSharedMemorySize, SM_CONV);
  cudaFuncSetAttribute(conv_mma<128,9,1,0>, cudaFuncAttributeMaxDynamicSharedMemorySize, SM_CONV);
  cudaFuncSetAttribute(conv_mma<64,9,2,1>,  cudaFuncAttributeMaxDynamicSharedMemorySize, SM_CONV);
  cudaFuncSetAttribute(k7_fused,            cudaFuncAttributeMaxDynamicSharedMemorySize, SM_K7);

  conv_mma<256,1,0,0><<<dim3(16,2,8), 256, SM_CONV>>>(x,    Wkc,  comp, bkc,  nullptr, nullptr, nullptr, nullptr);
  conv_mma<128,9,1,0><<<dim3(16,1,8), 256, SM_CONV>>>(comp, Wkp1, t,    bkp1, g1, be1, m1, v1);
  k3_kw     <<<128,          256>>>(Wkp2, bkp2);
  conv_mma<64,9,2,1> <<<dim3(16,4,8), 256, SM_CONV>>>(x,    Wdef, enh,  nullptr, nullptr, nullptr, nullptr, nullptr);
  k3b_gmap  <<<128,          256>>>();
  k5_pool   <<<2048,         256>>>(x);
  k6_gate   <<<8,            256>>>(Wg1, bg1, Wg2, bg2);
  k7_fused  <<<dim3(16,16,8),256, SM_K7>>>(x, out);
}

// round 8
// speedup vs baseline: 2.8167x; 1.0008x over previous
#include <cuda_runtime.h>
#include <cuda_fp16.h>
#include <cstdint>
#include <math.h>

#define BATCH 8
#define CH    256
#define HWP   4096   // 64*64

// ---------------- scratch (static device allocations; no cudaMalloc) ----------
__device__ float g_comp [BATCH*128*HWP];
__device__ float g_t    [BATCH*64*HWP];
__device__ float g_kw   [BATCH*HWP*36];
__device__ float g_kwsum[BATCH*HWP*9];
__device__ float g_gmap [BATCH*HWP];
__device__ float g_enh  [BATCH*CH*HWP];
__device__ float g_pooled[BATCH*CH];
__device__ float g_gate  [BATCH*CH];

// ---------------- helpers ------------------------------------------------------
__device__ __forceinline__ uint32_t s2u(const void* p){
  uint32_t a; asm("{ .reg .u64 t; cvta.to.shared.u64 t, %1; cvt.u32.u64 %0, t; }"
                  : "=r"(a) : "l"(p)); return a;
}
__device__ __forceinline__ uint16_t f16r(float v){
  __half h = __float2half_rn(v);
  return __half_as_ushort(h);
}
__device__ __forceinline__ void ldmx4(uint32_t r[4], uint32_t addr){
  asm volatile("ldmatrix.sync.aligned.m8n8.x4.shared.b16 {%0,%1,%2,%3}, [%4];"
               : "=r"(r[0]), "=r"(r[1]), "=r"(r[2]), "=r"(r[3]) : "r"(addr));
}
__device__ __forceinline__ void mma_f16(float c[4], const uint32_t a[4],
                                        uint32_t b0, uint32_t b1){
  asm volatile("mma.sync.aligned.m16n8k16.row.col.f32.f16.f16.f32 "
               "{%0,%1,%2,%3},{%4,%5,%6,%7},{%8,%9},{%0,%1,%2,%3};"
               : "+f"(c[0]), "+f"(c[1]), "+f"(c[2]), "+f"(c[3])
               : "r"(a[0]), "r"(a[1]), "r"(a[2]), "r"(a[3]), "r"(b0), "r"(b1));
}

// ================= implicit-GEMM conv on HMMA fp16 (single-pass) ==============
// CTA: 256 px (4 image rows) x 64 output channels. Warps: 4m x 2n, each warp
// computes 64px x 32co. Pixel tile: 6 rows x 66 cols halo, fp16, slot stride
// 48B (conflict-free ldmatrix). Weights: [tap][co][16ci re-paired] fp16 so
// each B fragment is one 8B LDS.64.
// EPI: 0 = +bias, 1 = +bias,BN,SiLU, 2 = raw
template<int CI, int TAPS, int EPI, int GROUPED>
__global__ __launch_bounds__(256, 2) void conv_mma(
    const float* __restrict__ in, const float* __restrict__ W,
    float* __restrict__ out,
    const float* __restrict__ bias, const float* __restrict__ g1,
    const float* __restrict__ be1, const float* __restrict__ m1,
    const float* __restrict__ v1) {
  extern __shared__ char sm[];
  constexpr uint32_t OP = 0;                              // pixel plane 19008 B
  constexpr uint32_t OW = 6*66*48;                        // 19008

  const int tid = threadIdx.x;
  const int lane = tid & 31, wid = tid >> 5;
  const int wy = wid >> 1, wx = wid & 1;                  // 4 m-warps x 2 n-warps
  const int g = lane >> 2, tq = lane & 3;
  const int rowblk = blockIdx.x;                          // 4 image rows
  const int cob = blockIdx.y;
  const int co0 = cob * 64;
  const int b = blockIdx.z;
  const int nco = gridDim.y * 64;
  const int nch = GROUPED ? gridDim.y * CI : CI;
  const int in_off = GROUPED ? cob * CI : 0;
  const float* inb = in + ((size_t)b*nch + in_off)*HWP;
  const uint32_t sbase = s2u(sm);

  float cacc[4][4][4];
  #pragma unroll
  for (int mm = 0; mm < 4; mm++)
    #pragma unroll
    for (int nn = 0; nn < 4; nn++)
      #pragma unroll
      for (int j = 0; j < 4; j++) cacc[mm][nn][j] = 0.f;

  for (int cb = 0; cb < CI/16; cb++) {
    __syncthreads();
    // ---- pixel tile [6 rows][66 cols][16 ci] fp16, 48B slot stride ----
    for (int i = tid; i < 792; i += 256) {
      int half = i & 1, slot = i >> 1;
      int r = slot / 66, c = slot - r*66;
      int y = rowblk*4 + r - 1, xx = c - 1;
      bool ok = ((unsigned)y < 64u) && ((unsigned)xx < 64u);
      const float* src = inb + (size_t)(cb*16 + half*8)*HWP + y*64 + xx;
      uint32_t hw[4];
      #pragma unroll
      for (int jj = 0; jj < 4; jj++) {
        float v0 = ok ? src[(size_t)(2*jj)*HWP]   : 0.f;
        float v1 = ok ? src[(size_t)(2*jj+1)*HWP] : 0.f;
        hw[jj] = (uint32_t)f16r(v0) | ((uint32_t)f16r(v1) << 16);
      }
      uint32_t boff = (uint32_t)slot*48 + half*16;
      *(uint4*)(sm + OP + boff) = make_uint4(hw[0],hw[1],hw[2],hw[3]);
    }
    // ---- weight tile [tap][64 co][16 ci re-paired] fp16 ----
    constexpr int PERM = TAPS*4;   // float4 per co-row for this ci-block
    for (int i = tid; i < 64*PERM; i += 256) {
      int m = i / PERM, q = i - m*PERM;
      const float* wm = W + ((size_t)(co0+m)*CI + cb*16)*TAPS;
      float4 v = *(const float4*)(wm + q*4);
      #pragma unroll
      for (int j = 0; j < 4; j++) {
        int e = q*4 + j;
        int ci = e / TAPS, t = e - ci*TAPS;
        int pos = ((ci & 7) >> 1)*4 + (ci >> 3)*2 + (ci & 1);
        uint32_t off = (uint32_t)((t*64 + m)*16 + pos)*2;
        *(uint16_t*)(sm + OW + off) = f16r((&v.x)[j]);
      }
    }
    __syncthreads();
    // ---- taps: shift pixel pointers, mma ----
    #pragma unroll 1
    for (int tap = 0; tap < TAPS; tap++) {
      int dy = (TAPS == 9) ? tap/3 - 1 : 0;
      int dx = (TAPS == 9) ? tap - (tap/3)*3 - 1 : 0;
      uint32_t ah[4][4];
      #pragma unroll
      for (int mm = 0; mm < 4; mm++) {
        int pxm = wy*64 + mm*16 + (lane & 15);
        int rr = (pxm >> 6) + 1 + dy;
        int cc = (pxm & 63) + 1 + dx;
        uint32_t boff = (uint32_t)(rr*66 + cc)*48 + ((lane >> 4) & 1)*16;
        ldmx4(ah[mm], sbase + OP + boff);
      }
      #pragma unroll
      for (int nn = 0; nn < 4; nn++) {
        int cof = wx*32 + nn*8 + g;
        uint32_t woff = (uint32_t)(tap*64 + cof)*32 + tq*8;
        uint2 bh = *(const uint2*)(sm + OW + woff);
        #pragma unroll
        for (int mm = 0; mm < 4; mm++) {
          mma_f16(cacc[mm][nn], ah[mm], bh.x, bh.y);
        }
      }
    }
  }
  // ---- epilogue: frags -> smem stage (stride 260 = conflict-free) -> gmem ----
  __syncthreads();
  float* osm = (float*)sm;
  #pragma unroll
  for (int mm = 0; mm < 4; mm++)
    #pragma unroll
    for (int nn = 0; nn < 4; nn++) {
      int px  = wy*64 + mm*16 + g;
      int col = wx*32 + nn*8 + tq*2;
      osm[(col  )*260 + px    ] = cacc[mm][nn][0];
      osm[(col+1)*260 + px    ] = cacc[mm][nn][1];
      osm[(col  )*260 + px + 8] = cacc[mm][nn][2];
      osm[(col+1)*260 + px + 8] = cacc[mm][nn][3];
    }
  __syncthreads();
  for (int i = tid; i < 16384; i += 256) {
    int col = i >> 8, px = i & 255;
    float v = osm[col*260 + px];
    int cg = co0 + col;
    if (EPI == 0) v += bias[cg];
    if (EPI == 1) {
      float sc = g1[cg] * rsqrtf(v1[cg] + 1e-5f);
      float sh = be1[cg] - m1[cg]*sc;
      v = (v + bias[cg])*sc + sh;
      v = v / (1.f + expf(-v));
    }
    out[((size_t)(b*nco + cg))*HWP + rowblk*256 + px] = v;
  }
}

// ---------------- K3: 1x1 conv 64->36 + softmax(9) groups ---------------------
__global__ __launch_bounds__(256) void k3_kw(const float* __restrict__ Wkp2,
                                             const float* __restrict__ bkp2) {
  __shared__ float ws[36*64];
  __shared__ float bs[36];
  int tid = threadIdx.x;
  for (int i = tid; i < 2304; i += 256) ws[i] = Wkp2[i];
  if (tid < 36) bs[tid] = bkp2[tid];
  __syncthreads();
  int gp = blockIdx.x*256 + tid;
  int b = gp >> 12, p = gp & 4095;
  float acc[36];
  #pragma unroll
  for (int j=0;j<36;j++) acc[j]=bs[j];
  const float* tb = g_t + (size_t)b*64*HWP + p;
  for (int ci=0; ci<64; ci++) {
    float tv = tb[(size_t)ci*HWP];
    #pragma unroll
    for (int j=0;j<36;j++) acc[j] += ws[j*64+ci]*tv;
  }
  float ks[9];
  #pragma unroll
  for (int k=0;k<9;k++) ks[k]=0.f;
  float* kwp = g_kw + (size_t)gp*36;
  #pragma unroll
  for (int s=0;s<4;s++) {
    float m = acc[s*9];
    #pragma unroll
    for (int k=1;k<9;k++) m = fmaxf(m, acc[s*9+k]);
    float e[9]; float sum=0.f;
    #pragma unroll
    for (int k=0;k<9;k++){ e[k]=expf(acc[s*9+k]-m); sum+=e[k]; }
    float inv = 1.f/sum;
    #pragma unroll
    for (int k=0;k<9;k++){ float v=e[k]*inv; kwp[s*9+k]=v; ks[k]+=v; }
  }
  float* ksp = g_kwsum + (size_t)gp*9;
  #pragma unroll
  for (int k=0;k<9;k++) ksp[k]=ks[k];
}

// ---------------- K3b: g map = 3x3 box correlation of kwsum -------------------
__global__ void k3b_gmap() {
  int gp = blockIdx.x*256 + threadIdx.x;
  int b = gp >> 12, p = gp & 4095;
  int i = p >> 6, j = p & 63;
  float s = 0.f;
  #pragma unroll
  for (int ih=0; ih<3; ih++)
    #pragma unroll
    for (int iw=0; iw<3; iw++) {
      int h = i + 1 - ih, w = j + 1 - iw;
      if ((unsigned)h < 64u && (unsigned)w < 64u)
        s += g_kwsum[(size_t)(b*4096 + h*64 + w)*9 + ih*3 + iw];
    }
  g_gmap[gp] = s;
}

// ---------------- K5: pooled[b,c] = sum(x*g)/16384 + sum(enh)/4096 ------------
__global__ __launch_bounds__(256) void k5_pool(const float* __restrict__ x) {
  int bc = blockIdx.x;
  int b = bc >> 8;
  const float* xp = x      + (size_t)bc*HWP;
  const float* ep = g_enh  + (size_t)bc*HWP;
  const float* gp = g_gmap + (size_t)b*HWP;
  int tid = threadIdx.x;
  float s1=0.f, s2=0.f;
  for (int i = tid; i < HWP; i += 256) { s1 += xp[i]*gp[i]; s2 += ep[i]; }
  __shared__ float r1[256], r2[256];
  r1[tid]=s1; r2[tid]=s2;
  __syncthreads();
  for (int st=128; st>0; st>>=1) {
    if (tid < st) { r1[tid]+=r1[tid+st]; r2[tid]+=r2[tid+st]; }
    __syncthreads();
  }
  if (tid==0) g_pooled[bc] = r1[0]*(1.f/16384.f) + r2[0]*(1.f/4096.f);
}

// ---------------- K6: SE gate ---------------------------------------------------
__global__ __launch_bounds__(256) void k6_gate(const float* __restrict__ Wg1,
    const float* __restrict__ bg1, const float* __restrict__ Wg2,
    const float* __restrict__ bg2) {
  int b = blockIdx.x, tid = threadIdx.x;
  __shared__ float pl[256], hid[64];
  pl[tid] = g_pooled[b*256 + tid];
  __syncthreads();
  if (tid < 64) {
    float a = bg1[tid];
    for (int ci=0; ci<256; ci++) a += Wg1[tid*256+ci]*pl[ci];
    hid[tid] = a / (1.f + expf(-a));
  }
  __syncthreads();
  float a = bg2[tid];
  for (int j=0;j<64;j++) a += Wg2[tid*64+j]*hid[j];
  g_gate[b*256+tid] = 1.f/(1.f+expf(-a));
}

// ---------------- K7: reassembly + bilinear up + gate -> output ----------------
// Block: 4 h-rows x 64 cols x 16 channels. One thread = one (h,col) pixel,
// owning all 36 softmax weights in registers; loops 16 channels.
__global__ __launch_bounds__(256, 2) void k7_fused(const float* __restrict__ x,
                                                   float* __restrict__ out) {
  extern __shared__ float sm7[];
  float* xs = sm7;                 // [16][6][66]
  float* es = sm7 + 16*6*66;       // [16][6][64]
  const int tid = threadIdx.x;
  const int c0 = blockIdx.x * 16;
  const int h0 = blockIdx.y * 4;
  const int b  = blockIdx.z;
  // loads: x halo rows h0-1..h0+4, zero-padded cols -1..64
  for (int i = tid; i < 16*6*66; i += 256) {
    int cc = i / 396, rem = i - cc*396;
    int rr = rem / 66, col = rem - rr*66 - 1;
    int y = h0 + rr - 1;
    float v = 0.f;
    if ((unsigned)y < 64u && (unsigned)col < 64u)
      v = x[((size_t)(b*CH)+c0+cc)*HWP + y*64 + col];
    xs[i] = v;
  }
  // enh rows h0-1..h0+4 clamped
  for (int i = tid; i < 16*6*64; i += 256) {
    int cc = i / 384, rem = i - cc*384;
    int rr = rem >> 6, col = rem & 63;
    int y = min(max(h0 + rr - 1, 0), 63);
    es[i] = g_enh[((size_t)(b*CH)+c0+cc)*HWP + y*64 + col];
  }
  __syncthreads();
  const int r = tid >> 6, col = tid & 63;
  const int h = h0 + r;
  // 36 softmax weights for this pixel -> registers (9x float4)
  float kp[36];
  {
    const float4* kq = (const float4*)(g_kw + ((size_t)(b*4096 + h*64 + col))*36);
    #pragma unroll
    for (int j = 0; j < 9; j++) {
      float4 v = kq[j];
      kp[4*j] = v.x; kp[4*j+1] = v.y; kp[4*j+2] = v.z; kp[4*j+3] = v.w;
    }
  }
  // bilinear column interp (half-pixel, clamped)
  int base; float fw;
  if (col & 1) { base = (col - 1) >> 1; fw = 0.25f; }
  else         { base = (col >> 1) - 1; fw = 0.75f; }
  int cA0 = max(base, 0);
  int cB0 = base + 1;
  int cA1 = base + 32;
  int cB1 = min(base + 33, 63);
  float fw1 = 1.f - fw;
  #pragma unroll 1
  for (int cc = 0; cc < 16; cc++) {
    int c = c0 + cc;
    float gt = g_gate[b*256 + c];
    const float* xr = &xs[cc*396 + r*66 + col];
    float x00=xr[0],   x01=xr[1],   x02=xr[2];
    float x10=xr[66],  x11=xr[67],  x12=xr[68];
    float x20=xr[132], x21=xr[133], x22=xr[134];
    const float* er = &es[cc*384 + r*64];
    float rv[3][2];
    #pragma unroll
    for (int j = 0; j < 3; j++) {
      rv[j][0] = fw1*er[j*64 + cA0] + fw*er[j*64 + cB0];
      rv[j][1] = fw1*er[j*64 + cA1] + fw*er[j*64 + cB1];
    }
    float up[2][2];
    up[0][0] = 0.25f*rv[0][0] + 0.75f*rv[1][0];
    up[0][1] = 0.25f*rv[0][1] + 0.75f*rv[1][1];
    up[1][0] = 0.75f*rv[1][0] + 0.25f*rv[2][0];
    up[1][1] = 0.75f*rv[1][1] + 0.25f*rv[2][1];
    #pragma unroll
    for (int s = 0; s < 4; s++) {
      const float* kq = &kp[s*9];
      float ko = x00*kq[0]+x01*kq[1]+x02*kq[2]
               + x10*kq[3]+x11*kq[4]+x12*kq[5]
               + x20*kq[6]+x21*kq[7]+x22*kq[8];
      int di = s >> 1, dj = s & 1;
      size_t oidx = (size_t)(b*256 + c)*16384 + (size_t)(2*h+di)*128 + (size_t)(dj*64 + col);
      out[oidx] = (ko + up[di][dj]) * gt;
    }
  }
}

// ---------------- launch --------------------------------------------------------
extern "C" void kernel_launch(void* const* d_in, const int* in_sizes, int n_in,
                              void* d_out, int out_size) {
  const float* x    = (const float*)d_in[0];
  const float* Wkc  = (const float*)d_in[1];
  const float* bkc  = (const float*)d_in[2];
  const float* Wkp1 = (const float*)d_in[3];
  const float* bkp1 = (const float*)d_in[4];
  const float* g1   = (const float*)d_in[5];
  const float* be1  = (const float*)d_in[6];
  const float* m1   = (const float*)d_in[7];
  const float* v1   = (const float*)d_in[8];
  const float* Wkp2 = (const float*)d_in[9];
  const float* bkp2 = (const float*)d_in[10];
  const float* Wdef = (const float*)d_in[11];
  const float* Wg1  = (const float*)d_in[12];
  const float* bg1  = (const float*)d_in[13];
  const float* Wg2  = (const float*)d_in[14];
  const float* bg2  = (const float*)d_in[15];
  float* out = (float*)d_out;

  float* comp = nullptr; float* t = nullptr; float* enh = nullptr;
  cudaGetSymbolAddress((void**)&comp, g_comp);
  cudaGetSymbolAddress((void**)&t,    g_t);
  cudaGetSymbolAddress((void**)&enh,  g_enh);

  // conv smem: max(pixel(19008) + W(TAPS*2048), out stage 64*260*4 = 66560)
  const int SM_CONV = 66560;
  const int SM_K7   = (16*6*66 + 16*6*64) * 4;   // 49920

  // one-time setup: func attrs + side stream/events for branched capture
  static cudaStream_t s2 = nullptr;
  static cudaEvent_t evFork = nullptr, evJoin = nullptr;
  if (s2 == nullptr) {
    cudaFuncSetAttribute(conv_mma<256,1,0,0>, cudaFuncAttributeMaxDynamicSharedMemorySize, SM_CONV);
    cudaFuncSetAttribute(conv_mma<128,9,1,0>, cudaFuncAttributeMaxDynamicSharedMemorySize, SM_CONV);
    cudaFuncSetAttribute(conv_mma<64,9,2,1>,  cudaFuncAttributeMaxDynamicSharedMemorySize, SM_CONV);
    cudaFuncSetAttribute(k7_fused,            cudaFuncAttributeMaxDynamicSharedMemorySize, SM_K7);
    cudaStreamCreateWithFlags(&s2, cudaStreamNonBlocking);
    cudaEventCreateWithFlags(&evFork, cudaEventDisableTiming);
    cudaEventCreateWithFlags(&evJoin, cudaEventDisableTiming);
  }

  // ---- fork: grouped conv (k4) on side stream, predictor chain on main ----
  cudaEventRecord(evFork, 0);
  cudaStreamWaitEvent(s2, evFork, 0);

  conv_mma<64,9,2,1> <<<dim3(16,4,8), 256, SM_CONV, s2>>>(x, Wdef, enh,
      nullptr, nullptr, nullptr, nullptr, nullptr);

  conv_mma<256,1,0,0><<<dim3(16,2,8), 256, SM_CONV>>>(x,    Wkc,  comp, bkc,  nullptr, nullptr, nullptr, nullptr);
  conv_mma<128,9,1,0><<<dim3(16,1,8), 256, SM_CONV>>>(comp, Wkp1, t,    bkp1, g1, be1, m1, v1);
  k3_kw   <<<128, 256>>>(Wkp2, bkp2);
  k3b_gmap<<<128, 256>>>();

  // ---- join: everything below needs enh (k4) ----
  cudaEventRecord(evJoin, s2);
  cudaStreamWaitEvent(0, evJoin, 0);

  k5_pool <<<2048, 256>>>(x);
  k6_gate <<<8,    256>>>(Wg1, bg1, Wg2, bg2);
  k7_fused<<<dim3(16,16,8), 256, SM_K7>>>(x, out);
}

// round 9
// speedup vs baseline: 2.8854x; 1.0244x over previous
#include <cuda_runtime.h>
#include <cuda_fp16.h>
#include <cstdint>
#include <math.h>

#define BATCH 8
#define CH    256
#define HWP   4096   // 64*64

// ---------------- scratch (static device allocations; no cudaMalloc) ----------
__device__ float g_comp [BATCH*128*HWP];
__device__ float g_t    [BATCH*64*HWP];
__device__ float g_kw   [BATCH*HWP*36];
__device__ float g_kwsum[BATCH*HWP*9];
__device__ float g_gmap [BATCH*HWP];
__device__ float g_enh  [BATCH*CH*HWP];
__device__ float g_pooled[BATCH*CH];
__device__ float g_gate  [BATCH*CH];

// ---------------- helpers ------------------------------------------------------
__device__ __forceinline__ uint32_t s2u(const void* p){
  uint32_t a; asm("{ .reg .u64 t; cvta.to.shared.u64 t, %1; cvt.u32.u64 %0, t; }"
                  : "=r"(a) : "l"(p)); return a;
}
__device__ __forceinline__ uint16_t f16r(float v){
  __half h = __float2half_rn(v);
  return __half_as_ushort(h);
}
__device__ __forceinline__ void ldmx4(uint32_t r[4], uint32_t addr){
  asm volatile("ldmatrix.sync.aligned.m8n8.x4.shared.b16 {%0,%1,%2,%3}, [%4];"
               : "=r"(r[0]), "=r"(r[1]), "=r"(r[2]), "=r"(r[3]) : "r"(addr));
}
__device__ __forceinline__ void mma_f16(float c[4], const uint32_t a[4],
                                        uint32_t b0, uint32_t b1){
  asm volatile("mma.sync.aligned.m16n8k16.row.col.f32.f16.f16.f32 "
               "{%0,%1,%2,%3},{%4,%5,%6,%7},{%8,%9},{%0,%1,%2,%3};"
               : "+f"(c[0]), "+f"(c[1]), "+f"(c[2]), "+f"(c[3])
               : "r"(a[0]), "r"(a[1]), "r"(a[2]), "r"(a[3]), "r"(b0), "r"(b1));
}

// ================= implicit-GEMM conv on HMMA fp16 (single-pass) ==============
template<int CI, int TAPS, int EPI, int GROUPED>
__global__ __launch_bounds__(256, 2) void conv_mma(
    const float* __restrict__ in, const float* __restrict__ W,
    float* __restrict__ out,
    const float* __restrict__ bias, const float* __restrict__ g1,
    const float* __restrict__ be1, const float* __restrict__ m1,
    const float* __restrict__ v1) {
  extern __shared__ char sm[];
  constexpr uint32_t OP = 0;                              // pixel plane 19008 B
  constexpr uint32_t OW = 6*66*48;                        // 19008

  const int tid = threadIdx.x;
  const int lane = tid & 31, wid = tid >> 5;
  const int wy = wid >> 1, wx = wid & 1;                  // 4 m-warps x 2 n-warps
  const int g = lane >> 2, tq = lane & 3;
  const int rowblk = blockIdx.x;                          // 4 image rows
  const int cob = blockIdx.y;
  const int co0 = cob * 64;
  const int b = blockIdx.z;
  const int nco = gridDim.y * 64;
  const int nch = GROUPED ? gridDim.y * CI : CI;
  const int in_off = GROUPED ? cob * CI : 0;
  const float* inb = in + ((size_t)b*nch + in_off)*HWP;
  const uint32_t sbase = s2u(sm);

  float cacc[4][4][4];
  #pragma unroll
  for (int mm = 0; mm < 4; mm++)
    #pragma unroll
    for (int nn = 0; nn < 4; nn++)
      #pragma unroll
      for (int j = 0; j < 4; j++) cacc[mm][nn][j] = 0.f;

  for (int cb = 0; cb < CI/16; cb++) {
    __syncthreads();
    // ---- pixel tile [6 rows][66 cols][16 ci] fp16, 48B slot stride ----
    for (int i = tid; i < 792; i += 256) {
      int half = i & 1, slot = i >> 1;
      int r = slot / 66, c = slot - r*66;
      int y = rowblk*4 + r - 1, xx = c - 1;
      bool ok = ((unsigned)y < 64u) && ((unsigned)xx < 64u);
      const float* src = inb + (size_t)(cb*16 + half*8)*HWP + y*64 + xx;
      uint32_t hw[4];
      #pragma unroll
      for (int jj = 0; jj < 4; jj++) {
        float v0 = ok ? src[(size_t)(2*jj)*HWP]   : 0.f;
        float v1 = ok ? src[(size_t)(2*jj+1)*HWP] : 0.f;
        hw[jj] = (uint32_t)f16r(v0) | ((uint32_t)f16r(v1) << 16);
      }
      uint32_t boff = (uint32_t)slot*48 + half*16;
      *(uint4*)(sm + OP + boff) = make_uint4(hw[0],hw[1],hw[2],hw[3]);
    }
    // ---- weight tile [tap][64 co][16 ci re-paired] fp16 ----
    constexpr int PERM = TAPS*4;   // float4 per co-row for this ci-block
    for (int i = tid; i < 64*PERM; i += 256) {
      int m = i / PERM, q = i - m*PERM;
      const float* wm = W + ((size_t)(co0+m)*CI + cb*16)*TAPS;
      float4 v = *(const float4*)(wm + q*4);
      #pragma unroll
      for (int j = 0; j < 4; j++) {
        int e = q*4 + j;
        int ci = e / TAPS, t = e - ci*TAPS;
        int pos = ((ci & 7) >> 1)*4 + (ci >> 3)*2 + (ci & 1);
        uint32_t off = (uint32_t)((t*64 + m)*16 + pos)*2;
        *(uint16_t*)(sm + OW + off) = f16r((&v.x)[j]);
      }
    }
    __syncthreads();
    // ---- taps: shift pixel pointers, mma ----
    #pragma unroll 1
    for (int tap = 0; tap < TAPS; tap++) {
      int dy = (TAPS == 9) ? tap/3 - 1 : 0;
      int dx = (TAPS == 9) ? tap - (tap/3)*3 - 1 : 0;
      uint32_t ah[4][4];
      #pragma unroll
      for (int mm = 0; mm < 4; mm++) {
        int pxm = wy*64 + mm*16 + (lane & 15);
        int rr = (pxm >> 6) + 1 + dy;
        int cc = (pxm & 63) + 1 + dx;
        uint32_t boff = (uint32_t)(rr*66 + cc)*48 + ((lane >> 4) & 1)*16;
        ldmx4(ah[mm], sbase + OP + boff);
      }
      #pragma unroll
      for (int nn = 0; nn < 4; nn++) {
        int cof = wx*32 + nn*8 + g;
        uint32_t woff = (uint32_t)(tap*64 + cof)*32 + tq*8;
        uint2 bh = *(const uint2*)(sm + OW + woff);
        #pragma unroll
        for (int mm = 0; mm < 4; mm++) {
          mma_f16(cacc[mm][nn], ah[mm], bh.x, bh.y);
        }
      }
    }
  }
  // ---- epilogue: frags -> smem stage (stride 260 = conflict-free) -> gmem ----
  __syncthreads();
  float* osm = (float*)sm;
  #pragma unroll
  for (int mm = 0; mm < 4; mm++)
    #pragma unroll
    for (int nn = 0; nn < 4; nn++) {
      int px  = wy*64 + mm*16 + g;
      int col = wx*32 + nn*8 + tq*2;
      osm[(col  )*260 + px    ] = cacc[mm][nn][0];
      osm[(col+1)*260 + px    ] = cacc[mm][nn][1];
      osm[(col  )*260 + px + 8] = cacc[mm][nn][2];
      osm[(col+1)*260 + px + 8] = cacc[mm][nn][3];
    }
  __syncthreads();
  for (int i = tid; i < 16384; i += 256) {
    int col = i >> 8, px = i & 255;
    float v = osm[col*260 + px];
    int cg = co0 + col;
    if (EPI == 0) v += bias[cg];
    if (EPI == 1) {
      float sc = g1[cg] * rsqrtf(v1[cg] + 1e-5f);
      float sh = be1[cg] - m1[cg]*sc;
      v = (v + bias[cg])*sc + sh;
      v = v / (1.f + expf(-v));
    }
    out[((size_t)(b*nco + cg))*HWP + rowblk*256 + px] = v;
  }
}

// ---------------- K3: 1x1 conv 64->36 + softmax(9) groups ---------------------
// 2 threads per pixel (ci halves), transposed weights, float4 broadcast loads.
__global__ __launch_bounds__(256) void k3_kw(const float* __restrict__ Wkp2,
                                             const float* __restrict__ bkp2) {
  __shared__ float wst[64][40];      // transposed [ci][j], padded row
  __shared__ float bs[36];
  __shared__ float part[128][37];    // odd stride -> conflict-free
  int tid = threadIdx.x;
  for (int i = tid; i < 2304; i += 256) {
    int j = i >> 6, ci = i & 63;
    wst[ci][j] = Wkp2[i];
  }
  if (tid < 36) bs[tid] = bkp2[tid];
  __syncthreads();
  int half = tid >> 7;               // ci half: 0 -> [0,32), 1 -> [32,64)
  int pl = tid & 127;
  int gp = blockIdx.x*128 + pl;      // 256 blocks x 128 px = 32768
  int b = gp >> 12, p = gp & 4095;
  float acc[36];
  #pragma unroll
  for (int j=0;j<36;j++) acc[j]=0.f;
  const float* tb = g_t + (size_t)b*64*HWP + p + (size_t)(half*32)*HWP;
  #pragma unroll 4
  for (int ci=0; ci<32; ci++) {
    float tv = tb[(size_t)ci*HWP];
    const float4* wp = (const float4*)&wst[half*32 + ci][0];
    #pragma unroll
    for (int q=0;q<9;q++) {
      float4 w = wp[q];
      acc[4*q+0] += w.x*tv; acc[4*q+1] += w.y*tv;
      acc[4*q+2] += w.z*tv; acc[4*q+3] += w.w*tv;
    }
  }
  if (half) {
    #pragma unroll
    for (int j=0;j<36;j++) part[pl][j] = acc[j];
  }
  __syncthreads();
  if (!half) {
    #pragma unroll
    for (int j=0;j<36;j++) acc[j] += part[pl][j] + bs[j];
    float ks[9];
    #pragma unroll
    for (int k=0;k<9;k++) ks[k]=0.f;
    float* kwp = g_kw + (size_t)gp*36;
    #pragma unroll
    for (int s=0;s<4;s++) {
      float m = acc[s*9];
      #pragma unroll
      for (int k=1;k<9;k++) m = fmaxf(m, acc[s*9+k]);
      float e[9]; float sum=0.f;
      #pragma unroll
      for (int k=0;k<9;k++){ e[k]=expf(acc[s*9+k]-m); sum+=e[k]; }
      float inv = 1.f/sum;
      #pragma unroll
      for (int k=0;k<9;k++){ float v=e[k]*inv; kwp[s*9+k]=v; ks[k]+=v; }
    }
    float* ksp = g_kwsum + (size_t)gp*9;
    #pragma unroll
    for (int k=0;k<9;k++) ksp[k]=ks[k];
  }
}

// ---------------- K3b: g map = 3x3 box correlation of kwsum -------------------
__global__ void k3b_gmap() {
  int gp = blockIdx.x*256 + threadIdx.x;
  int b = gp >> 12, p = gp & 4095;
  int i = p >> 6, j = p & 63;
  float s = 0.f;
  #pragma unroll
  for (int ih=0; ih<3; ih++)
    #pragma unroll
    for (int iw=0; iw<3; iw++) {
      int h = i + 1 - ih, w = j + 1 - iw;
      if ((unsigned)h < 64u && (unsigned)w < 64u)
        s += g_kwsum[(size_t)(b*4096 + h*64 + w)*9 + ih*3 + iw];
    }
  g_gmap[gp] = s;
}

// ---------------- K5: pooled[b,c] = sum(x*g)/16384 + sum(enh)/4096 ------------
__global__ __launch_bounds__(256) void k5_pool(const float* __restrict__ x) {
  int bc = blockIdx.x;
  int b = bc >> 8;
  const float* xp = x      + (size_t)bc*HWP;
  const float* ep = g_enh  + (size_t)bc*HWP;
  const float* gp = g_gmap + (size_t)b*HWP;
  int tid = threadIdx.x;
  float s1=0.f, s2=0.f;
  for (int i = tid; i < HWP; i += 256) { s1 += xp[i]*gp[i]; s2 += ep[i]; }
  __shared__ float r1[256], r2[256];
  r1[tid]=s1; r2[tid]=s2;
  __syncthreads();
  for (int st=128; st>0; st>>=1) {
    if (tid < st) { r1[tid]+=r1[tid+st]; r2[tid]+=r2[tid+st]; }
    __syncthreads();
  }
  if (tid==0) g_pooled[bc] = r1[0]*(1.f/16384.f) + r2[0]*(1.f/4096.f);
}

// ---------------- K6: SE gate ---------------------------------------------------
__global__ __launch_bounds__(256) void k6_gate(const float* __restrict__ Wg1,
    const float* __restrict__ bg1, const float* __restrict__ Wg2,
    const float* __restrict__ bg2) {
  int b = blockIdx.x, tid = threadIdx.x;
  __shared__ float pl[256], hid[64];
  pl[tid] = g_pooled[b*256 + tid];
  __syncthreads();
  if (tid < 64) {
    float a = bg1[tid];
    for (int ci=0; ci<256; ci++) a += Wg1[tid*256+ci]*pl[ci];
    hid[tid] = a / (1.f + expf(-a));
  }
  __syncthreads();
  float a = bg2[tid];
  for (int j=0;j<64;j++) a += Wg2[tid*64+j]*hid[j];
  g_gate[b*256+tid] = 1.f/(1.f+expf(-a));
}

// ---------------- K7: reassembly + bilinear up + gate -> output ----------------
__global__ __launch_bounds__(256, 2) void k7_fused(const float* __restrict__ x,
                                                   float* __restrict__ out) {
  extern __shared__ float sm7[];
  float* xs = sm7;                 // [16][6][66]
  float* es = sm7 + 16*6*66;       // [16][6][64]
  const int tid = threadIdx.x;
  const int c0 = blockIdx.x * 16;
  const int h0 = blockIdx.y * 4;
  const int b  = blockIdx.z;
  for (int i = tid; i < 16*6*66; i += 256) {
    int cc = i / 396, rem = i - cc*396;
    int rr = rem / 66, col = rem - rr*66 - 1;
    int y = h0 + rr - 1;
    float v = 0.f;
    if ((unsigned)y < 64u && (unsigned)col < 64u)
      v = x[((size_t)(b*CH)+c0+cc)*HWP + y*64 + col];
    xs[i] = v;
  }
  for (int i = tid; i < 16*6*64; i += 256) {
    int cc = i / 384, rem = i - cc*384;
    int rr = rem >> 6, col = rem & 63;
    int y = min(max(h0 + rr - 1, 0), 63);
    es[i] = g_enh[((size_t)(b*CH)+c0+cc)*HWP + y*64 + col];
  }
  __syncthreads();
  const int r = tid >> 6, col = tid & 63;
  const int h = h0 + r;
  float kp[36];
  {
    const float4* kq = (const float4*)(g_kw + ((size_t)(b*4096 + h*64 + col))*36);
    #pragma unroll
    for (int j = 0; j < 9; j++) {
      float4 v = kq[j];
      kp[4*j] = v.x; kp[4*j+1] = v.y; kp[4*j+2] = v.z; kp[4*j+3] = v.w;
    }
  }
  int base; float fw;
  if (col & 1) { base = (col - 1) >> 1; fw = 0.25f; }
  else         { base = (col >> 1) - 1; fw = 0.75f; }
  int cA0 = max(base, 0);
  int cB0 = base + 1;
  int cA1 = base + 32;
  int cB1 = min(base + 33, 63);
  float fw1 = 1.f - fw;
  #pragma unroll 1
  for (int cc = 0; cc < 16; cc++) {
    int c = c0 + cc;
    float gt = g_gate[b*256 + c];
    const float* xr = &xs[cc*396 + r*66 + col];
    float x00=xr[0],   x01=xr[1],   x02=xr[2];
    float x10=xr[66],  x11=xr[67],  x12=xr[68];
    float x20=xr[132], x21=xr[133], x22=xr[134];
    const float* er = &es[cc*384 + r*64];
    float rv[3][2];
    #pragma unroll
    for (int j = 0; j < 3; j++) {
      rv[j][0] = fw1*er[j*64 + cA0] + fw*er[j*64 + cB0];
      rv[j][1] = fw1*er[j*64 + cA1] + fw*er[j*64 + cB1];
    }
    float up[2][2];
    up[0][0] = 0.25f*rv[0][0] + 0.75f*rv[1][0];
    up[0][1] = 0.25f*rv[0][1] + 0.75f*rv[1][1];
    up[1][0] = 0.75f*rv[1][0] + 0.25f*rv[2][0];
    up[1][1] = 0.75f*rv[1][1] + 0.25f*rv[2][1];
    #pragma unroll
    for (int s = 0; s < 4; s++) {
      const float* kq = &kp[s*9];
      float ko = x00*kq[0]+x01*kq[1]+x02*kq[2]
               + x10*kq[3]+x11*kq[4]+x12*kq[5]
               + x20*kq[6]+x21*kq[7]+x22*kq[8];
      int di = s >> 1, dj = s & 1;
      size_t oidx = (size_t)(b*256 + c)*16384 + (size_t)(2*h+di)*128 + (size_t)(dj*64 + col);
      out[oidx] = (ko + up[di][dj]) * gt;
    }
  }
}

// ---------------- launch --------------------------------------------------------
extern "C" void kernel_launch(void* const* d_in, const int* in_sizes, int n_in,
                              void* d_out, int out_size) {
  const float* x    = (const float*)d_in[0];
  const float* Wkc  = (const float*)d_in[1];
  const float* bkc  = (const float*)d_in[2];
  const float* Wkp1 = (const float*)d_in[3];
  const float* bkp1 = (const float*)d_in[4];
  const float* g1   = (const float*)d_in[5];
  const float* be1  = (const float*)d_in[6];
  const float* m1   = (const float*)d_in[7];
  const float* v1   = (const float*)d_in[8];
  const float* Wkp2 = (const float*)d_in[9];
  const float* bkp2 = (const float*)d_in[10];
  const float* Wdef = (const float*)d_in[11];
  const float* Wg1  = (const float*)d_in[12];
  const float* bg1  = (const float*)d_in[13];
  const float* Wg2  = (const float*)d_in[14];
  const float* bg2  = (const float*)d_in[15];
  float* out = (float*)d_out;

  float* comp = nullptr; float* t = nullptr; float* enh = nullptr;
  cudaGetSymbolAddress((void**)&comp, g_comp);
  cudaGetSymbolAddress((void**)&t,    g_t);
  cudaGetSymbolAddress((void**)&enh,  g_enh);

  const int SM_CONV = 66560;
  const int SM_K7   = (16*6*66 + 16*6*64) * 4;   // 49920

  static cudaStream_t s2 = nullptr;
  static cudaEvent_t evFork = nullptr, evJoin = nullptr;
  if (s2 == nullptr) {
    cudaFuncSetAttribute(conv_mma<256,1,0,0>, cudaFuncAttributeMaxDynamicSharedMemorySize, SM_CONV);
    cudaFuncSetAttribute(conv_mma<128,9,1,0>, cudaFuncAttributeMaxDynamicSharedMemorySize, SM_CONV);
    cudaFuncSetAttribute(conv_mma<64,9,2,1>,  cudaFuncAttributeMaxDynamicSharedMemorySize, SM_CONV);
    cudaFuncSetAttribute(k7_fused,            cudaFuncAttributeMaxDynamicSharedMemorySize, SM_K7);
    cudaStreamCreateWithFlags(&s2, cudaStreamNonBlocking);
    cudaEventCreateWithFlags(&evFork, cudaEventDisableTiming);
    cudaEventCreateWithFlags(&evJoin, cudaEventDisableTiming);
  }

  // ---- fork: grouped conv (k4) on side stream, predictor chain on main ----
  cudaEventRecord(evFork, 0);
  cudaStreamWaitEvent(s2, evFork, 0);

  conv_mma<64,9,2,1> <<<dim3(16,4,8), 256, SM_CONV, s2>>>(x, Wdef, enh,
      nullptr, nullptr, nullptr, nullptr, nullptr);

  conv_mma<256,1,0,0><<<dim3(16,2,8), 256, SM_CONV>>>(x,    Wkc,  comp, bkc,  nullptr, nullptr, nullptr, nullptr);
  conv_mma<128,9,1,0><<<dim3(16,1,8), 256, SM_CONV>>>(comp, Wkp1, t,    bkp1, g1, be1, m1, v1);
  k3_kw   <<<256, 256>>>(Wkp2, bkp2);
  k3b_gmap<<<128, 256>>>();

  // ---- join: everything below needs enh (k4) ----
  cudaEventRecord(evJoin, s2);
  cudaStreamWaitEvent(0, evJoin, 0);

  k5_pool <<<2048, 256>>>(x);
  k6_gate <<<8,    256>>>(Wg1, bg1, Wg2, bg2);
  k7_fused<<<dim3(16,16,8), 256, SM_K7>>>(x, out);
}

// round 10
// speedup vs baseline: 3.0987x; 1.0739x over previous
#include <cuda_runtime.h>
#include <cuda_fp16.h>
#include <cstdint>
#include <math.h>

#define BATCH 8
#define CH    256
#define HWP   4096   // 64*64

// ---------------- scratch (static device allocations; no cudaMalloc) ----------
__device__ float g_comp [BATCH*128*HWP];
__device__ float g_t    [BATCH*64*HWP];
__device__ float g_part [4*BATCH*64*HWP];   // k2 ci-split partials (33.5 MB)
__device__ float g_kw   [BATCH*HWP*36];
__device__ float g_kwsum[BATCH*HWP*9];
__device__ float g_gmap [BATCH*HWP];
__device__ float g_enh  [BATCH*CH*HWP];
__device__ float g_pooled[BATCH*CH];
__device__ float g_gate  [BATCH*CH];

// ---------------- helpers ------------------------------------------------------
__device__ __forceinline__ uint32_t s2u(const void* p){
  uint32_t a; asm("{ .reg .u64 t; cvta.to.shared.u64 t, %1; cvt.u32.u64 %0, t; }"
                  : "=r"(a) : "l"(p)); return a;
}
__device__ __forceinline__ uint16_t f16r(float v){
  __half h = __float2half_rn(v);
  return __half_as_ushort(h);
}
__device__ __forceinline__ void ldmx4(uint32_t r[4], uint32_t addr){
  asm volatile("ldmatrix.sync.aligned.m8n8.x4.shared.b16 {%0,%1,%2,%3}, [%4];"
               : "=r"(r[0]), "=r"(r[1]), "=r"(r[2]), "=r"(r[3]) : "r"(addr));
}
__device__ __forceinline__ void mma_f16(float c[4], const uint32_t a[4],
                                        uint32_t b0, uint32_t b1){
  asm volatile("mma.sync.aligned.m16n8k16.row.col.f32.f16.f16.f32 "
               "{%0,%1,%2,%3},{%4,%5,%6,%7},{%8,%9},{%0,%1,%2,%3};"
               : "+f"(c[0]), "+f"(c[1]), "+f"(c[2]), "+f"(c[3])
               : "r"(a[0]), "r"(a[1]), "r"(a[2]), "r"(a[3]), "r"(b0), "r"(b1));
}

// ================= implicit-GEMM conv on HMMA fp16 (single-pass) ==============
// MODE 0: dense, blockIdx.y = co block    (k1)
// MODE 1: grouped, blockIdx.y = group     (k4)
// MODE 2: ci-split, blockIdx.y = split, co0=0, raw partials out (k2)
// EPI: 0 = +bias, 1 = +bias,BN,SiLU, 2 = raw
template<int CI, int CI_TOT, int TAPS, int EPI, int MODE>
__global__ __launch_bounds__(256, 2) void conv_mma(
    const float* __restrict__ in, const float* __restrict__ W,
    float* __restrict__ out,
    const float* __restrict__ bias, const float* __restrict__ g1,
    const float* __restrict__ be1, const float* __restrict__ m1,
    const float* __restrict__ v1) {
  extern __shared__ char sm[];
  constexpr uint32_t OP = 0;                              // pixel plane 19008 B
  constexpr uint32_t OW = 6*66*48;                        // 19008

  const int tid = threadIdx.x;
  const int lane = tid & 31, wid = tid >> 5;
  const int wy = wid >> 1, wx = wid & 1;                  // 4 m-warps x 2 n-warps
  const int g = lane >> 2, tq = lane & 3;
  const int rowblk = blockIdx.x;                          // 4 image rows
  const int cob = blockIdx.y;
  const int co0 = (MODE == 2) ? 0 : cob * 64;
  const int b = blockIdx.z;
  const int in_off = (MODE == 0) ? 0 : cob * CI;
  const float* inb = in + ((size_t)b*CI_TOT + in_off)*HWP;
  const uint32_t sbase = s2u(sm);

  float cacc[4][4][4];
  #pragma unroll
  for (int mm = 0; mm < 4; mm++)
    #pragma unroll
    for (int nn = 0; nn < 4; nn++)
      #pragma unroll
      for (int j = 0; j < 4; j++) cacc[mm][nn][j] = 0.f;

  for (int cb = 0; cb < CI/16; cb++) {
    __syncthreads();
    // ---- pixel tile [6 rows][66 cols][16 ci] fp16, 48B slot stride ----
    for (int i = tid; i < 792; i += 256) {
      int half = i & 1, slot = i >> 1;
      int r = slot / 66, c = slot - r*66;
      int y = rowblk*4 + r - 1, xx = c - 1;
      bool ok = ((unsigned)y < 64u) && ((unsigned)xx < 64u);
      const float* src = inb + (size_t)(cb*16 + half*8)*HWP + y*64 + xx;
      uint32_t hw[4];
      #pragma unroll
      for (int jj = 0; jj < 4; jj++) {
        float v0 = ok ? src[(size_t)(2*jj)*HWP]   : 0.f;
        float v1 = ok ? src[(size_t)(2*jj+1)*HWP] : 0.f;
        hw[jj] = (uint32_t)f16r(v0) | ((uint32_t)f16r(v1) << 16);
      }
      uint32_t boff = (uint32_t)slot*48 + half*16;
      *(uint4*)(sm + OP + boff) = make_uint4(hw[0],hw[1],hw[2],hw[3]);
    }
    // ---- weight tile [tap][64 co][16 ci re-paired] fp16 ----
    constexpr int PERM = TAPS*4;   // float4 per co-row for this ci-block
    for (int i = tid; i < 64*PERM; i += 256) {
      int m = i / PERM, q = i - m*PERM;
      size_t wb;
      if (MODE == 2) wb = ((size_t)m*CI_TOT + cob*CI + cb*16);
      else           wb = ((size_t)(co0 + m)*CI + cb*16);
      const float* wm = W + wb*TAPS;
      float4 v = *(const float4*)(wm + q*4);
      #pragma unroll
      for (int j = 0; j < 4; j++) {
        int e = q*4 + j;
        int ci = e / TAPS, t = e - ci*TAPS;
        int pos = ((ci & 7) >> 1)*4 + (ci >> 3)*2 + (ci & 1);
        uint32_t off = (uint32_t)((t*64 + m)*16 + pos)*2;
        *(uint16_t*)(sm + OW + off) = f16r((&v.x)[j]);
      }
    }
    __syncthreads();
    // ---- taps: shift pixel pointers, mma ----
    #pragma unroll 1
    for (int tap = 0; tap < TAPS; tap++) {
      int dy = (TAPS == 9) ? tap/3 - 1 : 0;
      int dx = (TAPS == 9) ? tap - (tap/3)*3 - 1 : 0;
      uint32_t ah[4][4];
      #pragma unroll
      for (int mm = 0; mm < 4; mm++) {
        int pxm = wy*64 + mm*16 + (lane & 15);
        int rr = (pxm >> 6) + 1 + dy;
        int cc = (pxm & 63) + 1 + dx;
        uint32_t boff = (uint32_t)(rr*66 + cc)*48 + ((lane >> 4) & 1)*16;
        ldmx4(ah[mm], sbase + OP + boff);
      }
      #pragma unroll
      for (int nn = 0; nn < 4; nn++) {
        int cof = wx*32 + nn*8 + g;
        uint32_t woff = (uint32_t)(tap*64 + cof)*32 + tq*8;
        uint2 bh = *(const uint2*)(sm + OW + woff);
        #pragma unroll
        for (int mm = 0; mm < 4; mm++) {
          mma_f16(cacc[mm][nn], ah[mm], bh.x, bh.y);
        }
      }
    }
  }
  // ---- epilogue: frags -> smem stage (stride 260 = conflict-free) -> gmem ----
  __syncthreads();
  float* osm = (float*)sm;
  #pragma unroll
  for (int mm = 0; mm < 4; mm++)
    #pragma unroll
    for (int nn = 0; nn < 4; nn++) {
      int px  = wy*64 + mm*16 + g;
      int col = wx*32 + nn*8 + tq*2;
      osm[(col  )*260 + px    ] = cacc[mm][nn][0];
      osm[(col+1)*260 + px    ] = cacc[mm][nn][1];
      osm[(col  )*260 + px + 8] = cacc[mm][nn][2];
      osm[(col+1)*260 + px + 8] = cacc[mm][nn][3];
    }
  __syncthreads();
  for (int i = tid; i < 16384; i += 256) {
    int col = i >> 8, px = i & 255;
    float v = osm[col*260 + px];
    int cg = co0 + col;
    if (EPI == 0) v += bias[cg];
    if (EPI == 1) {
      float sc = g1[cg] * rsqrtf(v1[cg] + 1e-5f);
      float sh = be1[cg] - m1[cg]*sc;
      v = (v + bias[cg])*sc + sh;
      v = v / (1.f + expf(-v));
    }
    size_t obase;
    if (MODE == 2) obase = ((size_t)cob*BATCH*64 + (size_t)b*64 + cg)*HWP;
    else           obase = ((size_t)b*(gridDim.y*64) + cg)*HWP;
    out[obase + rowblk*256 + px] = v;
  }
}

// ---------------- K2c: combine ci-split partials + bias + BN + SiLU -----------
__global__ __launch_bounds__(256) void k2_combine(const float* __restrict__ bias,
    const float* __restrict__ g1, const float* __restrict__ be1,
    const float* __restrict__ m1, const float* __restrict__ v1) {
  const int SL = BATCH*64*HWP;   // 2097152
  int i = blockIdx.x*256 + threadIdx.x;
  int c = (i >> 12) & 63;
  float v = g_part[i] + g_part[i+SL] + g_part[i+2*SL] + g_part[i+3*SL] + bias[c];
  float sc = g1[c]*rsqrtf(v1[c]+1e-5f);
  v = v*sc + (be1[c] - m1[c]*sc);
  g_t[i] = v/(1.f+expf(-v));
}

// ---------------- K3: 1x1 conv 64->36 + softmax(9) groups ---------------------
// 4 threads per pixel (16-ci quarters), transposed weights, float4 broadcasts.
__global__ __launch_bounds__(256) void k3_kw(const float* __restrict__ Wkp2,
                                             const float* __restrict__ bkp2) {
  __shared__ float wst[64][40];      // transposed [ci][j], padded row
  __shared__ float bs[36];
  __shared__ float part[3][64][37];  // odd stride -> conflict-free
  int tid = threadIdx.x;
  for (int i = tid; i < 2304; i += 256) {
    int j = i >> 6, ci = i & 63;
    wst[ci][j] = Wkp2[i];
  }
  if (tid < 36) bs[tid] = bkp2[tid];
  __syncthreads();
  int quart = tid >> 6;              // ci quarter
  int pl = tid & 63;
  int gp = blockIdx.x*64 + pl;       // 512 blocks x 64 px = 32768
  int b = gp >> 12, p = gp & 4095;
  float acc[36];
  #pragma unroll
  for (int j=0;j<36;j++) acc[j]=0.f;
  const float* tb = g_t + (size_t)b*64*HWP + p + (size_t)(quart*16)*HWP;
  #pragma unroll 4
  for (int ci=0; ci<16; ci++) {
    float tv = tb[(size_t)ci*HWP];
    const float4* wp = (const float4*)&wst[quart*16 + ci][0];
    #pragma unroll
    for (int q=0;q<9;q++) {
      float4 w = wp[q];
      acc[4*q+0] += w.x*tv; acc[4*q+1] += w.y*tv;
      acc[4*q+2] += w.z*tv; acc[4*q+3] += w.w*tv;
    }
  }
  if (quart) {
    #pragma unroll
    for (int j=0;j<36;j++) part[quart-1][pl][j] = acc[j];
  }
  __syncthreads();
  if (!quart) {
    #pragma unroll
    for (int j=0;j<36;j++)
      acc[j] += part[0][pl][j] + part[1][pl][j] + part[2][pl][j] + bs[j];
    float ks[9];
    #pragma unroll
    for (int k=0;k<9;k++) ks[k]=0.f;
    float* kwp = g_kw + (size_t)gp*36;
    #pragma unroll
    for (int s=0;s<4;s++) {
      float m = acc[s*9];
      #pragma unroll
      for (int k=1;k<9;k++) m = fmaxf(m, acc[s*9+k]);
      float e[9]; float sum=0.f;
      #pragma unroll
      for (int k=0;k<9;k++){ e[k]=expf(acc[s*9+k]-m); sum+=e[k]; }
      float inv = 1.f/sum;
      #pragma unroll
      for (int k=0;k<9;k++){ float v=e[k]*inv; kwp[s*9+k]=v; ks[k]+=v; }
    }
    float* ksp = g_kwsum + (size_t)gp*9;
    #pragma unroll
    for (int k=0;k<9;k++) ksp[k]=ks[k];
  }
}

// ---------------- K3b: g map = 3x3 box correlation of kwsum -------------------
__global__ void k3b_gmap() {
  int gp = blockIdx.x*256 + threadIdx.x;
  int b = gp >> 12, p = gp & 4095;
  int i = p >> 6, j = p & 63;
  float s = 0.f;
  #pragma unroll
  for (int ih=0; ih<3; ih++)
    #pragma unroll
    for (int iw=0; iw<3; iw++) {
      int h = i + 1 - ih, w = j + 1 - iw;
      if ((unsigned)h < 64u && (unsigned)w < 64u)
        s += g_kwsum[(size_t)(b*4096 + h*64 + w)*9 + ih*3 + iw];
    }
  g_gmap[gp] = s;
}

// ---------------- K5: pooled[b,c] = sum(x*g)/16384 + sum(enh)/4096 ------------
__global__ __launch_bounds__(256) void k5_pool(const float* __restrict__ x) {
  int bc = blockIdx.x;
  int b = bc >> 8;
  const float* xp = x      + (size_t)bc*HWP;
  const float* ep = g_enh  + (size_t)bc*HWP;
  const float* gp = g_gmap + (size_t)b*HWP;
  int tid = threadIdx.x;
  float s1=0.f, s2=0.f;
  for (int i = tid; i < HWP; i += 256) { s1 += xp[i]*gp[i]; s2 += ep[i]; }
  __shared__ float r1[256], r2[256];
  r1[tid]=s1; r2[tid]=s2;
  __syncthreads();
  for (int st=128; st>0; st>>=1) {
    if (tid < st) { r1[tid]+=r1[tid+st]; r2[tid]+=r2[tid+st]; }
    __syncthreads();
  }
  if (tid==0) g_pooled[bc] = r1[0]*(1.f/16384.f) + r2[0]*(1.f/4096.f);
}

// ---------------- K6: SE gate ---------------------------------------------------
__global__ __launch_bounds__(256) void k6_gate(const float* __restrict__ Wg1,
    const float* __restrict__ bg1, const float* __restrict__ Wg2,
    const float* __restrict__ bg2) {
  int b = blockIdx.x, tid = threadIdx.x;
  __shared__ float pl[256], hid[64];
  pl[tid] = g_pooled[b*256 + tid];
  __syncthreads();
  if (tid < 64) {
    float a = bg1[tid];
    for (int ci=0; ci<256; ci++) a += Wg1[tid*256+ci]*pl[ci];
    hid[tid] = a / (1.f + expf(-a));
  }
  __syncthreads();
  float a = bg2[tid];
  for (int j=0;j<64;j++) a += Wg2[tid*64+j]*hid[j];
  g_gate[b*256+tid] = 1.f/(1.f+expf(-a));
}

// ---------------- K7: reassembly + bilinear up + gate -> output ----------------
__global__ __launch_bounds__(256, 2) void k7_fused(const float* __restrict__ x,
                                                   float* __restrict__ out) {
  extern __shared__ float sm7[];
  float* xs = sm7;                 // [16][6][66]
  float* es = sm7 + 16*6*66;       // [16][6][64]
  const int tid = threadIdx.x;
  const int c0 = blockIdx.x * 16;
  const int h0 = blockIdx.y * 4;
  const int b  = blockIdx.z;
  for (int i = tid; i < 16*6*66; i += 256) {
    int cc = i / 396, rem = i - cc*396;
    int rr = rem / 66, col = rem - rr*66 - 1;
    int y = h0 + rr - 1;
    float v = 0.f;
    if ((unsigned)y < 64u && (unsigned)col < 64u)
      v = x[((size_t)(b*CH)+c0+cc)*HWP + y*64 + col];
    xs[i] = v;
  }
  for (int i = tid; i < 16*6*64; i += 256) {
    int cc = i / 384, rem = i - cc*384;
    int rr = rem >> 6, col = rem & 63;
    int y = min(max(h0 + rr - 1, 0), 63);
    es[i] = g_enh[((size_t)(b*CH)+c0+cc)*HWP + y*64 + col];
  }
  __syncthreads();
  const int r = tid >> 6, col = tid & 63;
  const int h = h0 + r;
  float kp[36];
  {
    const float4* kq = (const float4*)(g_kw + ((size_t)(b*4096 + h*64 + col))*36);
    #pragma unroll
    for (int j = 0; j < 9; j++) {
      float4 v = kq[j];
      kp[4*j] = v.x; kp[4*j+1] = v.y; kp[4*j+2] = v.z; kp[4*j+3] = v.w;
    }
  }
  int base; float fw;
  if (col & 1) { base = (col - 1) >> 1; fw = 0.25f; }
  else         { base = (col >> 1) - 1; fw = 0.75f; }
  int cA0 = max(base, 0);
  int cB0 = base + 1;
  int cA1 = base + 32;
  int cB1 = min(base + 33, 63);
  float fw1 = 1.f - fw;
  #pragma unroll 1
  for (int cc = 0; cc < 16; cc++) {
    int c = c0 + cc;
    float gt = g_gate[b*256 + c];
    const float* xr = &xs[cc*396 + r*66 + col];
    float x00=xr[0],   x01=xr[1],   x02=xr[2];
    float x10=xr[66],  x11=xr[67],  x12=xr[68];
    float x20=xr[132], x21=xr[133], x22=xr[134];
    const float* er = &es[cc*384 + r*64];
    float rv[3][2];
    #pragma unroll
    for (int j = 0; j < 3; j++) {
      rv[j][0] = fw1*er[j*64 + cA0] + fw*er[j*64 + cB0];
      rv[j][1] = fw1*er[j*64 + cA1] + fw*er[j*64 + cB1];
    }
    float up[2][2];
    up[0][0] = 0.25f*rv[0][0] + 0.75f*rv[1][0];
    up[0][1] = 0.25f*rv[0][1] + 0.75f*rv[1][1];
    up[1][0] = 0.75f*rv[1][0] + 0.25f*rv[2][0];
    up[1][1] = 0.75f*rv[1][1] + 0.25f*rv[2][1];
    #pragma unroll
    for (int s = 0; s < 4; s++) {
      const float* kq = &kp[s*9];
      float ko = x00*kq[0]+x01*kq[1]+x02*kq[2]
               + x10*kq[3]+x11*kq[4]+x12*kq[5]
               + x20*kq[6]+x21*kq[7]+x22*kq[8];
      int di = s >> 1, dj = s & 1;
      size_t oidx = (size_t)(b*256 + c)*16384 + (size_t)(2*h+di)*128 + (size_t)(dj*64 + col);
      out[oidx] = (ko + up[di][dj]) * gt;
    }
  }
}

// ---------------- launch --------------------------------------------------------
extern "C" void kernel_launch(void* const* d_in, const int* in_sizes, int n_in,
                              void* d_out, int out_size) {
  const float* x    = (const float*)d_in[0];
  const float* Wkc  = (const float*)d_in[1];
  const float* bkc  = (const float*)d_in[2];
  const float* Wkp1 = (const float*)d_in[3];
  const float* bkp1 = (const float*)d_in[4];
  const float* g1   = (const float*)d_in[5];
  const float* be1  = (const float*)d_in[6];
  const float* m1   = (const float*)d_in[7];
  const float* v1   = (const float*)d_in[8];
  const float* Wkp2 = (const float*)d_in[9];
  const float* bkp2 = (const float*)d_in[10];
  const float* Wdef = (const float*)d_in[11];
  const float* Wg1  = (const float*)d_in[12];
  const float* bg1  = (const float*)d_in[13];
  const float* Wg2  = (const float*)d_in[14];
  const float* bg2  = (const float*)d_in[15];
  float* out = (float*)d_out;

  float* comp = nullptr; float* part = nullptr; float* enh = nullptr;
  cudaGetSymbolAddress((void**)&comp, g_comp);
  cudaGetSymbolAddress((void**)&part, g_part);
  cudaGetSymbolAddress((void**)&enh,  g_enh);

  const int SM_CONV = 66560;
  const int SM_K7   = (16*6*66 + 16*6*64) * 4;   // 49920

  static cudaStream_t s2 = nullptr;
  static cudaEvent_t evFork = nullptr, evJoin = nullptr;
  if (s2 == nullptr) {
    cudaFuncSetAttribute((const void*)conv_mma<256,256,1,0,0>, cudaFuncAttributeMaxDynamicSharedMemorySize, SM_CONV);
    cudaFuncSetAttribute((const void*)conv_mma<32,128,9,2,2>,  cudaFuncAttributeMaxDynamicSharedMemorySize, SM_CONV);
    cudaFuncSetAttribute((const void*)conv_mma<64,256,9,2,1>,  cudaFuncAttributeMaxDynamicSharedMemorySize, SM_CONV);
    cudaFuncSetAttribute((const void*)k7_fused,                cudaFuncAttributeMaxDynamicSharedMemorySize, SM_K7);
    cudaStreamCreateWithFlags(&s2, cudaStreamNonBlocking);
    cudaEventCreateWithFlags(&evFork, cudaEventDisableTiming);
    cudaEventCreateWithFlags(&evJoin, cudaEventDisableTiming);
  }

  // ---- fork: grouped conv (k4) on side stream, predictor chain on main ----
  cudaEventRecord(evFork, 0);
  cudaStreamWaitEvent(s2, evFork, 0);

  conv_mma<64,256,9,2,1><<<dim3(16,4,8), 256, SM_CONV, s2>>>(x, Wdef, enh,
      nullptr, nullptr, nullptr, nullptr, nullptr);

  conv_mma<256,256,1,0,0><<<dim3(16,2,8), 256, SM_CONV>>>(x, Wkc, comp, bkc,
      nullptr, nullptr, nullptr, nullptr);
  conv_mma<32,128,9,2,2><<<dim3(16,4,8), 256, SM_CONV>>>(comp, Wkp1, part,
      nullptr, nullptr, nullptr, nullptr, nullptr);
  k2_combine<<<8192, 256>>>(bkp1, g1, be1, m1, v1);
  k3_kw   <<<512, 256>>>(Wkp2, bkp2);
  k3b_gmap<<<128, 256>>>();

  // ---- join: everything below needs enh (k4) ----
  cudaEventRecord(evJoin, s2);
  cudaStreamWaitEvent(0, evJoin, 0);

  k5_pool <<<2048, 256>>>(x);
  k6_gate <<<8,    256>>>(Wg1, bg1, Wg2, bg2);
  k7_fused<<<dim3(16,16,8), 256, SM_K7>>>(x, out);
}

// round 11
// speedup vs baseline: 3.1292x; 1.0098x over previous
#include <cuda_runtime.h>
#include <cuda_fp16.h>
#include <cstdint>
#include <math.h>

#define BATCH 8
#define CH    256
#define HWP   4096   // 64*64

// ---------------- scratch (static device allocations; no cudaMalloc) ----------
__device__ float g_comp [BATCH*128*HWP];
__device__ float g_part [4*BATCH*64*HWP];   // k2 ci-split partials (33.5 MB)
__device__ float g_kw   [BATCH*HWP*36];
__device__ float g_kwsum[BATCH*HWP*9];
__device__ float g_gmap [BATCH*HWP];
__device__ float g_enh  [BATCH*CH*HWP];
__device__ float g_pool_x[BATCH*CH];
__device__ float g_pool_e[BATCH*CH];
__device__ float g_gate  [BATCH*CH];

// ---------------- helpers ------------------------------------------------------
__device__ __forceinline__ uint32_t s2u(const void* p){
  uint32_t a; asm("{ .reg .u64 t; cvta.to.shared.u64 t, %1; cvt.u32.u64 %0, t; }"
                  : "=r"(a) : "l"(p)); return a;
}
__device__ __forceinline__ uint16_t f16r(float v){
  __half h = __float2half_rn(v);
  return __half_as_ushort(h);
}
__device__ __forceinline__ void ldmx4(uint32_t r[4], uint32_t addr){
  asm volatile("ldmatrix.sync.aligned.m8n8.x4.shared.b16 {%0,%1,%2,%3}, [%4];"
               : "=r"(r[0]), "=r"(r[1]), "=r"(r[2]), "=r"(r[3]) : "r"(addr));
}
__device__ __forceinline__ void mma_f16(float c[4], const uint32_t a[4],
                                        uint32_t b0, uint32_t b1){
  asm volatile("mma.sync.aligned.m16n8k16.row.col.f32.f16.f16.f32 "
               "{%0,%1,%2,%3},{%4,%5,%6,%7},{%8,%9},{%0,%1,%2,%3};"
               : "+f"(c[0]), "+f"(c[1]), "+f"(c[2]), "+f"(c[3])
               : "r"(a[0]), "r"(a[1]), "r"(a[2]), "r"(a[3]), "r"(b0), "r"(b1));
}

// ================= implicit-GEMM conv on HMMA fp16 (single-pass) ==============
// MODE 0: dense, blockIdx.y = co block    (k1)
// MODE 1: grouped, blockIdx.y = group     (k4)
// MODE 2: ci-split, blockIdx.y = split, co0=0, raw partials out (k2)
// EPI: 0 = +bias, 2 = raw
template<int CI, int CI_TOT, int TAPS, int EPI, int MODE>
__global__ __launch_bounds__(256, 2) void conv_mma(
    const float* __restrict__ in, const float* __restrict__ W,
    float* __restrict__ out, const float* __restrict__ bias) {
  extern __shared__ char sm[];
  constexpr uint32_t OP = 0;                              // pixel plane 19008 B
  constexpr uint32_t OW = 6*66*48;                        // 19008

  const int tid = threadIdx.x;
  const int lane = tid & 31, wid = tid >> 5;
  const int wy = wid >> 1, wx = wid & 1;                  // 4 m-warps x 2 n-warps
  const int g = lane >> 2, tq = lane & 3;
  const int rowblk = blockIdx.x;                          // 4 image rows
  const int cob = blockIdx.y;
  const int co0 = (MODE == 2) ? 0 : cob * 64;
  const int b = blockIdx.z;
  const int in_off = (MODE == 0) ? 0 : cob * CI;
  const float* inb = in + ((size_t)b*CI_TOT + in_off)*HWP;
  const uint32_t sbase = s2u(sm);

  float cacc[4][4][4];
  #pragma unroll
  for (int mm = 0; mm < 4; mm++)
    #pragma unroll
    for (int nn = 0; nn < 4; nn++)
      #pragma unroll
      for (int j = 0; j < 4; j++) cacc[mm][nn][j] = 0.f;

  for (int cb = 0; cb < CI/16; cb++) {
    __syncthreads();
    // ---- pixel tile [6 rows][66 cols][16 ci] fp16, 48B slot stride ----
    for (int i = tid; i < 792; i += 256) {
      int half = i & 1, slot = i >> 1;
      int r = slot / 66, c = slot - r*66;
      int y = rowblk*4 + r - 1, xx = c - 1;
      bool ok = ((unsigned)y < 64u) && ((unsigned)xx < 64u);
      const float* src = inb + (size_t)(cb*16 + half*8)*HWP + y*64 + xx;
      uint32_t hw[4];
      #pragma unroll
      for (int jj = 0; jj < 4; jj++) {
        float v0 = ok ? src[(size_t)(2*jj)*HWP]   : 0.f;
        float v1 = ok ? src[(size_t)(2*jj+1)*HWP] : 0.f;
        hw[jj] = (uint32_t)f16r(v0) | ((uint32_t)f16r(v1) << 16);
      }
      uint32_t boff = (uint32_t)slot*48 + half*16;
      *(uint4*)(sm + OP + boff) = make_uint4(hw[0],hw[1],hw[2],hw[3]);
    }
    // ---- weight tile [tap][64 co][16 ci re-paired] fp16 ----
    constexpr int PERM = TAPS*4;   // float4 per co-row for this ci-block
    for (int i = tid; i < 64*PERM; i += 256) {
      int m = i / PERM, q = i - m*PERM;
      size_t wb;
      if (MODE == 2) wb = ((size_t)m*CI_TOT + cob*CI + cb*16);
      else           wb = ((size_t)(co0 + m)*CI + cb*16);
      const float* wm = W + wb*TAPS;
      float4 v = *(const float4*)(wm + q*4);
      #pragma unroll
      for (int j = 0; j < 4; j++) {
        int e = q*4 + j;
        int ci = e / TAPS, t = e - ci*TAPS;
        int pos = ((ci & 7) >> 1)*4 + (ci >> 3)*2 + (ci & 1);
        uint32_t off = (uint32_t)((t*64 + m)*16 + pos)*2;
        *(uint16_t*)(sm + OW + off) = f16r((&v.x)[j]);
      }
    }
    __syncthreads();
    // ---- taps: shift pixel pointers, mma ----
    #pragma unroll 1
    for (int tap = 0; tap < TAPS; tap++) {
      int dy = (TAPS == 9) ? tap/3 - 1 : 0;
      int dx = (TAPS == 9) ? tap - (tap/3)*3 - 1 : 0;
      uint32_t ah[4][4];
      #pragma unroll
      for (int mm = 0; mm < 4; mm++) {
        int pxm = wy*64 + mm*16 + (lane & 15);
        int rr = (pxm >> 6) + 1 + dy;
        int cc = (pxm & 63) + 1 + dx;
        uint32_t boff = (uint32_t)(rr*66 + cc)*48 + ((lane >> 4) & 1)*16;
        ldmx4(ah[mm], sbase + OP + boff);
      }
      #pragma unroll
      for (int nn = 0; nn < 4; nn++) {
        int cof = wx*32 + nn*8 + g;
        uint32_t woff = (uint32_t)(tap*64 + cof)*32 + tq*8;
        uint2 bh = *(const uint2*)(sm + OW + woff);
        #pragma unroll
        for (int mm = 0; mm < 4; mm++) {
          mma_f16(cacc[mm][nn], ah[mm], bh.x, bh.y);
        }
      }
    }
  }
  // ---- epilogue: frags -> smem stage (stride 260 = conflict-free) -> gmem ----
  __syncthreads();
  float* osm = (float*)sm;
  #pragma unroll
  for (int mm = 0; mm < 4; mm++)
    #pragma unroll
    for (int nn = 0; nn < 4; nn++) {
      int px  = wy*64 + mm*16 + g;
      int col = wx*32 + nn*8 + tq*2;
      osm[(col  )*260 + px    ] = cacc[mm][nn][0];
      osm[(col+1)*260 + px    ] = cacc[mm][nn][1];
      osm[(col  )*260 + px + 8] = cacc[mm][nn][2];
      osm[(col+1)*260 + px + 8] = cacc[mm][nn][3];
    }
  __syncthreads();
  for (int i = tid; i < 16384; i += 256) {
    int col = i >> 8, px = i & 255;
    float v = osm[col*260 + px];
    int cg = co0 + col;
    if (EPI == 0) v += bias[cg];
    size_t obase;
    if (MODE == 2) obase = ((size_t)cob*BATCH*64 + (size_t)b*64 + cg)*HWP;
    else           obase = ((size_t)b*(gridDim.y*64) + cg)*HWP;
    out[obase + rowblk*256 + px] = v;
  }
}

// ---------------- K3: combine partials + BN + SiLU + 1x1 conv + softmax -------
// 4 threads per pixel (16-ci quarters); reads the 4 k2 partial slabs directly.
__global__ __launch_bounds__(256) void k3_kw(const float* __restrict__ Wkp2,
    const float* __restrict__ bkp2, const float* __restrict__ bkp1,
    const float* __restrict__ g1, const float* __restrict__ be1,
    const float* __restrict__ m1, const float* __restrict__ v1) {
  __shared__ float wst[64][40];      // transposed [ci][j], padded row
  __shared__ float bs[36];
  __shared__ float scs[64], shs[64];
  __shared__ float part[3][64][37];  // odd stride -> conflict-free
  int tid = threadIdx.x;
  for (int i = tid; i < 2304; i += 256) {
    int j = i >> 6, ci = i & 63;
    wst[ci][j] = Wkp2[i];
  }
  if (tid < 36) bs[tid] = bkp2[tid];
  if (tid >= 64 && tid < 128) {
    int c = tid - 64;
    float sc = g1[c]*rsqrtf(v1[c]+1e-5f);
    scs[c] = sc;
    shs[c] = be1[c] - m1[c]*sc + bkp1[c]*sc;
  }
  __syncthreads();
  int quart = tid >> 6;              // ci quarter
  int pl = tid & 63;
  int gp = blockIdx.x*64 + pl;       // 512 blocks x 64 px = 32768
  int b = gp >> 12, p = gp & 4095;
  const int SL = BATCH*64*HWP;
  float acc[36];
  #pragma unroll
  for (int j=0;j<36;j++) acc[j]=0.f;
  const float* pb = g_part + (size_t)(b*64 + quart*16)*HWP + p;
  #pragma unroll 2
  for (int ci=0; ci<16; ci++) {
    size_t o = (size_t)ci*HWP;
    float v = pb[o] + pb[o+SL] + pb[o+2*(size_t)SL] + pb[o+3*(size_t)SL];
    int cg = quart*16 + ci;
    v = v*scs[cg] + shs[cg];
    float tv = v/(1.f+expf(-v));
    const float4* wp = (const float4*)&wst[cg][0];
    #pragma unroll
    for (int q=0;q<9;q++) {
      float4 w = wp[q];
      acc[4*q+0] += w.x*tv; acc[4*q+1] += w.y*tv;
      acc[4*q+2] += w.z*tv; acc[4*q+3] += w.w*tv;
    }
  }
  if (quart) {
    #pragma unroll
    for (int j=0;j<36;j++) part[quart-1][pl][j] = acc[j];
  }
  __syncthreads();
  if (!quart) {
    #pragma unroll
    for (int j=0;j<36;j++)
      acc[j] += part[0][pl][j] + part[1][pl][j] + part[2][pl][j] + bs[j];
    float ks[9];
    #pragma unroll
    for (int k=0;k<9;k++) ks[k]=0.f;
    float* kwp = g_kw + (size_t)gp*36;
    #pragma unroll
    for (int s=0;s<4;s++) {
      float m = acc[s*9];
      #pragma unroll
      for (int k=1;k<9;k++) m = fmaxf(m, acc[s*9+k]);
      float e[9]; float sum=0.f;
      #pragma unroll
      for (int k=0;k<9;k++){ e[k]=expf(acc[s*9+k]-m); sum+=e[k]; }
      float inv = 1.f/sum;
      #pragma unroll
      for (int k=0;k<9;k++){ float v=e[k]*inv; kwp[s*9+k]=v; ks[k]+=v; }
    }
    float* ksp = g_kwsum + (size_t)gp*9;
    #pragma unroll
    for (int k=0;k<9;k++) ksp[k]=ks[k];
  }
}

// ---------------- K3b: g map = 3x3 box correlation of kwsum -------------------
__global__ void k3b_gmap() {
  int gp = blockIdx.x*256 + threadIdx.x;
  int b = gp >> 12, p = gp & 4095;
  int i = p >> 6, j = p & 63;
  float s = 0.f;
  #pragma unroll
  for (int ih=0; ih<3; ih++)
    #pragma unroll
    for (int iw=0; iw<3; iw++) {
      int h = i + 1 - ih, w = j + 1 - iw;
      if ((unsigned)h < 64u && (unsigned)w < 64u)
        s += g_kwsum[(size_t)(b*4096 + h*64 + w)*9 + ih*3 + iw];
    }
  g_gmap[gp] = s;
}

// ---------------- K5a: pool enh (side stream, after k4) -----------------------
__global__ __launch_bounds__(256) void k5a_pool(){
  int bc = blockIdx.x;
  const float* ep = g_enh + (size_t)bc*HWP;
  int tid = threadIdx.x;
  float s = 0.f;
  for (int i = tid; i < HWP; i += 256) s += ep[i];
  __shared__ float r[256];
  r[tid]=s; __syncthreads();
  for (int st=128; st>0; st>>=1) {
    if (tid < st) r[tid]+=r[tid+st];
    __syncthreads();
  }
  if (tid==0) g_pool_e[bc] = r[0];
}

// ---------------- K5b: pool x*gmap (main, after k3b) ---------------------------
__global__ __launch_bounds__(256) void k5b_pool(const float* __restrict__ x){
  int bc = blockIdx.x;
  int b = bc >> 8;
  const float* xp = x + (size_t)bc*HWP;
  const float* gp = g_gmap + (size_t)b*HWP;
  int tid = threadIdx.x;
  float s = 0.f;
  for (int i = tid; i < HWP; i += 256) s += xp[i]*gp[i];
  __shared__ float r[256];
  r[tid]=s; __syncthreads();
  for (int st=128; st>0; st>>=1) {
    if (tid < st) r[tid]+=r[tid+st];
    __syncthreads();
  }
  if (tid==0) g_pool_x[bc] = r[0];
}

// ---------------- K6: SE gate ---------------------------------------------------
__global__ __launch_bounds__(256) void k6_gate(const float* __restrict__ Wg1,
    const float* __restrict__ bg1, const float* __restrict__ Wg2,
    const float* __restrict__ bg2) {
  int b = blockIdx.x, tid = threadIdx.x;
  __shared__ float pl[256], hid[64];
  pl[tid] = g_pool_x[b*256+tid]*(1.f/16384.f) + g_pool_e[b*256+tid]*(1.f/4096.f);
  __syncthreads();
  if (tid < 64) {
    float a = bg1[tid];
    for (int ci=0; ci<256; ci++) a += Wg1[tid*256+ci]*pl[ci];
    hid[tid] = a / (1.f + expf(-a));
  }
  __syncthreads();
  float a = bg2[tid];
  for (int j=0;j<64;j++) a += Wg2[tid*64+j]*hid[j];
  g_gate[b*256+tid] = 1.f/(1.f+expf(-a));
}

// ---------------- K7: reassembly + bilinear up + gate -> output ----------------
__global__ __launch_bounds__(256, 2) void k7_fused(const float* __restrict__ x,
                                                   float* __restrict__ out) {
  extern __shared__ float sm7[];
  float* xs = sm7;                 // [16][6][66]
  float* es = sm7 + 16*6*66;       // [16][6][64]
  const int tid = threadIdx.x;
  const int c0 = blockIdx.x * 16;
  const int h0 = blockIdx.y * 4;
  const int b  = blockIdx.z;
  for (int i = tid; i < 16*6*66; i += 256) {
    int cc = i / 396, rem = i - cc*396;
    int rr = rem / 66, col = rem - rr*66 - 1;
    int y = h0 + rr - 1;
    float v = 0.f;
    if ((unsigned)y < 64u && (unsigned)col < 64u)
      v = x[((size_t)(b*CH)+c0+cc)*HWP + y*64 + col];
    xs[i] = v;
  }
  for (int i = tid; i < 16*6*64; i += 256) {
    int cc = i / 384, rem = i - cc*384;
    int rr = rem >> 6, col = rem & 63;
    int y = min(max(h0 + rr - 1, 0), 63);
    es[i] = g_enh[((size_t)(b*CH)+c0+cc)*HWP + y*64 + col];
  }
  __syncthreads();
  const int r = tid >> 6, col = tid & 63;
  const int h = h0 + r;
  float kp[36];
  {
    const float4* kq = (const float4*)(g_kw + ((size_t)(b*4096 + h*64 + col))*36);
    #pragma unroll
    for (int j = 0; j < 9; j++) {
      float4 v = kq[j];
      kp[4*j] = v.x; kp[4*j+1] = v.y; kp[4*j+2] = v.z; kp[4*j+3] = v.w;
    }
  }
  int base; float fw;
  if (col & 1) { base = (col - 1) >> 1; fw = 0.25f; }
  else         { base = (col >> 1) - 1; fw = 0.75f; }
  int cA0 = max(base, 0);
  int cB0 = base + 1;
  int cA1 = base + 32;
  int cB1 = min(base + 33, 63);
  float fw1 = 1.f - fw;
  #pragma unroll 1
  for (int cc = 0; cc < 16; cc++) {
    int c = c0 + cc;
    float gt = g_gate[b*256 + c];
    const float* xr = &xs[cc*396 + r*66 + col];
    float x00=xr[0],   x01=xr[1],   x02=xr[2];
    float x10=xr[66],  x11=xr[67],  x12=xr[68];
    float x20=xr[132], x21=xr[133], x22=xr[134];
    const float* er = &es[cc*384 + r*64];
    float rv[3][2];
    #pragma unroll
    for (int j = 0; j < 3; j++) {
      rv[j][0] = fw1*er[j*64 + cA0] + fw*er[j*64 + cB0];
      rv[j][1] = fw1*er[j*64 + cA1] + fw*er[j*64 + cB1];
    }
    float up[2][2];
    up[0][0] = 0.25f*rv[0][0] + 0.75f*rv[1][0];
    up[0][1] = 0.25f*rv[0][1] + 0.75f*rv[1][1];
    up[1][0] = 0.75f*rv[1][0] + 0.25f*rv[2][0];
    up[1][1] = 0.75f*rv[1][1] + 0.25f*rv[2][1];
    #pragma unroll
    for (int s = 0; s < 4; s++) {
      const float* kq = &kp[s*9];
      float ko = x00*kq[0]+x01*kq[1]+x02*kq[2]
               + x10*kq[3]+x11*kq[4]+x12*kq[5]
               + x20*kq[6]+x21*kq[7]+x22*kq[8];
      int di = s >> 1, dj = s & 1;
      size_t oidx = (size_t)(b*256 + c)*16384 + (size_t)(2*h+di)*128 + (size_t)(dj*64 + col);
      __stcs(&out[oidx], (ko + up[di][dj]) * gt);
    }
  }
}

// ---------------- launch --------------------------------------------------------
extern "C" void kernel_launch(void* const* d_in, const int* in_sizes, int n_in,
                              void* d_out, int out_size) {
  const float* x    = (const float*)d_in[0];
  const float* Wkc  = (const float*)d_in[1];
  const float* bkc  = (const float*)d_in[2];
  const float* Wkp1 = (const float*)d_in[3];
  const float* bkp1 = (const float*)d_in[4];
  const float* g1   = (const float*)d_in[5];
  const float* be1  = (const float*)d_in[6];
  const float* m1   = (const float*)d_in[7];
  const float* v1   = (const float*)d_in[8];
  const float* Wkp2 = (const float*)d_in[9];
  const float* bkp2 = (const float*)d_in[10];
  const float* Wdef = (const float*)d_in[11];
  const float* Wg1  = (const float*)d_in[12];
  const float* bg1  = (const float*)d_in[13];
  const float* Wg2  = (const float*)d_in[14];
  const float* bg2  = (const float*)d_in[15];
  float* out = (float*)d_out;

  float* comp = nullptr; float* part = nullptr; float* enh = nullptr;
  cudaGetSymbolAddress((void**)&comp, g_comp);
  cudaGetSymbolAddress((void**)&part, g_part);
  cudaGetSymbolAddress((void**)&enh,  g_enh);

  const int SM_CONV = 66560;
  const int SM_K7   = (16*6*66 + 16*6*64) * 4;   // 49920

  static cudaStream_t s2 = nullptr;
  static cudaEvent_t evFork = nullptr, evJoin = nullptr;
  if (s2 == nullptr) {
    cudaFuncSetAttribute((const void*)conv_mma<256,256,1,0,0>, cudaFuncAttributeMaxDynamicSharedMemorySize, SM_CONV);
    cudaFuncSetAttribute((const void*)conv_mma<32,128,9,2,2>,  cudaFuncAttributeMaxDynamicSharedMemorySize, SM_CONV);
    cudaFuncSetAttribute((const void*)conv_mma<64,256,9,2,1>,  cudaFuncAttributeMaxDynamicSharedMemorySize, SM_CONV);
    cudaFuncSetAttribute((const void*)k7_fused,                cudaFuncAttributeMaxDynamicSharedMemorySize, SM_K7);
    cudaStreamCreateWithFlags(&s2, cudaStreamNonBlocking);
    cudaEventCreateWithFlags(&evFork, cudaEventDisableTiming);
    cudaEventCreateWithFlags(&evJoin, cudaEventDisableTiming);
  }

  // ---- fork: k4 + enh-pool on side stream; predictor chain on main ----
  cudaEventRecord(evFork, 0);
  cudaStreamWaitEvent(s2, evFork, 0);

  conv_mma<64,256,9,2,1><<<dim3(16,4,8), 256, SM_CONV, s2>>>(x, Wdef, enh, nullptr);
  k5a_pool<<<2048, 256, 0, s2>>>();

  conv_mma<256,256,1,0,0><<<dim3(16,2,8), 256, SM_CONV>>>(x, Wkc, comp, bkc);
  conv_mma<32,128,9,2,2><<<dim3(16,4,8), 256, SM_CONV>>>(comp, Wkp1, part, nullptr);
  k3_kw   <<<512, 256>>>(Wkp2, bkp2, bkp1, g1, be1, m1, v1);
  k3b_gmap<<<128, 256>>>();
  k5b_pool<<<2048, 256>>>(x);

  // ---- join: k6/k7 need enh + both pools ----
  cudaEventRecord(evJoin, s2);
  cudaStreamWaitEvent(0, evJoin, 0);

  k6_gate <<<8, 256>>>(Wg1, bg1, Wg2, bg2);
  k7_fused<<<dim3(16,16,8), 256, SM_K7>>>(x, out);
}